// round 9
// baseline (speedup 1.0000x reference)
#include <cuda_runtime.h>
#include <cuda_bf16.h>
#include <math.h>
#include <stddef.h>
#include <stdint.h>

// ---------------------------------------------------------------------------
// Problem constants
// ---------------------------------------------------------------------------
#define BATCH   2
#define SEQL    2048
#define DIM     4096
#define NH      32
#define NKV     8
#define HEADD   128
#define HIDDEN  11008
#define TOK     (BATCH * SEQL)        /* 4096 */
#define QD      (NH  * HEADD)         /* 4096 */
#define KVD     (NKV * HEADD)         /* 1024 */
#define MAXEL   ((size_t)TOK * HIDDEN)

// ---------------------------------------------------------------------------
// Scratch (static device globals; allocation-free per harness rules)
// ---------------------------------------------------------------------------
__device__ float g_q [(size_t)TOK * QD];
__device__ float g_k [(size_t)TOK * KVD];
__device__ float g_v [(size_t)TOK * KVD];
__device__ float g_h [(size_t)TOK * DIM];
__device__ float g_f1[(size_t)TOK * HIDDEN];
__device__ float g_f3[(size_t)TOK * HIDDEN];
__device__ __nv_bfloat16 g_ahi[MAXEL];
__device__ __nv_bfloat16 g_alo[MAXEL];
__device__ __nv_bfloat16 g_whi[MAXEL];
__device__ __nv_bfloat16 g_wlo[MAXEL];
// flash attention bf16 operands (qhi/qlo double as h hi/lo after flash)
__device__ __nv_bfloat16 g_qhi[(size_t)TOK * QD];
__device__ __nv_bfloat16 g_qlo[(size_t)TOK * QD];
__device__ __nv_bfloat16 g_khi[(size_t)TOK * KVD];
__device__ __nv_bfloat16 g_klo[(size_t)TOK * KVD];
__device__ __nv_bfloat16 g_vthi[(size_t)TOK * KVD];  // [B][NKV][HEADD][SEQL]
__device__ __nv_bfloat16 g_vtlo[(size_t)TOK * KVD];

// ---------------------------------------------------------------------------
// PTX helpers (sm_100-safe: cp.async / ldmatrix / mma.sync only)
// ---------------------------------------------------------------------------
__device__ __forceinline__ uint32_t smem_u32(const void* p) {
    uint32_t a;
    asm("{ .reg .u64 t; cvta.to.shared.u64 t, %1; cvt.u32.u64 %0, t; }"
        : "=r"(a) : "l"(p));
    return a;
}
#define CP_ASYNC16(dst, src) \
    asm volatile("cp.async.cg.shared.global [%0], [%1], 16;" \
                 :: "r"(dst), "l"(src) : "memory")
#define CP_COMMIT() asm volatile("cp.async.commit_group;" ::: "memory")
#define CP_WAIT0()  asm volatile("cp.async.wait_group 0;" ::: "memory")
#define CP_WAIT1()  asm volatile("cp.async.wait_group 1;" ::: "memory")

#define LDMX4(r0, r1, r2, r3, addr) \
    asm volatile("ldmatrix.sync.aligned.m8n8.x4.shared.b16 {%0,%1,%2,%3}, [%4];" \
                 : "=r"(r0), "=r"(r1), "=r"(r2), "=r"(r3) : "r"(addr))

#define MMA16816(c0, c1, c2, c3, a0, a1, a2, a3, b0, b1) \
    asm volatile("mma.sync.aligned.m16n8k16.row.col.f32.bf16.bf16.f32 " \
                 "{%0,%1,%2,%3}, {%4,%5,%6,%7}, {%8,%9}, {%0,%1,%2,%3};" \
                 : "+f"(c0), "+f"(c1), "+f"(c2), "+f"(c3) \
                 : "r"(a0), "r"(a1), "r"(a2), "r"(a3), "r"(b0), "r"(b1))

__device__ __forceinline__ uint32_t swz(uint32_t o) { return o ^ ((o >> 3) & 0x70); }

__device__ __forceinline__ uint32_t pack_bf16x2(float x, float y) {
    __nv_bfloat162 t = __floats2bfloat162_rn(x, y);
    return *(uint32_t*)&t;
}
// hi/lo split of a float pair packed as bf16x2 words
__device__ __forceinline__ void split2(float x, float y, uint32_t& hi, uint32_t& lo) {
    __nv_bfloat16 hx = __float2bfloat16(x), hy = __float2bfloat16(y);
    __nv_bfloat162 hh; hh.x = hx; hh.y = hy;
    hi = *(uint32_t*)&hh;
    lo = pack_bf16x2(x - __bfloat162float(hx), y - __bfloat162float(hy));
}

// ---------------------------------------------------------------------------
// bf16 HMMA GEMM, hi/lo-FUSED smem rows [hi 64B | lo 64B]; 3 passes per
// 32-wide K chunk. 128x128 CTA tile, 8 warps (2Mx4N), 3-stage cp.async ring
// (96 KB smem, 2 CTAs/SM), ONE __syncthreads per chunk.
// Optional bf16 hi/lo outputs (Chi/Clo) written alongside fp32 C.
// ---------------------------------------------------------------------------
#define STG 32768                 /* A-packed 16K + B-packed 16K */
#define NSTAGE 3
#define GEMM_SMEM (STG * NSTAGE)  /* 98304 */

__global__ void __launch_bounds__(256, 2) mma_gemm(
    const __nv_bfloat16* __restrict__ Ahi, const __nv_bfloat16* __restrict__ Alo,
    const __nv_bfloat16* __restrict__ Bhi, const __nv_bfloat16* __restrict__ Blo,
    const float* __restrict__ resid, float* __restrict__ C,
    __nv_bfloat16* __restrict__ Chi, __nv_bfloat16* __restrict__ Clo,
    int K, int ldc)
{
    extern __shared__ char smc[];
    const uint32_t sbase = smem_u32(smc);
    const int tid   = threadIdx.x;
    const int lane  = tid & 31;
    const int wid   = tid >> 5;
    const int warpM = wid >> 2;
    const int warpN = wid & 3;
    const int m0 = blockIdx.y * 128;
    const int n0 = blockIdx.x * 128;

    const int NC = K >> 5;               // fused 32-wide K chunks

    float acc[4][4][4];
#pragma unroll
    for (int mt = 0; mt < 4; mt++)
#pragma unroll
        for (int nt = 0; nt < 4; nt++)
#pragma unroll
            for (int e = 0; e < 4; e++) acc[mt][nt][e] = 0.f;

    auto load_chunk = [&](int c, int stage) {
        const int k0 = c << 5;
        const uint32_t uA = sbase + stage * STG;
        const uint32_t uB = uA + 16384;
#pragma unroll
        for (int it = 0; it < 4; it++) {
            const int idx = tid + it * 256;          // 0..1023
            const int r  = idx >> 3;
            const int cc = idx & 7;
            const uint32_t o = swz((uint32_t)(r * 128 + cc * 16));
            const int kk = k0 + (cc & 3) * 8;
            const __nv_bfloat16* As = (cc < 4) ? Ahi : Alo;
            const __nv_bfloat16* Bs = (cc < 4) ? Bhi : Blo;
            CP_ASYNC16(uA + o, As + (size_t)(m0 + r) * K + kk);
            CP_ASYNC16(uB + o, Bs + (size_t)(n0 + r) * K + kk);
        }
    };

    auto compute_chunk = [&](int stage) {
        const uint32_t uA = sbase + stage * STG;
        const uint32_t uB = uA + 16384;
#pragma unroll
        for (int ks = 0; ks < 2; ks++) {
            const int kb = ks * 32;
            uint32_t a[4][4];
#pragma unroll
            for (int mt = 0; mt < 4; mt++) {
                const int r = warpM * 64 + mt * 16 + (lane & 15);
                const uint32_t o = swz((uint32_t)(r * 128 + kb + ((lane >> 4) << 4)));
                LDMX4(a[mt][0], a[mt][1], a[mt][2], a[mt][3], uA + o);
            }
            uint32_t bH[2][4], bL[2][4];
#pragma unroll
            for (int g = 0; g < 2; g++) {
                const int r = warpN * 32 + g * 16 + (lane & 7) + ((lane >> 4) << 3);
                const uint32_t col = kb + (((lane >> 3) & 1) << 4);
                const uint32_t oH = swz((uint32_t)(r * 128 + col));
                const uint32_t oL = swz((uint32_t)(r * 128 + 64 + col));
                LDMX4(bH[g][0], bH[g][1], bH[g][2], bH[g][3], uB + oH);
                LDMX4(bL[g][0], bL[g][1], bL[g][2], bL[g][3], uB + oL);
            }
#pragma unroll
            for (int mt = 0; mt < 4; mt++)
#pragma unroll
                for (int nt = 0; nt < 4; nt++) {
                    const int gq = nt >> 1, t2 = nt & 1;
                    MMA16816(acc[mt][nt][0], acc[mt][nt][1],
                             acc[mt][nt][2], acc[mt][nt][3],
                             a[mt][0], a[mt][1], a[mt][2], a[mt][3],
                             bH[gq][t2 * 2], bH[gq][t2 * 2 + 1]);
                    MMA16816(acc[mt][nt][0], acc[mt][nt][1],
                             acc[mt][nt][2], acc[mt][nt][3],
                             a[mt][0], a[mt][1], a[mt][2], a[mt][3],
                             bL[gq][t2 * 2], bL[gq][t2 * 2 + 1]);
                }
#pragma unroll
            for (int mt = 0; mt < 4; mt++) {
                const int r = warpM * 64 + mt * 16 + (lane & 15);
                const uint32_t o = swz((uint32_t)(r * 128 + 64 + kb + ((lane >> 4) << 4)));
                LDMX4(a[mt][0], a[mt][1], a[mt][2], a[mt][3], uA + o);
            }
#pragma unroll
            for (int mt = 0; mt < 4; mt++)
#pragma unroll
                for (int nt = 0; nt < 4; nt++) {
                    const int gq = nt >> 1, t2 = nt & 1;
                    MMA16816(acc[mt][nt][0], acc[mt][nt][1],
                             acc[mt][nt][2], acc[mt][nt][3],
                             a[mt][0], a[mt][1], a[mt][2], a[mt][3],
                             bH[gq][t2 * 2], bH[gq][t2 * 2 + 1]);
                }
        }
    };

    // prologue: fill 2 of 3 stages
    load_chunk(0, 0); CP_COMMIT();
    load_chunk(1, 1); CP_COMMIT();

    for (int i = 0; i < NC; i++) {
        if (i < NC - 1) { CP_WAIT1(); } else { CP_WAIT0(); }
        __syncthreads();   // chunk i resident everywhere; slot (i+2)%3 free
        if (i + 2 < NC) {
            load_chunk(i + 2, (i + 2) % NSTAGE);
            CP_COMMIT();
        }
        compute_chunk(i % NSTAGE);
    }

    const int g  = lane >> 2;
    const int tg = lane & 3;
#pragma unroll
    for (int mt = 0; mt < 4; mt++) {
        const int row = m0 + warpM * 64 + mt * 16 + g;
#pragma unroll
        for (int nt = 0; nt < 4; nt++) {
            const int col = n0 + warpN * 32 + nt * 8 + tg * 2;
            const size_t i0 = (size_t)row * ldc + col;
            const size_t i1 = (size_t)(row + 8) * ldc + col;
            float2 v0 = make_float2(acc[mt][nt][0], acc[mt][nt][1]);
            float2 v1 = make_float2(acc[mt][nt][2], acc[mt][nt][3]);
            if (resid) {
                float2 r0 = *(const float2*)(resid + i0);
                float2 r1 = *(const float2*)(resid + i1);
                v0.x += r0.x; v0.y += r0.y;
                v1.x += r1.x; v1.y += r1.y;
            }
            *(float2*)(C + i0) = v0;
            *(float2*)(C + i1) = v1;
            if (Chi) {
                uint32_t h0, l0, h1, l1;
                split2(v0.x, v0.y, h0, l0);
                split2(v1.x, v1.y, h1, l1);
                *(uint32_t*)(Chi + i0) = h0;
                *(uint32_t*)(Clo + i0) = l0;
                *(uint32_t*)(Chi + i1) = h1;
                *(uint32_t*)(Clo + i1) = l1;
            }
        }
    }
}

// ---------------------------------------------------------------------------
// fp32 -> bf16 hi/lo split (elementwise)
// ---------------------------------------------------------------------------
__global__ void split_kernel(const float* __restrict__ src,
                             __nv_bfloat16* __restrict__ hi,
                             __nv_bfloat16* __restrict__ lo, size_t n)
{
    const size_t stride = (size_t)gridDim.x * blockDim.x;
    for (size_t i = (size_t)blockIdx.x * blockDim.x + threadIdx.x; i < n; i += stride) {
        float v = src[i];
        __nv_bfloat16 h = __float2bfloat16(v);
        hi[i] = h;
        lo[i] = __float2bfloat16(v - __bfloat162float(h));
    }
}

// fused: g = silu(f1raw) * f3raw, written directly as bf16 hi/lo
__global__ void silu_split_kernel(const float* __restrict__ f1,
                                  const float* __restrict__ f3,
                                  __nv_bfloat16* __restrict__ hi,
                                  __nv_bfloat16* __restrict__ lo, size_t n)
{
    const size_t stride = (size_t)gridDim.x * blockDim.x;
    for (size_t i = (size_t)blockIdx.x * blockDim.x + threadIdx.x; i < n; i += stride) {
        float a = f1[i];
        float gv = a / (1.0f + __expf(-a)) * f3[i];
        __nv_bfloat16 h = __float2bfloat16(gv);
        hi[i] = h;
        lo[i] = __float2bfloat16(gv - __bfloat162float(h));
    }
}

// W [K,N] fp32 -> W^T [N,K] bf16 hi/lo.  grid=(N/32, K/32), block=(32,8)
__global__ void split_transpose_kernel(const float* __restrict__ W,
                                       __nv_bfloat16* __restrict__ hi,
                                       __nv_bfloat16* __restrict__ lo,
                                       int K, int N)
{
    __shared__ float t[32][33];
    const int nb = blockIdx.x * 32, kb = blockIdx.y * 32;
    const int tx = threadIdx.x, ty = threadIdx.y;
#pragma unroll
    for (int j = 0; j < 4; j++)
        t[ty + j * 8][tx] = W[(size_t)(kb + ty + j * 8) * N + nb + tx];
    __syncthreads();
#pragma unroll
    for (int j = 0; j < 4; j++) {
        const int n = nb + ty + j * 8;
        const float v = t[tx][ty + j * 8];
        __nv_bfloat16 h = __float2bfloat16(v);
        hi[(size_t)n * K + kb + tx] = h;
        lo[(size_t)n * K + kb + tx] = __float2bfloat16(v - __bfloat162float(h));
    }
}

// v [tok][kv*128+d] fp32 -> vt [(b*NKV+kv)*HEADD + d][s] bf16 hi/lo
__global__ void vt_split_kernel(const float* __restrict__ v,
                                __nv_bfloat16* __restrict__ hi,
                                __nv_bfloat16* __restrict__ lo)
{
    __shared__ float t[32][33];
    const int z = blockIdx.z, b = z >> 3, kvh = z & 7;
    const int sb = blockIdx.x * 32, db = blockIdx.y * 32;
    const int tx = threadIdx.x, ty = threadIdx.y;
#pragma unroll
    for (int j = 0; j < 4; j++)
        t[ty + j * 8][tx] =
            v[(size_t)(b * SEQL + sb + ty + j * 8) * KVD + kvh * HEADD + db + tx];
    __syncthreads();
#pragma unroll
    for (int j = 0; j < 4; j++) {
        const int d = db + ty + j * 8, s = sb + tx;
        const float val = t[tx][ty + j * 8];
        __nv_bfloat16 h = __float2bfloat16(val);
        const size_t o = ((size_t)(b * NKV + kvh) * HEADD + d) * SEQL + s;
        hi[o] = h;
        lo[o] = __float2bfloat16(val - __bfloat162float(h));
    }
}

// ---------------------------------------------------------------------------
// RoPE (interleaved pairs)
// ---------------------------------------------------------------------------
__global__ void rope_kernel(float* __restrict__ t,
                            const float* __restrict__ fcos,
                            const float* __restrict__ fsin,
                            int nheads, int npairs_total)
{
    int gid = blockIdx.x * blockDim.x + threadIdx.x;
    if (gid >= npairs_total) return;
    int i    = gid & 63;
    int rest = gid >> 6;
    int hh   = rest % nheads;
    int tok  = rest / nheads;
    int s    = tok & (SEQL - 1);
    float c  = fcos[s * 64 + i];
    float sn = fsin[s * 64 + i];
    size_t base = ((size_t)tok * nheads + hh) * HEADD + 2 * i;
    float a = t[base], b = t[base + 1];
    t[base]     = a * c - b * sn;
    t[base + 1] = a * sn + b * c;
}

// ---------------------------------------------------------------------------
// HMMA flash attention, causal, 3-pass hi/lo.  Output written directly as
// bf16 hi/lo (A-operand layout for the Wo GEMM).
// ---------------------------------------------------------------------------
#define SQ_HI 0
#define SQ_LO 32768
#define SKV0  65536
#define KVSTG 65536
#define FLASH_SMEM (SKV0 + 2 * KVSTG)   /* 196608 */

__global__ void __launch_bounds__(256) flash_mma_kernel(
    const __nv_bfloat16* __restrict__ qhi, const __nv_bfloat16* __restrict__ qlo,
    const __nv_bfloat16* __restrict__ khi, const __nv_bfloat16* __restrict__ klo,
    const __nv_bfloat16* __restrict__ vthi, const __nv_bfloat16* __restrict__ vtlo,
    __nv_bfloat16* __restrict__ ohi, __nv_bfloat16* __restrict__ olo)
{
    extern __shared__ char smc[];
    const uint32_t sb = smem_u32(smc);
    const int z = blockIdx.y, b = z >> 5, h = z & 31, kv = h >> 2;
    const int qt = blockIdx.x, q0 = qt * 128;
    const int tid = threadIdx.x, lane = tid & 31, w = tid >> 5;
    const int g = lane >> 2, tg = lane & 3;

    {
        const __nv_bfloat16* qh = qhi + (size_t)(b * SEQL + q0) * QD + h * HEADD;
        const __nv_bfloat16* ql = qlo + (size_t)(b * SEQL + q0) * QD + h * HEADD;
#pragma unroll
        for (int it = 0; it < 8; it++) {
            const int idx = tid + it * 256;
            const int sub = idx >> 10, rem = idx & 1023;
            const int r = rem >> 3, cc = rem & 7;
            const uint32_t o = swz((uint32_t)(r * 128 + cc * 16));
            const size_t src = (size_t)r * QD + sub * 64 + cc * 8;
            CP_ASYNC16(sb + SQ_HI + sub * 16384 + o, qh + src);
            CP_ASYNC16(sb + SQ_LO + sub * 16384 + o, ql + src);
        }
        CP_COMMIT();
    }

    const int nkt = 2 * qt + 2;
    auto load_kv = [&](int kt) {
        const uint32_t base = sb + SKV0 + (kt & 1) * KVSTG;
        const int s0 = kt * 64;
        const __nv_bfloat16* kh = khi + (size_t)(b * SEQL + s0) * KVD + kv * HEADD;
        const __nv_bfloat16* kl = klo + (size_t)(b * SEQL + s0) * KVD + kv * HEADD;
#pragma unroll
        for (int it = 0; it < 4; it++) {
            const int idx = tid + it * 256;
            const int sub = idx >> 9, rem = idx & 511;
            const int r = rem >> 3, cc = rem & 7;
            const uint32_t o = swz((uint32_t)(r * 128 + cc * 16));
            const size_t src = (size_t)r * KVD + sub * 64 + cc * 8;
            CP_ASYNC16(base + sub * 8192 + o, kh + src);
            CP_ASYNC16(base + 16384 + sub * 8192 + o, kl + src);
        }
        const __nv_bfloat16* vh = vthi + (size_t)(b * NKV + kv) * HEADD * SEQL + s0;
        const __nv_bfloat16* vl = vtlo + (size_t)(b * NKV + kv) * HEADD * SEQL + s0;
#pragma unroll
        for (int it = 0; it < 4; it++) {
            const int idx = tid + it * 256;
            const int r = idx >> 3, cc = idx & 7;
            const uint32_t o = swz((uint32_t)(r * 128 + cc * 16));
            const size_t src = (size_t)r * SEQL + cc * 8;
            CP_ASYNC16(base + 32768 + o, vh + src);
            CP_ASYNC16(base + 49152 + o, vl + src);
        }
        CP_COMMIT();
    };
    load_kv(0);
    if (nkt > 1) load_kv(1);

    float m0 = -1e30f, m1 = -1e30f, l0 = 0.f, l1 = 0.f;
    float O[16][4];
#pragma unroll
    for (int nt = 0; nt < 16; nt++)
#pragma unroll
        for (int e = 0; e < 4; e++) O[nt][e] = 0.f;

    const float SC = 0.08838834764831843f;

    for (int kt = 0; kt < nkt; kt++) {
        if (kt + 1 < nkt) CP_WAIT1(); else CP_WAIT0();
        __syncthreads();
        const uint32_t base = sb + SKV0 + (kt & 1) * KVSTG;

        float S[8][4];
#pragma unroll
        for (int nt = 0; nt < 8; nt++)
#pragma unroll
            for (int e = 0; e < 4; e++) S[nt][e] = 0.f;

#pragma unroll
        for (int ks = 0; ks < 8; ks++) {
            const int sub = ks >> 2, kb = (ks & 3) * 32;
            const uint32_t oA =
                swz((uint32_t)((w * 16 + (lane & 15)) * 128 + kb + ((lane >> 4) << 4)));
            uint32_t aH[4], aL[4];
            LDMX4(aH[0], aH[1], aH[2], aH[3], sb + SQ_HI + sub * 16384 + oA);
            LDMX4(aL[0], aL[1], aL[2], aL[3], sb + SQ_LO + sub * 16384 + oA);
#pragma unroll
            for (int nb = 0; nb < 4; nb++) {
                const uint32_t oB = swz((uint32_t)(
                    (nb * 16 + (lane & 7) + ((lane >> 4) << 3)) * 128 +
                    kb + (((lane >> 3) & 1) << 4)));
                uint32_t bH[4], bL[4];
                LDMX4(bH[0], bH[1], bH[2], bH[3], base + sub * 8192 + oB);
                LDMX4(bL[0], bL[1], bL[2], bL[3], base + 16384 + sub * 8192 + oB);
#pragma unroll
                for (int t2 = 0; t2 < 2; t2++) {
                    const int nt = nb * 2 + t2;
                    MMA16816(S[nt][0], S[nt][1], S[nt][2], S[nt][3],
                             aH[0], aH[1], aH[2], aH[3], bH[t2 * 2], bH[t2 * 2 + 1]);
                    MMA16816(S[nt][0], S[nt][1], S[nt][2], S[nt][3],
                             aH[0], aH[1], aH[2], aH[3], bL[t2 * 2], bL[t2 * 2 + 1]);
                    MMA16816(S[nt][0], S[nt][1], S[nt][2], S[nt][3],
                             aL[0], aL[1], aL[2], aL[3], bH[t2 * 2], bH[t2 * 2 + 1]);
                }
            }
        }

        const int s0 = kt * 64;
        const int row0 = q0 + w * 16 + g;
#pragma unroll
        for (int nt = 0; nt < 8; nt++)
#pragma unroll
            for (int e = 0; e < 2; e++) {
                const int col = s0 + nt * 8 + tg * 2 + e;
                float v0 = S[nt][e] * SC;
                float v1 = S[nt][2 + e] * SC;
                if (col > row0)     v0 = -1e30f;
                if (col > row0 + 8) v1 = -1e30f;
                S[nt][e] = v0;
                S[nt][2 + e] = v1;
            }
        float tm0 = -1e30f, tm1 = -1e30f;
#pragma unroll
        for (int nt = 0; nt < 8; nt++) {
            tm0 = fmaxf(tm0, fmaxf(S[nt][0], S[nt][1]));
            tm1 = fmaxf(tm1, fmaxf(S[nt][2], S[nt][3]));
        }
        tm0 = fmaxf(tm0, __shfl_xor_sync(0xffffffffu, tm0, 1));
        tm0 = fmaxf(tm0, __shfl_xor_sync(0xffffffffu, tm0, 2));
        tm1 = fmaxf(tm1, __shfl_xor_sync(0xffffffffu, tm1, 1));
        tm1 = fmaxf(tm1, __shfl_xor_sync(0xffffffffu, tm1, 2));
        const float mn0 = fmaxf(m0, tm0), mn1 = fmaxf(m1, tm1);
        const float sc0 = __expf(m0 - mn0), sc1 = __expf(m1 - mn1);
        m0 = mn0; m1 = mn1;
        float ts0 = 0.f, ts1 = 0.f;
#pragma unroll
        for (int nt = 0; nt < 8; nt++) {
            S[nt][0] = __expf(S[nt][0] - mn0);
            S[nt][1] = __expf(S[nt][1] - mn0);
            S[nt][2] = __expf(S[nt][2] - mn1);
            S[nt][3] = __expf(S[nt][3] - mn1);
            ts0 += S[nt][0] + S[nt][1];
            ts1 += S[nt][2] + S[nt][3];
        }
        ts0 += __shfl_xor_sync(0xffffffffu, ts0, 1);
        ts0 += __shfl_xor_sync(0xffffffffu, ts0, 2);
        ts1 += __shfl_xor_sync(0xffffffffu, ts1, 1);
        ts1 += __shfl_xor_sync(0xffffffffu, ts1, 2);
        l0 = l0 * sc0 + ts0;
        l1 = l1 * sc1 + ts1;
#pragma unroll
        for (int nt = 0; nt < 16; nt++) {
            O[nt][0] *= sc0; O[nt][1] *= sc0;
            O[nt][2] *= sc1; O[nt][3] *= sc1;
        }

#pragma unroll
        for (int ks = 0; ks < 4; ks++) {
            uint32_t pH[4], pL[4];
#pragma unroll
            for (int half = 0; half < 2; half++) {
                const int st = 2 * ks + half;
                split2(S[st][0], S[st][1], pH[half * 2 + 0], pL[half * 2 + 0]);
                split2(S[st][2], S[st][3], pH[half * 2 + 1], pL[half * 2 + 1]);
            }
#pragma unroll
            for (int nb = 0; nb < 8; nb++) {
                const uint32_t oB = swz((uint32_t)(
                    (nb * 16 + (lane & 7) + ((lane >> 4) << 3)) * 128 +
                    ks * 32 + (((lane >> 3) & 1) << 4)));
                uint32_t vH[4], vL[4];
                LDMX4(vH[0], vH[1], vH[2], vH[3], base + 32768 + oB);
                LDMX4(vL[0], vL[1], vL[2], vL[3], base + 49152 + oB);
#pragma unroll
                for (int t2 = 0; t2 < 2; t2++) {
                    const int nt = nb * 2 + t2;
                    MMA16816(O[nt][0], O[nt][1], O[nt][2], O[nt][3],
                             pH[0], pH[1], pH[2], pH[3], vH[t2 * 2], vH[t2 * 2 + 1]);
                    MMA16816(O[nt][0], O[nt][1], O[nt][2], O[nt][3],
                             pL[0], pL[1], pL[2], pL[3], vH[t2 * 2], vH[t2 * 2 + 1]);
                    MMA16816(O[nt][0], O[nt][1], O[nt][2], O[nt][3],
                             pH[0], pH[1], pH[2], pH[3], vL[t2 * 2], vL[t2 * 2 + 1]);
                }
            }
        }
        __syncthreads();
        if (kt + 2 < nkt) load_kv(kt + 2);
    }

    // ---- normalize + write bf16 hi/lo directly (A-operand layout)
    const float il0 = 1.0f / l0, il1 = 1.0f / l1;
    __nv_bfloat16* OH = ohi + (size_t)(b * SEQL) * QD + h * HEADD;
    __nv_bfloat16* OL = olo + (size_t)(b * SEQL) * QD + h * HEADD;
#pragma unroll
    for (int nt = 0; nt < 16; nt++) {
        const int col = nt * 8 + tg * 2;
        const size_t i0 = (size_t)(q0 + w * 16 + g) * QD + col;
        const size_t i1 = (size_t)(q0 + w * 16 + g + 8) * QD + col;
        uint32_t h0, lo0, h1, lo1;
        split2(O[nt][0] * il0, O[nt][1] * il0, h0, lo0);
        split2(O[nt][2] * il1, O[nt][3] * il1, h1, lo1);
        *(uint32_t*)(OH + i0) = h0;
        *(uint32_t*)(OL + i0) = lo0;
        *(uint32_t*)(OH + i1) = h1;
        *(uint32_t*)(OL + i1) = lo1;
    }
}

// ---------------------------------------------------------------------------
// kernel_launch
// ---------------------------------------------------------------------------
extern "C" void kernel_launch(void* const* d_in, const int* in_sizes, int n_in,
                              void* d_out, int out_size)
{
    const float* x    = (const float*)d_in[0];
    /* d_in[1] = mask (unused; causal handled analytically) */
    const float* fcos = (const float*)d_in[2];
    const float* fsin = (const float*)d_in[3];
    const float* wq   = (const float*)d_in[4];
    const float* wk   = (const float*)d_in[5];
    const float* wv   = (const float*)d_in[6];
    const float* wo   = (const float*)d_in[7];
    const float* w1   = (const float*)d_in[8];
    const float* w2   = (const float*)d_in[9];
    const float* w3   = (const float*)d_in[10];
    float* out = (float*)d_out;

    float *q, *k, *v, *h, *f1, *f3;
    __nv_bfloat16 *ahi, *alo, *whi, *wlo;
    __nv_bfloat16 *qhi, *qlo, *khi, *klo, *vthi, *vtlo;
    cudaGetSymbolAddress((void**)&q,    g_q);
    cudaGetSymbolAddress((void**)&k,    g_k);
    cudaGetSymbolAddress((void**)&v,    g_v);
    cudaGetSymbolAddress((void**)&h,    g_h);
    cudaGetSymbolAddress((void**)&f1,   g_f1);
    cudaGetSymbolAddress((void**)&f3,   g_f3);
    cudaGetSymbolAddress((void**)&ahi,  g_ahi);
    cudaGetSymbolAddress((void**)&alo,  g_alo);
    cudaGetSymbolAddress((void**)&whi,  g_whi);
    cudaGetSymbolAddress((void**)&wlo,  g_wlo);
    cudaGetSymbolAddress((void**)&qhi,  g_qhi);
    cudaGetSymbolAddress((void**)&qlo,  g_qlo);
    cudaGetSymbolAddress((void**)&khi,  g_khi);
    cudaGetSymbolAddress((void**)&klo,  g_klo);
    cudaGetSymbolAddress((void**)&vthi, g_vthi);
    cudaGetSymbolAddress((void**)&vtlo, g_vtlo);

    static int attr_done = 0;
    if (!attr_done) {
        cudaFuncSetAttribute(mma_gemm,
            cudaFuncAttributeMaxDynamicSharedMemorySize, GEMM_SMEM);
        cudaFuncSetAttribute(flash_mma_kernel,
            cudaFuncAttributeMaxDynamicSharedMemorySize, FLASH_SMEM);
        attr_done = 1;
    }

    const dim3 tb(32, 8);

    // x -> bf16 split (shared by Q/K/V projections)
    split_kernel<<<2048, 256>>>(x, ahi, alo, (size_t)TOK * DIM);

    // QKV projections (fp32 out for RoPE)
    split_transpose_kernel<<<dim3(QD / 32, DIM / 32), tb>>>(wq, whi, wlo, DIM, QD);
    mma_gemm<<<dim3(QD / 128, TOK / 128), 256, GEMM_SMEM>>>(
        ahi, alo, whi, wlo, nullptr, q, nullptr, nullptr, DIM, QD);
    split_transpose_kernel<<<dim3(KVD / 32, DIM / 32), tb>>>(wk, whi, wlo, DIM, KVD);
    mma_gemm<<<dim3(KVD / 128, TOK / 128), 256, GEMM_SMEM>>>(
        ahi, alo, whi, wlo, nullptr, k, nullptr, nullptr, DIM, KVD);
    split_transpose_kernel<<<dim3(KVD / 32, DIM / 32), tb>>>(wv, whi, wlo, DIM, KVD);
    mma_gemm<<<dim3(KVD / 128, TOK / 128), 256, GEMM_SMEM>>>(
        ahi, alo, whi, wlo, nullptr, v, nullptr, nullptr, DIM, KVD);

    // RoPE
    {
        int nq  = TOK * NH  * 64;
        int nk2 = TOK * NKV * 64;
        rope_kernel<<<(nq + 255) / 256, 256>>>(q, fcos, fsin, NH,  nq);
        rope_kernel<<<(nk2 + 255) / 256, 256>>>(k, fcos, fsin, NKV, nk2);
    }

    // convert flash operands to bf16 hi/lo (V transposed per kv-head)
    split_kernel<<<2048, 256>>>(q, qhi, qlo, (size_t)TOK * QD);
    split_kernel<<<1024, 256>>>(k, khi, klo, (size_t)TOK * KVD);
    vt_split_kernel<<<dim3(SEQL / 32, HEADD / 32, BATCH * NKV), tb>>>(v, vthi, vtlo);

    // HMMA flash attention -> attn out directly as bf16 hi/lo (into ahi/alo)
    flash_mma_kernel<<<dim3(SEQL / 128, BATCH * NH), 256, FLASH_SMEM>>>(
        qhi, qlo, khi, klo, vthi, vtlo, ahi, alo);

    // h = x + attn @ wo ; epilogue also emits h as bf16 hi/lo into qhi/qlo
    split_transpose_kernel<<<dim3(DIM / 32, QD / 32), tb>>>(wo, whi, wlo, QD, DIM);
    mma_gemm<<<dim3(DIM / 128, TOK / 128), 256, GEMM_SMEM>>>(
        ahi, alo, whi, wlo, x, h, qhi, qlo, QD, DIM);

    // FFN: f1 = h @ w1, f3 = h @ w3 (fp32 out)
    split_transpose_kernel<<<dim3(HIDDEN / 32, DIM / 32), tb>>>(w1, whi, wlo, DIM, HIDDEN);
    mma_gemm<<<dim3(HIDDEN / 128, TOK / 128), 256, GEMM_SMEM>>>(
        qhi, qlo, whi, wlo, nullptr, f1, nullptr, nullptr, DIM, HIDDEN);
    split_transpose_kernel<<<dim3(HIDDEN / 32, DIM / 32), tb>>>(w3, whi, wlo, DIM, HIDDEN);
    mma_gemm<<<dim3(HIDDEN / 128, TOK / 128), 256, GEMM_SMEM>>>(
        qhi, qlo, whi, wlo, nullptr, f3, nullptr, nullptr, DIM, HIDDEN);

    // gated = silu(f1) * f3 -> bf16 hi/lo directly (never materialized fp32)
    silu_split_kernel<<<4096, 256>>>(f1, f3, ahi, alo, (size_t)TOK * HIDDEN);

    // out = h + gated @ w2
    split_transpose_kernel<<<dim3(DIM / 32, HIDDEN / 32), tb>>>(w2, whi, wlo, HIDDEN, DIM);
    mma_gemm<<<dim3(DIM / 128, TOK / 128), 256, GEMM_SMEM>>>(
        ahi, alo, whi, wlo, h, out, nullptr, nullptr, HIDDEN, DIM);
}

// round 10
// speedup vs baseline: 1.0566x; 1.0566x over previous
#include <cuda_runtime.h>
#include <cuda_bf16.h>
#include <math.h>
#include <stddef.h>
#include <stdint.h>

// ---------------------------------------------------------------------------
// Problem constants
// ---------------------------------------------------------------------------
#define BATCH   2
#define SEQL    2048
#define DIM     4096
#define NH      32
#define NKV     8
#define HEADD   128
#define HIDDEN  11008
#define TOK     (BATCH * SEQL)        /* 4096 */
#define QD      (NH  * HEADD)         /* 4096 */
#define KVD     (NKV * HEADD)         /* 1024 */
#define MAXEL   ((size_t)TOK * HIDDEN)

// ---------------------------------------------------------------------------
// Scratch (static device globals; allocation-free per harness rules)
// ---------------------------------------------------------------------------
__device__ float g_q [(size_t)TOK * QD];
__device__ float g_k [(size_t)TOK * KVD];
__device__ float g_v [(size_t)TOK * KVD];
__device__ float g_h [(size_t)TOK * DIM];
__device__ float g_f1[(size_t)TOK * HIDDEN];
__device__ float g_f3[(size_t)TOK * HIDDEN];
__device__ __nv_bfloat16 g_ahi[MAXEL];
__device__ __nv_bfloat16 g_alo[MAXEL];
__device__ __nv_bfloat16 g_whi[MAXEL];
__device__ __nv_bfloat16 g_wlo[MAXEL];
// flash attention bf16 operands (qhi/qlo double as h hi/lo after flash)
__device__ __nv_bfloat16 g_qhi[(size_t)TOK * QD];
__device__ __nv_bfloat16 g_qlo[(size_t)TOK * QD];
__device__ __nv_bfloat16 g_khi[(size_t)TOK * KVD];
__device__ __nv_bfloat16 g_klo[(size_t)TOK * KVD];
__device__ __nv_bfloat16 g_vthi[(size_t)TOK * KVD];  // [B][NKV][HEADD][SEQL]
__device__ __nv_bfloat16 g_vtlo[(size_t)TOK * KVD];

// ---------------------------------------------------------------------------
// PTX helpers (sm_100-safe: cp.async / ldmatrix / mma.sync only)
// ---------------------------------------------------------------------------
__device__ __forceinline__ uint32_t smem_u32(const void* p) {
    uint32_t a;
    asm("{ .reg .u64 t; cvta.to.shared.u64 t, %1; cvt.u32.u64 %0, t; }"
        : "=r"(a) : "l"(p));
    return a;
}
#define CP_ASYNC16(dst, src) \
    asm volatile("cp.async.cg.shared.global [%0], [%1], 16;" \
                 :: "r"(dst), "l"(src) : "memory")
#define CP_COMMIT() asm volatile("cp.async.commit_group;" ::: "memory")
#define CP_WAIT0()  asm volatile("cp.async.wait_group 0;" ::: "memory")
#define CP_WAIT1()  asm volatile("cp.async.wait_group 1;" ::: "memory")

#define LDMX4(r0, r1, r2, r3, addr) \
    asm volatile("ldmatrix.sync.aligned.m8n8.x4.shared.b16 {%0,%1,%2,%3}, [%4];" \
                 : "=r"(r0), "=r"(r1), "=r"(r2), "=r"(r3) : "r"(addr))

#define MMA16816(c0, c1, c2, c3, a0, a1, a2, a3, b0, b1) \
    asm volatile("mma.sync.aligned.m16n8k16.row.col.f32.bf16.bf16.f32 " \
                 "{%0,%1,%2,%3}, {%4,%5,%6,%7}, {%8,%9}, {%0,%1,%2,%3};" \
                 : "+f"(c0), "+f"(c1), "+f"(c2), "+f"(c3) \
                 : "r"(a0), "r"(a1), "r"(a2), "r"(a3), "r"(b0), "r"(b1))

__device__ __forceinline__ uint32_t swz(uint32_t o) { return o ^ ((o >> 3) & 0x70); }

__device__ __forceinline__ uint32_t pack_bf16x2(float x, float y) {
    __nv_bfloat162 t = __floats2bfloat162_rn(x, y);
    return *(uint32_t*)&t;
}
// hi/lo split of a float pair packed as bf16x2 words
__device__ __forceinline__ void split2(float x, float y, uint32_t& hi, uint32_t& lo) {
    __nv_bfloat16 hx = __float2bfloat16(x), hy = __float2bfloat16(y);
    __nv_bfloat162 hh; hh.x = hx; hh.y = hy;
    hi = *(uint32_t*)&hh;
    lo = pack_bf16x2(x - __bfloat162float(hx), y - __bfloat162float(hy));
}

// ---------------------------------------------------------------------------
// bf16 HMMA GEMM, hi/lo-FUSED smem rows [hi 64B | lo 64B]; 3 passes per
// 32-wide K chunk. 128x128 CTA tile, 8 warps (2Mx4N), 2-stage cp.async
// (round-8 proven structure: 64 KB smem, 2 CTAs/SM, 2 syncs per chunk).
// Optional bf16 hi/lo outputs (Chi/Clo) written alongside fp32 C.
// ---------------------------------------------------------------------------
#define STG 32768                 /* A-packed 16K + B-packed 16K */
#define GEMM_SMEM 65536

__global__ void __launch_bounds__(256, 2) mma_gemm(
    const __nv_bfloat16* __restrict__ Ahi, const __nv_bfloat16* __restrict__ Alo,
    const __nv_bfloat16* __restrict__ Bhi, const __nv_bfloat16* __restrict__ Blo,
    const float* __restrict__ resid, float* __restrict__ C,
    __nv_bfloat16* __restrict__ Chi, __nv_bfloat16* __restrict__ Clo,
    int K, int ldc)
{
    extern __shared__ char smc[];
    const uint32_t sbase = smem_u32(smc);
    const int tid   = threadIdx.x;
    const int lane  = tid & 31;
    const int wid   = tid >> 5;
    const int warpM = wid >> 2;
    const int warpN = wid & 3;
    const int m0 = blockIdx.y * 128;
    const int n0 = blockIdx.x * 128;

    const int NC = K >> 5;               // fused 32-wide K chunks

    float acc[4][4][4];
#pragma unroll
    for (int mt = 0; mt < 4; mt++)
#pragma unroll
        for (int nt = 0; nt < 4; nt++)
#pragma unroll
            for (int e = 0; e < 4; e++) acc[mt][nt][e] = 0.f;

    auto load_chunk = [&](int c, int stage) {
        const int k0 = c << 5;
        const uint32_t uA = sbase + stage * STG;
        const uint32_t uB = uA + 16384;
#pragma unroll
        for (int it = 0; it < 4; it++) {
            const int idx = tid + it * 256;          // 0..1023
            const int r  = idx >> 3;
            const int cc = idx & 7;
            const uint32_t o = swz((uint32_t)(r * 128 + cc * 16));
            const int kk = k0 + (cc & 3) * 8;
            const __nv_bfloat16* As = (cc < 4) ? Ahi : Alo;
            const __nv_bfloat16* Bs = (cc < 4) ? Bhi : Blo;
            CP_ASYNC16(uA + o, As + (size_t)(m0 + r) * K + kk);
            CP_ASYNC16(uB + o, Bs + (size_t)(n0 + r) * K + kk);
        }
    };

    auto compute_chunk = [&](int stage) {
        const uint32_t uA = sbase + stage * STG;
        const uint32_t uB = uA + 16384;
#pragma unroll
        for (int ks = 0; ks < 2; ks++) {
            const int kb = ks * 32;
            uint32_t a[4][4];
#pragma unroll
            for (int mt = 0; mt < 4; mt++) {
                const int r = warpM * 64 + mt * 16 + (lane & 15);
                const uint32_t o = swz((uint32_t)(r * 128 + kb + ((lane >> 4) << 4)));
                LDMX4(a[mt][0], a[mt][1], a[mt][2], a[mt][3], uA + o);
            }
            uint32_t bH[2][4], bL[2][4];
#pragma unroll
            for (int g = 0; g < 2; g++) {
                const int r = warpN * 32 + g * 16 + (lane & 7) + ((lane >> 4) << 3);
                const uint32_t col = kb + (((lane >> 3) & 1) << 4);
                const uint32_t oH = swz((uint32_t)(r * 128 + col));
                const uint32_t oL = swz((uint32_t)(r * 128 + 64 + col));
                LDMX4(bH[g][0], bH[g][1], bH[g][2], bH[g][3], uB + oH);
                LDMX4(bL[g][0], bL[g][1], bL[g][2], bL[g][3], uB + oL);
            }
#pragma unroll
            for (int mt = 0; mt < 4; mt++)
#pragma unroll
                for (int nt = 0; nt < 4; nt++) {
                    const int gq = nt >> 1, t2 = nt & 1;
                    MMA16816(acc[mt][nt][0], acc[mt][nt][1],
                             acc[mt][nt][2], acc[mt][nt][3],
                             a[mt][0], a[mt][1], a[mt][2], a[mt][3],
                             bH[gq][t2 * 2], bH[gq][t2 * 2 + 1]);
                    MMA16816(acc[mt][nt][0], acc[mt][nt][1],
                             acc[mt][nt][2], acc[mt][nt][3],
                             a[mt][0], a[mt][1], a[mt][2], a[mt][3],
                             bL[gq][t2 * 2], bL[gq][t2 * 2 + 1]);
                }
#pragma unroll
            for (int mt = 0; mt < 4; mt++) {
                const int r = warpM * 64 + mt * 16 + (lane & 15);
                const uint32_t o = swz((uint32_t)(r * 128 + 64 + kb + ((lane >> 4) << 4)));
                LDMX4(a[mt][0], a[mt][1], a[mt][2], a[mt][3], uA + o);
            }
#pragma unroll
            for (int mt = 0; mt < 4; mt++)
#pragma unroll
                for (int nt = 0; nt < 4; nt++) {
                    const int gq = nt >> 1, t2 = nt & 1;
                    MMA16816(acc[mt][nt][0], acc[mt][nt][1],
                             acc[mt][nt][2], acc[mt][nt][3],
                             a[mt][0], a[mt][1], a[mt][2], a[mt][3],
                             bH[gq][t2 * 2], bH[gq][t2 * 2 + 1]);
                }
        }
    };

    load_chunk(0, 0);
    CP_COMMIT();

    for (int i = 0; i < NC; i++) {
        const int b = i & 1;
        if (i + 1 < NC) {
            load_chunk(i + 1, b ^ 1);
            CP_COMMIT();
            CP_WAIT1();
        } else {
            CP_WAIT0();
        }
        __syncthreads();
        compute_chunk(b);
        __syncthreads();
    }

    const int g  = lane >> 2;
    const int tg = lane & 3;
#pragma unroll
    for (int mt = 0; mt < 4; mt++) {
        const int row = m0 + warpM * 64 + mt * 16 + g;
#pragma unroll
        for (int nt = 0; nt < 4; nt++) {
            const int col = n0 + warpN * 32 + nt * 8 + tg * 2;
            const size_t i0 = (size_t)row * ldc + col;
            const size_t i1 = (size_t)(row + 8) * ldc + col;
            float2 v0 = make_float2(acc[mt][nt][0], acc[mt][nt][1]);
            float2 v1 = make_float2(acc[mt][nt][2], acc[mt][nt][3]);
            if (resid) {
                float2 r0 = *(const float2*)(resid + i0);
                float2 r1 = *(const float2*)(resid + i1);
                v0.x += r0.x; v0.y += r0.y;
                v1.x += r1.x; v1.y += r1.y;
            }
            *(float2*)(C + i0) = v0;
            *(float2*)(C + i1) = v1;
            if (Chi) {
                uint32_t h0, l0, h1, l1;
                split2(v0.x, v0.y, h0, l0);
                split2(v1.x, v1.y, h1, l1);
                *(uint32_t*)(Chi + i0) = h0;
                *(uint32_t*)(Clo + i0) = l0;
                *(uint32_t*)(Chi + i1) = h1;
                *(uint32_t*)(Clo + i1) = l1;
            }
        }
    }
}

// ---------------------------------------------------------------------------
// fp32 -> bf16 hi/lo split (elementwise)
// ---------------------------------------------------------------------------
__global__ void split_kernel(const float* __restrict__ src,
                             __nv_bfloat16* __restrict__ hi,
                             __nv_bfloat16* __restrict__ lo, size_t n)
{
    const size_t stride = (size_t)gridDim.x * blockDim.x;
    for (size_t i = (size_t)blockIdx.x * blockDim.x + threadIdx.x; i < n; i += stride) {
        float v = src[i];
        __nv_bfloat16 h = __float2bfloat16(v);
        hi[i] = h;
        lo[i] = __float2bfloat16(v - __bfloat162float(h));
    }
}

// fused: g = silu(f1raw) * f3raw, written directly as bf16 hi/lo
__global__ void silu_split_kernel(const float* __restrict__ f1,
                                  const float* __restrict__ f3,
                                  __nv_bfloat16* __restrict__ hi,
                                  __nv_bfloat16* __restrict__ lo, size_t n)
{
    const size_t stride = (size_t)gridDim.x * blockDim.x;
    for (size_t i = (size_t)blockIdx.x * blockDim.x + threadIdx.x; i < n; i += stride) {
        float a = f1[i];
        float gv = a / (1.0f + __expf(-a)) * f3[i];
        __nv_bfloat16 h = __float2bfloat16(gv);
        hi[i] = h;
        lo[i] = __float2bfloat16(gv - __bfloat162float(h));
    }
}

// W [K,N] fp32 -> W^T [N,K] bf16 hi/lo.  grid=(N/32, K/32), block=(32,8)
__global__ void split_transpose_kernel(const float* __restrict__ W,
                                       __nv_bfloat16* __restrict__ hi,
                                       __nv_bfloat16* __restrict__ lo,
                                       int K, int N)
{
    __shared__ float t[32][33];
    const int nb = blockIdx.x * 32, kb = blockIdx.y * 32;
    const int tx = threadIdx.x, ty = threadIdx.y;
#pragma unroll
    for (int j = 0; j < 4; j++)
        t[ty + j * 8][tx] = W[(size_t)(kb + ty + j * 8) * N + nb + tx];
    __syncthreads();
#pragma unroll
    for (int j = 0; j < 4; j++) {
        const int n = nb + ty + j * 8;
        const float v = t[tx][ty + j * 8];
        __nv_bfloat16 h = __float2bfloat16(v);
        hi[(size_t)n * K + kb + tx] = h;
        lo[(size_t)n * K + kb + tx] = __float2bfloat16(v - __bfloat162float(h));
    }
}

// v [tok][kv*128+d] fp32 -> vt [(b*NKV+kv)*HEADD + d][s] bf16 hi/lo
__global__ void vt_split_kernel(const float* __restrict__ v,
                                __nv_bfloat16* __restrict__ hi,
                                __nv_bfloat16* __restrict__ lo)
{
    __shared__ float t[32][33];
    const int z = blockIdx.z, b = z >> 3, kvh = z & 7;
    const int sb = blockIdx.x * 32, db = blockIdx.y * 32;
    const int tx = threadIdx.x, ty = threadIdx.y;
#pragma unroll
    for (int j = 0; j < 4; j++)
        t[ty + j * 8][tx] =
            v[(size_t)(b * SEQL + sb + ty + j * 8) * KVD + kvh * HEADD + db + tx];
    __syncthreads();
#pragma unroll
    for (int j = 0; j < 4; j++) {
        const int d = db + ty + j * 8, s = sb + tx;
        const float val = t[tx][ty + j * 8];
        __nv_bfloat16 h = __float2bfloat16(val);
        const size_t o = ((size_t)(b * NKV + kvh) * HEADD + d) * SEQL + s;
        hi[o] = h;
        lo[o] = __float2bfloat16(val - __bfloat162float(h));
    }
}

// ---------------------------------------------------------------------------
// RoPE (interleaved pairs)
// ---------------------------------------------------------------------------
__global__ void rope_kernel(float* __restrict__ t,
                            const float* __restrict__ fcos,
                            const float* __restrict__ fsin,
                            int nheads, int npairs_total)
{
    int gid = blockIdx.x * blockDim.x + threadIdx.x;
    if (gid >= npairs_total) return;
    int i    = gid & 63;
    int rest = gid >> 6;
    int hh   = rest % nheads;
    int tok  = rest / nheads;
    int s    = tok & (SEQL - 1);
    float c  = fcos[s * 64 + i];
    float sn = fsin[s * 64 + i];
    size_t base = ((size_t)tok * nheads + hh) * HEADD + 2 * i;
    float a = t[base], b = t[base + 1];
    t[base]     = a * c - b * sn;
    t[base + 1] = a * sn + b * c;
}

// ---------------------------------------------------------------------------
// HMMA flash attention, causal, 3-pass hi/lo.  Output written directly as
// bf16 hi/lo (A-operand layout for the Wo GEMM).
// ---------------------------------------------------------------------------
#define SQ_HI 0
#define SQ_LO 32768
#define SKV0  65536
#define KVSTG 65536
#define FLASH_SMEM (SKV0 + 2 * KVSTG)   /* 196608 */

__global__ void __launch_bounds__(256) flash_mma_kernel(
    const __nv_bfloat16* __restrict__ qhi, const __nv_bfloat16* __restrict__ qlo,
    const __nv_bfloat16* __restrict__ khi, const __nv_bfloat16* __restrict__ klo,
    const __nv_bfloat16* __restrict__ vthi, const __nv_bfloat16* __restrict__ vtlo,
    __nv_bfloat16* __restrict__ ohi, __nv_bfloat16* __restrict__ olo)
{
    extern __shared__ char smc[];
    const uint32_t sb = smem_u32(smc);
    const int z = blockIdx.y, b = z >> 5, h = z & 31, kv = h >> 2;
    const int qt = blockIdx.x, q0 = qt * 128;
    const int tid = threadIdx.x, lane = tid & 31, w = tid >> 5;
    const int g = lane >> 2, tg = lane & 3;

    {
        const __nv_bfloat16* qh = qhi + (size_t)(b * SEQL + q0) * QD + h * HEADD;
        const __nv_bfloat16* ql = qlo + (size_t)(b * SEQL + q0) * QD + h * HEADD;
#pragma unroll
        for (int it = 0; it < 8; it++) {
            const int idx = tid + it * 256;
            const int sub = idx >> 10, rem = idx & 1023;
            const int r = rem >> 3, cc = rem & 7;
            const uint32_t o = swz((uint32_t)(r * 128 + cc * 16));
            const size_t src = (size_t)r * QD + sub * 64 + cc * 8;
            CP_ASYNC16(sb + SQ_HI + sub * 16384 + o, qh + src);
            CP_ASYNC16(sb + SQ_LO + sub * 16384 + o, ql + src);
        }
        CP_COMMIT();
    }

    const int nkt = 2 * qt + 2;
    auto load_kv = [&](int kt) {
        const uint32_t base = sb + SKV0 + (kt & 1) * KVSTG;
        const int s0 = kt * 64;
        const __nv_bfloat16* kh = khi + (size_t)(b * SEQL + s0) * KVD + kv * HEADD;
        const __nv_bfloat16* kl = klo + (size_t)(b * SEQL + s0) * KVD + kv * HEADD;
#pragma unroll
        for (int it = 0; it < 4; it++) {
            const int idx = tid + it * 256;
            const int sub = idx >> 9, rem = idx & 511;
            const int r = rem >> 3, cc = rem & 7;
            const uint32_t o = swz((uint32_t)(r * 128 + cc * 16));
            const size_t src = (size_t)r * KVD + sub * 64 + cc * 8;
            CP_ASYNC16(base + sub * 8192 + o, kh + src);
            CP_ASYNC16(base + 16384 + sub * 8192 + o, kl + src);
        }
        const __nv_bfloat16* vh = vthi + (size_t)(b * NKV + kv) * HEADD * SEQL + s0;
        const __nv_bfloat16* vl = vtlo + (size_t)(b * NKV + kv) * HEADD * SEQL + s0;
#pragma unroll
        for (int it = 0; it < 4; it++) {
            const int idx = tid + it * 256;
            const int r = idx >> 3, cc = idx & 7;
            const uint32_t o = swz((uint32_t)(r * 128 + cc * 16));
            const size_t src = (size_t)r * SEQL + cc * 8;
            CP_ASYNC16(base + 32768 + o, vh + src);
            CP_ASYNC16(base + 49152 + o, vl + src);
        }
        CP_COMMIT();
    };
    load_kv(0);
    if (nkt > 1) load_kv(1);

    float m0 = -1e30f, m1 = -1e30f, l0 = 0.f, l1 = 0.f;
    float O[16][4];
#pragma unroll
    for (int nt = 0; nt < 16; nt++)
#pragma unroll
        for (int e = 0; e < 4; e++) O[nt][e] = 0.f;

    const float SC = 0.08838834764831843f;

    for (int kt = 0; kt < nkt; kt++) {
        if (kt + 1 < nkt) CP_WAIT1(); else CP_WAIT0();
        __syncthreads();
        const uint32_t base = sb + SKV0 + (kt & 1) * KVSTG;

        float S[8][4];
#pragma unroll
        for (int nt = 0; nt < 8; nt++)
#pragma unroll
            for (int e = 0; e < 4; e++) S[nt][e] = 0.f;

#pragma unroll
        for (int ks = 0; ks < 8; ks++) {
            const int sub = ks >> 2, kb = (ks & 3) * 32;
            const uint32_t oA =
                swz((uint32_t)((w * 16 + (lane & 15)) * 128 + kb + ((lane >> 4) << 4)));
            uint32_t aH[4], aL[4];
            LDMX4(aH[0], aH[1], aH[2], aH[3], sb + SQ_HI + sub * 16384 + oA);
            LDMX4(aL[0], aL[1], aL[2], aL[3], sb + SQ_LO + sub * 16384 + oA);
#pragma unroll
            for (int nb = 0; nb < 4; nb++) {
                const uint32_t oB = swz((uint32_t)(
                    (nb * 16 + (lane & 7) + ((lane >> 4) << 3)) * 128 +
                    kb + (((lane >> 3) & 1) << 4)));
                uint32_t bH[4], bL[4];
                LDMX4(bH[0], bH[1], bH[2], bH[3], base + sub * 8192 + oB);
                LDMX4(bL[0], bL[1], bL[2], bL[3], base + 16384 + sub * 8192 + oB);
#pragma unroll
                for (int t2 = 0; t2 < 2; t2++) {
                    const int nt = nb * 2 + t2;
                    MMA16816(S[nt][0], S[nt][1], S[nt][2], S[nt][3],
                             aH[0], aH[1], aH[2], aH[3], bH[t2 * 2], bH[t2 * 2 + 1]);
                    MMA16816(S[nt][0], S[nt][1], S[nt][2], S[nt][3],
                             aH[0], aH[1], aH[2], aH[3], bL[t2 * 2], bL[t2 * 2 + 1]);
                    MMA16816(S[nt][0], S[nt][1], S[nt][2], S[nt][3],
                             aL[0], aL[1], aL[2], aL[3], bH[t2 * 2], bH[t2 * 2 + 1]);
                }
            }
        }

        const int s0 = kt * 64;
        const int row0 = q0 + w * 16 + g;
#pragma unroll
        for (int nt = 0; nt < 8; nt++)
#pragma unroll
            for (int e = 0; e < 2; e++) {
                const int col = s0 + nt * 8 + tg * 2 + e;
                float v0 = S[nt][e] * SC;
                float v1 = S[nt][2 + e] * SC;
                if (col > row0)     v0 = -1e30f;
                if (col > row0 + 8) v1 = -1e30f;
                S[nt][e] = v0;
                S[nt][2 + e] = v1;
            }
        float tm0 = -1e30f, tm1 = -1e30f;
#pragma unroll
        for (int nt = 0; nt < 8; nt++) {
            tm0 = fmaxf(tm0, fmaxf(S[nt][0], S[nt][1]));
            tm1 = fmaxf(tm1, fmaxf(S[nt][2], S[nt][3]));
        }
        tm0 = fmaxf(tm0, __shfl_xor_sync(0xffffffffu, tm0, 1));
        tm0 = fmaxf(tm0, __shfl_xor_sync(0xffffffffu, tm0, 2));
        tm1 = fmaxf(tm1, __shfl_xor_sync(0xffffffffu, tm1, 1));
        tm1 = fmaxf(tm1, __shfl_xor_sync(0xffffffffu, tm1, 2));
        const float mn0 = fmaxf(m0, tm0), mn1 = fmaxf(m1, tm1);
        const float sc0 = __expf(m0 - mn0), sc1 = __expf(m1 - mn1);
        m0 = mn0; m1 = mn1;
        float ts0 = 0.f, ts1 = 0.f;
#pragma unroll
        for (int nt = 0; nt < 8; nt++) {
            S[nt][0] = __expf(S[nt][0] - mn0);
            S[nt][1] = __expf(S[nt][1] - mn0);
            S[nt][2] = __expf(S[nt][2] - mn1);
            S[nt][3] = __expf(S[nt][3] - mn1);
            ts0 += S[nt][0] + S[nt][1];
            ts1 += S[nt][2] + S[nt][3];
        }
        ts0 += __shfl_xor_sync(0xffffffffu, ts0, 1);
        ts0 += __shfl_xor_sync(0xffffffffu, ts0, 2);
        ts1 += __shfl_xor_sync(0xffffffffu, ts1, 1);
        ts1 += __shfl_xor_sync(0xffffffffu, ts1, 2);
        l0 = l0 * sc0 + ts0;
        l1 = l1 * sc1 + ts1;
#pragma unroll
        for (int nt = 0; nt < 16; nt++) {
            O[nt][0] *= sc0; O[nt][1] *= sc0;
            O[nt][2] *= sc1; O[nt][3] *= sc1;
        }

#pragma unroll
        for (int ks = 0; ks < 4; ks++) {
            uint32_t pH[4], pL[4];
#pragma unroll
            for (int half = 0; half < 2; half++) {
                const int st = 2 * ks + half;
                split2(S[st][0], S[st][1], pH[half * 2 + 0], pL[half * 2 + 0]);
                split2(S[st][2], S[st][3], pH[half * 2 + 1], pL[half * 2 + 1]);
            }
#pragma unroll
            for (int nb = 0; nb < 8; nb++) {
                const uint32_t oB = swz((uint32_t)(
                    (nb * 16 + (lane & 7) + ((lane >> 4) << 3)) * 128 +
                    ks * 32 + (((lane >> 3) & 1) << 4)));
                uint32_t vH[4], vL[4];
                LDMX4(vH[0], vH[1], vH[2], vH[3], base + 32768 + oB);
                LDMX4(vL[0], vL[1], vL[2], vL[3], base + 49152 + oB);
#pragma unroll
                for (int t2 = 0; t2 < 2; t2++) {
                    const int nt = nb * 2 + t2;
                    MMA16816(O[nt][0], O[nt][1], O[nt][2], O[nt][3],
                             pH[0], pH[1], pH[2], pH[3], vH[t2 * 2], vH[t2 * 2 + 1]);
                    MMA16816(O[nt][0], O[nt][1], O[nt][2], O[nt][3],
                             pL[0], pL[1], pL[2], pL[3], vH[t2 * 2], vH[t2 * 2 + 1]);
                    MMA16816(O[nt][0], O[nt][1], O[nt][2], O[nt][3],
                             pH[0], pH[1], pH[2], pH[3], vL[t2 * 2], vL[t2 * 2 + 1]);
                }
            }
        }
        __syncthreads();
        if (kt + 2 < nkt) load_kv(kt + 2);
    }

    // ---- normalize + write bf16 hi/lo directly (A-operand layout)
    const float il0 = 1.0f / l0, il1 = 1.0f / l1;
    __nv_bfloat16* OH = ohi + (size_t)(b * SEQL) * QD + h * HEADD;
    __nv_bfloat16* OL = olo + (size_t)(b * SEQL) * QD + h * HEADD;
#pragma unroll
    for (int nt = 0; nt < 16; nt++) {
        const int col = nt * 8 + tg * 2;
        const size_t i0 = (size_t)(q0 + w * 16 + g) * QD + col;
        const size_t i1 = (size_t)(q0 + w * 16 + g + 8) * QD + col;
        uint32_t h0, lo0, h1, lo1;
        split2(O[nt][0] * il0, O[nt][1] * il0, h0, lo0);
        split2(O[nt][2] * il1, O[nt][3] * il1, h1, lo1);
        *(uint32_t*)(OH + i0) = h0;
        *(uint32_t*)(OL + i0) = lo0;
        *(uint32_t*)(OH + i1) = h1;
        *(uint32_t*)(OL + i1) = lo1;
    }
}

// ---------------------------------------------------------------------------
// kernel_launch
// ---------------------------------------------------------------------------
extern "C" void kernel_launch(void* const* d_in, const int* in_sizes, int n_in,
                              void* d_out, int out_size)
{
    const float* x    = (const float*)d_in[0];
    /* d_in[1] = mask (unused; causal handled analytically) */
    const float* fcos = (const float*)d_in[2];
    const float* fsin = (const float*)d_in[3];
    const float* wq   = (const float*)d_in[4];
    const float* wk   = (const float*)d_in[5];
    const float* wv   = (const float*)d_in[6];
    const float* wo   = (const float*)d_in[7];
    const float* w1   = (const float*)d_in[8];
    const float* w2   = (const float*)d_in[9];
    const float* w3   = (const float*)d_in[10];
    float* out = (float*)d_out;

    float *q, *k, *v, *h, *f1, *f3;
    __nv_bfloat16 *ahi, *alo, *whi, *wlo;
    __nv_bfloat16 *qhi, *qlo, *khi, *klo, *vthi, *vtlo;
    cudaGetSymbolAddress((void**)&q,    g_q);
    cudaGetSymbolAddress((void**)&k,    g_k);
    cudaGetSymbolAddress((void**)&v,    g_v);
    cudaGetSymbolAddress((void**)&h,    g_h);
    cudaGetSymbolAddress((void**)&f1,   g_f1);
    cudaGetSymbolAddress((void**)&f3,   g_f3);
    cudaGetSymbolAddress((void**)&ahi,  g_ahi);
    cudaGetSymbolAddress((void**)&alo,  g_alo);
    cudaGetSymbolAddress((void**)&whi,  g_whi);
    cudaGetSymbolAddress((void**)&wlo,  g_wlo);
    cudaGetSymbolAddress((void**)&qhi,  g_qhi);
    cudaGetSymbolAddress((void**)&qlo,  g_qlo);
    cudaGetSymbolAddress((void**)&khi,  g_khi);
    cudaGetSymbolAddress((void**)&klo,  g_klo);
    cudaGetSymbolAddress((void**)&vthi, g_vthi);
    cudaGetSymbolAddress((void**)&vtlo, g_vtlo);

    static int attr_done = 0;
    if (!attr_done) {
        cudaFuncSetAttribute(mma_gemm,
            cudaFuncAttributeMaxDynamicSharedMemorySize, GEMM_SMEM);
        cudaFuncSetAttribute(flash_mma_kernel,
            cudaFuncAttributeMaxDynamicSharedMemorySize, FLASH_SMEM);
        attr_done = 1;
    }

    const dim3 tb(32, 8);

    // x -> bf16 split (shared by Q/K/V projections)
    split_kernel<<<2048, 256>>>(x, ahi, alo, (size_t)TOK * DIM);

    // QKV projections (fp32 out for RoPE)
    split_transpose_kernel<<<dim3(QD / 32, DIM / 32), tb>>>(wq, whi, wlo, DIM, QD);
    mma_gemm<<<dim3(QD / 128, TOK / 128), 256, GEMM_SMEM>>>(
        ahi, alo, whi, wlo, nullptr, q, nullptr, nullptr, DIM, QD);
    split_transpose_kernel<<<dim3(KVD / 32, DIM / 32), tb>>>(wk, whi, wlo, DIM, KVD);
    mma_gemm<<<dim3(KVD / 128, TOK / 128), 256, GEMM_SMEM>>>(
        ahi, alo, whi, wlo, nullptr, k, nullptr, nullptr, DIM, KVD);
    split_transpose_kernel<<<dim3(KVD / 32, DIM / 32), tb>>>(wv, whi, wlo, DIM, KVD);
    mma_gemm<<<dim3(KVD / 128, TOK / 128), 256, GEMM_SMEM>>>(
        ahi, alo, whi, wlo, nullptr, v, nullptr, nullptr, DIM, KVD);

    // RoPE
    {
        int nq  = TOK * NH  * 64;
        int nk2 = TOK * NKV * 64;
        rope_kernel<<<(nq + 255) / 256, 256>>>(q, fcos, fsin, NH,  nq);
        rope_kernel<<<(nk2 + 255) / 256, 256>>>(k, fcos, fsin, NKV, nk2);
    }

    // convert flash operands to bf16 hi/lo (V transposed per kv-head)
    split_kernel<<<2048, 256>>>(q, qhi, qlo, (size_t)TOK * QD);
    split_kernel<<<1024, 256>>>(k, khi, klo, (size_t)TOK * KVD);
    vt_split_kernel<<<dim3(SEQL / 32, HEADD / 32, BATCH * NKV), tb>>>(v, vthi, vtlo);

    // HMMA flash attention -> attn out directly as bf16 hi/lo (into ahi/alo)
    flash_mma_kernel<<<dim3(SEQL / 128, BATCH * NH), 256, FLASH_SMEM>>>(
        qhi, qlo, khi, klo, vthi, vtlo, ahi, alo);

    // h = x + attn @ wo ; epilogue also emits h as bf16 hi/lo into qhi/qlo
    split_transpose_kernel<<<dim3(DIM / 32, QD / 32), tb>>>(wo, whi, wlo, QD, DIM);
    mma_gemm<<<dim3(DIM / 128, TOK / 128), 256, GEMM_SMEM>>>(
        ahi, alo, whi, wlo, x, h, qhi, qlo, QD, DIM);

    // FFN: f1 = h @ w1, f3 = h @ w3 (fp32 out)
    split_transpose_kernel<<<dim3(HIDDEN / 32, DIM / 32), tb>>>(w1, whi, wlo, DIM, HIDDEN);
    mma_gemm<<<dim3(HIDDEN / 128, TOK / 128), 256, GEMM_SMEM>>>(
        qhi, qlo, whi, wlo, nullptr, f1, nullptr, nullptr, DIM, HIDDEN);
    split_transpose_kernel<<<dim3(HIDDEN / 32, DIM / 32), tb>>>(w3, whi, wlo, DIM, HIDDEN);
    mma_gemm<<<dim3(HIDDEN / 128, TOK / 128), 256, GEMM_SMEM>>>(
        qhi, qlo, whi, wlo, nullptr, f3, nullptr, nullptr, DIM, HIDDEN);

    // gated = silu(f1) * f3 -> bf16 hi/lo directly (never materialized fp32)
    silu_split_kernel<<<4096, 256>>>(f1, f3, ahi, alo, (size_t)TOK * HIDDEN);

    // out = h + gated @ w2
    split_transpose_kernel<<<dim3(DIM / 32, HIDDEN / 32), tb>>>(w2, whi, wlo, HIDDEN, DIM);
    mma_gemm<<<dim3(DIM / 128, TOK / 128), 256, GEMM_SMEM>>>(
        ahi, alo, whi, wlo, h, out, nullptr, nullptr, HIDDEN, DIM);
}

// round 11
// speedup vs baseline: 1.0615x; 1.0047x over previous
#include <cuda_runtime.h>
#include <cuda_bf16.h>
#include <math.h>
#include <stddef.h>
#include <stdint.h>

// ---------------------------------------------------------------------------
// Problem constants
// ---------------------------------------------------------------------------
#define BATCH   2
#define SEQL    2048
#define DIM     4096
#define NH      32
#define NKV     8
#define HEADD   128
#define HIDDEN  11008
#define TOK     (BATCH * SEQL)        /* 4096 */
#define QD      (NH  * HEADD)         /* 4096 */
#define KVD     (NKV * HEADD)         /* 1024 */
#define QKVN    (QD + 2 * KVD)        /* 6144 */
#define VOFF    (QD + KVD)            /* 5120 */
#define MAXEL   ((size_t)TOK * HIDDEN)
#define WMAX    ((size_t)(2 * HIDDEN) * DIM)   /* 90.2M: packed w1|w3 */

// ---------------------------------------------------------------------------
// Scratch (static device globals; allocation-free per harness rules)
// ---------------------------------------------------------------------------
__device__ float g_h [(size_t)TOK * DIM];     // residual h
__device__ float g_f1[MAXEL];                 // qkv fp32 (reused), then f1
__device__ float g_f3[MAXEL];                 // f3
__device__ __nv_bfloat16 g_ahi[MAXEL];        // x / attn / gated hi
__device__ __nv_bfloat16 g_alo[MAXEL];
__device__ __nv_bfloat16 g_whi[WMAX];         // packed W^T hi
__device__ __nv_bfloat16 g_wlo[WMAX];
__device__ __nv_bfloat16 g_qhi[(size_t)TOK * QD];   // q hi/lo, then h hi/lo
__device__ __nv_bfloat16 g_qlo[(size_t)TOK * QD];
__device__ __nv_bfloat16 g_khi[(size_t)TOK * KVD];
__device__ __nv_bfloat16 g_klo[(size_t)TOK * KVD];
__device__ __nv_bfloat16 g_vthi[(size_t)TOK * KVD]; // [B][NKV][HEADD][SEQL]
__device__ __nv_bfloat16 g_vtlo[(size_t)TOK * KVD];

// ---------------------------------------------------------------------------
// PTX helpers (sm_100-safe: cp.async / ldmatrix / mma.sync only)
// ---------------------------------------------------------------------------
__device__ __forceinline__ uint32_t smem_u32(const void* p) {
    uint32_t a;
    asm("{ .reg .u64 t; cvta.to.shared.u64 t, %1; cvt.u32.u64 %0, t; }"
        : "=r"(a) : "l"(p));
    return a;
}
#define CP_ASYNC16(dst, src) \
    asm volatile("cp.async.cg.shared.global [%0], [%1], 16;" \
                 :: "r"(dst), "l"(src) : "memory")
#define CP_COMMIT() asm volatile("cp.async.commit_group;" ::: "memory")
#define CP_WAIT0()  asm volatile("cp.async.wait_group 0;" ::: "memory")
#define CP_WAIT1()  asm volatile("cp.async.wait_group 1;" ::: "memory")

#define LDMX4(r0, r1, r2, r3, addr) \
    asm volatile("ldmatrix.sync.aligned.m8n8.x4.shared.b16 {%0,%1,%2,%3}, [%4];" \
                 : "=r"(r0), "=r"(r1), "=r"(r2), "=r"(r3) : "r"(addr))

#define MMA16816(c0, c1, c2, c3, a0, a1, a2, a3, b0, b1) \
    asm volatile("mma.sync.aligned.m16n8k16.row.col.f32.bf16.bf16.f32 " \
                 "{%0,%1,%2,%3}, {%4,%5,%6,%7}, {%8,%9}, {%0,%1,%2,%3};" \
                 : "+f"(c0), "+f"(c1), "+f"(c2), "+f"(c3) \
                 : "r"(a0), "r"(a1), "r"(a2), "r"(a3), "r"(b0), "r"(b1))

__device__ __forceinline__ uint32_t swz(uint32_t o) { return o ^ ((o >> 3) & 0x70); }

__device__ __forceinline__ uint32_t pack_bf16x2(float x, float y) {
    __nv_bfloat162 t = __floats2bfloat162_rn(x, y);
    return *(uint32_t*)&t;
}
__device__ __forceinline__ void split2(float x, float y, uint32_t& hi, uint32_t& lo) {
    __nv_bfloat16 hx = __float2bfloat16(x), hy = __float2bfloat16(y);
    __nv_bfloat162 hh; hh.x = hx; hh.y = hy;
    hi = *(uint32_t*)&hh;
    lo = pack_bf16x2(x - __bfloat162float(hx), y - __bfloat162float(hy));
}

// ---------------------------------------------------------------------------
// bf16 HMMA GEMM, hi/lo-fused smem rows; round-8 proven mainloop (2-stage,
// 64 KB, 2 CTAs/SM, 2 syncs/chunk).  Epilogue extensions:
//   * C2/nsplit: tile-granular output routing (merged W1|W3)
//   * Chi/Clo:   optional bf16 hi/lo duplicate output
// ---------------------------------------------------------------------------
#define STG 32768
#define GEMM_SMEM 65536

__global__ void __launch_bounds__(256, 2) mma_gemm(
    const __nv_bfloat16* __restrict__ Ahi, const __nv_bfloat16* __restrict__ Alo,
    const __nv_bfloat16* __restrict__ Bhi, const __nv_bfloat16* __restrict__ Blo,
    const float* __restrict__ resid, float* __restrict__ C,
    float* __restrict__ C2, int nsplit,
    __nv_bfloat16* __restrict__ Chi, __nv_bfloat16* __restrict__ Clo,
    int K, int ldc)
{
    extern __shared__ char smc[];
    const uint32_t sbase = smem_u32(smc);
    const int tid   = threadIdx.x;
    const int lane  = tid & 31;
    const int wid   = tid >> 5;
    const int warpM = wid >> 2;
    const int warpN = wid & 3;
    const int m0 = blockIdx.y * 128;
    const int n0 = blockIdx.x * 128;

    const int NC = K >> 5;

    float acc[4][4][4];
#pragma unroll
    for (int mt = 0; mt < 4; mt++)
#pragma unroll
        for (int nt = 0; nt < 4; nt++)
#pragma unroll
            for (int e = 0; e < 4; e++) acc[mt][nt][e] = 0.f;

    auto load_chunk = [&](int c, int stage) {
        const int k0 = c << 5;
        const uint32_t uA = sbase + stage * STG;
        const uint32_t uB = uA + 16384;
#pragma unroll
        for (int it = 0; it < 4; it++) {
            const int idx = tid + it * 256;
            const int r  = idx >> 3;
            const int cc = idx & 7;
            const uint32_t o = swz((uint32_t)(r * 128 + cc * 16));
            const int kk = k0 + (cc & 3) * 8;
            const __nv_bfloat16* As = (cc < 4) ? Ahi : Alo;
            const __nv_bfloat16* Bs = (cc < 4) ? Bhi : Blo;
            CP_ASYNC16(uA + o, As + (size_t)(m0 + r) * K + kk);
            CP_ASYNC16(uB + o, Bs + (size_t)(n0 + r) * K + kk);
        }
    };

    auto compute_chunk = [&](int stage) {
        const uint32_t uA = sbase + stage * STG;
        const uint32_t uB = uA + 16384;
#pragma unroll
        for (int ks = 0; ks < 2; ks++) {
            const int kb = ks * 32;
            uint32_t a[4][4];
#pragma unroll
            for (int mt = 0; mt < 4; mt++) {
                const int r = warpM * 64 + mt * 16 + (lane & 15);
                const uint32_t o = swz((uint32_t)(r * 128 + kb + ((lane >> 4) << 4)));
                LDMX4(a[mt][0], a[mt][1], a[mt][2], a[mt][3], uA + o);
            }
            uint32_t bH[2][4], bL[2][4];
#pragma unroll
            for (int g = 0; g < 2; g++) {
                const int r = warpN * 32 + g * 16 + (lane & 7) + ((lane >> 4) << 3);
                const uint32_t col = kb + (((lane >> 3) & 1) << 4);
                const uint32_t oH = swz((uint32_t)(r * 128 + col));
                const uint32_t oL = swz((uint32_t)(r * 128 + 64 + col));
                LDMX4(bH[g][0], bH[g][1], bH[g][2], bH[g][3], uB + oH);
                LDMX4(bL[g][0], bL[g][1], bL[g][2], bL[g][3], uB + oL);
            }
#pragma unroll
            for (int mt = 0; mt < 4; mt++)
#pragma unroll
                for (int nt = 0; nt < 4; nt++) {
                    const int gq = nt >> 1, t2 = nt & 1;
                    MMA16816(acc[mt][nt][0], acc[mt][nt][1],
                             acc[mt][nt][2], acc[mt][nt][3],
                             a[mt][0], a[mt][1], a[mt][2], a[mt][3],
                             bH[gq][t2 * 2], bH[gq][t2 * 2 + 1]);
                    MMA16816(acc[mt][nt][0], acc[mt][nt][1],
                             acc[mt][nt][2], acc[mt][nt][3],
                             a[mt][0], a[mt][1], a[mt][2], a[mt][3],
                             bL[gq][t2 * 2], bL[gq][t2 * 2 + 1]);
                }
#pragma unroll
            for (int mt = 0; mt < 4; mt++) {
                const int r = warpM * 64 + mt * 16 + (lane & 15);
                const uint32_t o = swz((uint32_t)(r * 128 + 64 + kb + ((lane >> 4) << 4)));
                LDMX4(a[mt][0], a[mt][1], a[mt][2], a[mt][3], uA + o);
            }
#pragma unroll
            for (int mt = 0; mt < 4; mt++)
#pragma unroll
                for (int nt = 0; nt < 4; nt++) {
                    const int gq = nt >> 1, t2 = nt & 1;
                    MMA16816(acc[mt][nt][0], acc[mt][nt][1],
                             acc[mt][nt][2], acc[mt][nt][3],
                             a[mt][0], a[mt][1], a[mt][2], a[mt][3],
                             bH[gq][t2 * 2], bH[gq][t2 * 2 + 1]);
                }
        }
    };

    load_chunk(0, 0);
    CP_COMMIT();

    for (int i = 0; i < NC; i++) {
        const int b = i & 1;
        if (i + 1 < NC) {
            load_chunk(i + 1, b ^ 1);
            CP_COMMIT();
            CP_WAIT1();
        } else {
            CP_WAIT0();
        }
        __syncthreads();
        compute_chunk(b);
        __syncthreads();
    }

    // output routing (merged W1|W3): whole 128-tile goes to one side
    float* Cout = C;
    int nbase = n0;
    if (C2 && n0 >= nsplit) { Cout = C2; nbase = n0 - nsplit; }

    const int g  = lane >> 2;
    const int tg = lane & 3;
#pragma unroll
    for (int mt = 0; mt < 4; mt++) {
        const int row = m0 + warpM * 64 + mt * 16 + g;
#pragma unroll
        for (int nt = 0; nt < 4; nt++) {
            const int col = nbase + warpN * 32 + nt * 8 + tg * 2;
            const size_t i0 = (size_t)row * ldc + col;
            const size_t i1 = (size_t)(row + 8) * ldc + col;
            float2 v0 = make_float2(acc[mt][nt][0], acc[mt][nt][1]);
            float2 v1 = make_float2(acc[mt][nt][2], acc[mt][nt][3]);
            if (resid) {
                float2 r0 = *(const float2*)(resid + i0);
                float2 r1 = *(const float2*)(resid + i1);
                v0.x += r0.x; v0.y += r0.y;
                v1.x += r1.x; v1.y += r1.y;
            }
            *(float2*)(Cout + i0) = v0;
            *(float2*)(Cout + i1) = v1;
            if (Chi) {
                uint32_t h0, l0, h1, l1;
                split2(v0.x, v0.y, h0, l0);
                split2(v1.x, v1.y, h1, l1);
                *(uint32_t*)(Chi + i0) = h0;
                *(uint32_t*)(Clo + i0) = l0;
                *(uint32_t*)(Chi + i1) = h1;
                *(uint32_t*)(Clo + i1) = l1;
            }
        }
    }
}

// ---------------------------------------------------------------------------
// fp32 -> bf16 hi/lo split (elementwise)
// ---------------------------------------------------------------------------
__global__ void split_kernel(const float* __restrict__ src,
                             __nv_bfloat16* __restrict__ hi,
                             __nv_bfloat16* __restrict__ lo, size_t n)
{
    const size_t stride = (size_t)gridDim.x * blockDim.x;
    for (size_t i = (size_t)blockIdx.x * blockDim.x + threadIdx.x; i < n; i += stride) {
        float v = src[i];
        __nv_bfloat16 h = __float2bfloat16(v);
        hi[i] = h;
        lo[i] = __float2bfloat16(v - __bfloat162float(h));
    }
}

// fused: g = silu(f1) * f3 -> bf16 hi/lo directly
__global__ void silu_split_kernel(const float* __restrict__ f1,
                                  const float* __restrict__ f3,
                                  __nv_bfloat16* __restrict__ hi,
                                  __nv_bfloat16* __restrict__ lo, size_t n)
{
    const size_t stride = (size_t)gridDim.x * blockDim.x;
    for (size_t i = (size_t)blockIdx.x * blockDim.x + threadIdx.x; i < n; i += stride) {
        float a = f1[i];
        float gv = a / (1.0f + __expf(-a)) * f3[i];
        __nv_bfloat16 h = __float2bfloat16(gv);
        hi[i] = h;
        lo[i] = __float2bfloat16(gv - __bfloat162float(h));
    }
}

// W [K,N] fp32 -> W^T [N,K] bf16 hi/lo (written at caller-provided offset)
__global__ void split_transpose_kernel(const float* __restrict__ W,
                                       __nv_bfloat16* __restrict__ hi,
                                       __nv_bfloat16* __restrict__ lo,
                                       int K, int N)
{
    __shared__ float t[32][33];
    const int nb = blockIdx.x * 32, kb = blockIdx.y * 32;
    const int tx = threadIdx.x, ty = threadIdx.y;
#pragma unroll
    for (int j = 0; j < 4; j++)
        t[ty + j * 8][tx] = W[(size_t)(kb + ty + j * 8) * N + nb + tx];
    __syncthreads();
#pragma unroll
    for (int j = 0; j < 4; j++) {
        const int n = nb + ty + j * 8;
        const float v = t[tx][ty + j * 8];
        __nv_bfloat16 h = __float2bfloat16(v);
        hi[(size_t)n * K + kb + tx] = h;
        lo[(size_t)n * K + kb + tx] = __float2bfloat16(v - __bfloat162float(h));
    }
}

// fused RoPE + hi/lo split: reads strided fp32 qkv, writes packed hi/lo
__global__ void rope_split_kernel(const float* __restrict__ src, int ld, int coloff,
                                  const float* __restrict__ fcos,
                                  const float* __restrict__ fsin,
                                  int nheads,
                                  __nv_bfloat16* __restrict__ hi,
                                  __nv_bfloat16* __restrict__ lo,
                                  int npairs)
{
    int gid = blockIdx.x * blockDim.x + threadIdx.x;
    if (gid >= npairs) return;
    const int i    = gid & 63;
    const int rest = gid >> 6;
    const int hh   = rest % nheads;
    const int tok  = rest / nheads;
    const int s    = tok & (SEQL - 1);
    const float c  = fcos[s * 64 + i];
    const float sn = fsin[s * 64 + i];
    const float* p = src + (size_t)tok * ld + coloff + hh * HEADD + 2 * i;
    const float a = p[0], b = p[1];
    const float r0 = a * c - b * sn;
    const float r1 = a * sn + b * c;
    const size_t ob = ((size_t)tok * nheads + hh) * HEADD + 2 * i;
    uint32_t h2, l2;
    split2(r0, r1, h2, l2);
    *(uint32_t*)(hi + ob) = h2;
    *(uint32_t*)(lo + ob) = l2;
}

// v slice of qkv [tok][VOFF + kv*128+d] -> vt [(b*NKV+kv)*HEADD + d][s] hi/lo
__global__ void vt_split_kernel(const float* __restrict__ qkv,
                                __nv_bfloat16* __restrict__ hi,
                                __nv_bfloat16* __restrict__ lo)
{
    __shared__ float t[32][33];
    const int z = blockIdx.z, b = z >> 3, kvh = z & 7;
    const int sb = blockIdx.x * 32, db = blockIdx.y * 32;
    const int tx = threadIdx.x, ty = threadIdx.y;
#pragma unroll
    for (int j = 0; j < 4; j++)
        t[ty + j * 8][tx] =
            qkv[(size_t)(b * SEQL + sb + ty + j * 8) * QKVN + VOFF + kvh * HEADD + db + tx];
    __syncthreads();
#pragma unroll
    for (int j = 0; j < 4; j++) {
        const int d = db + ty + j * 8, s = sb + tx;
        const float val = t[tx][ty + j * 8];
        __nv_bfloat16 h = __float2bfloat16(val);
        const size_t o = ((size_t)(b * NKV + kvh) * HEADD + d) * SEQL + s;
        hi[o] = h;
        lo[o] = __float2bfloat16(val - __bfloat162float(h));
    }
}

// ---------------------------------------------------------------------------
// HMMA flash attention, causal, 3-pass hi/lo (unchanged from round 10)
// ---------------------------------------------------------------------------
#define SQ_HI 0
#define SQ_LO 32768
#define SKV0  65536
#define KVSTG 65536
#define FLASH_SMEM (SKV0 + 2 * KVSTG)   /* 196608 */

__global__ void __launch_bounds__(256) flash_mma_kernel(
    const __nv_bfloat16* __restrict__ qhi, const __nv_bfloat16* __restrict__ qlo,
    const __nv_bfloat16* __restrict__ khi, const __nv_bfloat16* __restrict__ klo,
    const __nv_bfloat16* __restrict__ vthi, const __nv_bfloat16* __restrict__ vtlo,
    __nv_bfloat16* __restrict__ ohi, __nv_bfloat16* __restrict__ olo)
{
    extern __shared__ char smc[];
    const uint32_t sb = smem_u32(smc);
    const int z = blockIdx.y, b = z >> 5, h = z & 31, kv = h >> 2;
    const int qt = blockIdx.x, q0 = qt * 128;
    const int tid = threadIdx.x, lane = tid & 31, w = tid >> 5;
    const int g = lane >> 2, tg = lane & 3;

    {
        const __nv_bfloat16* qh = qhi + (size_t)(b * SEQL + q0) * QD + h * HEADD;
        const __nv_bfloat16* ql = qlo + (size_t)(b * SEQL + q0) * QD + h * HEADD;
#pragma unroll
        for (int it = 0; it < 8; it++) {
            const int idx = tid + it * 256;
            const int sub = idx >> 10, rem = idx & 1023;
            const int r = rem >> 3, cc = rem & 7;
            const uint32_t o = swz((uint32_t)(r * 128 + cc * 16));
            const size_t src = (size_t)r * QD + sub * 64 + cc * 8;
            CP_ASYNC16(sb + SQ_HI + sub * 16384 + o, qh + src);
            CP_ASYNC16(sb + SQ_LO + sub * 16384 + o, ql + src);
        }
        CP_COMMIT();
    }

    const int nkt = 2 * qt + 2;
    auto load_kv = [&](int kt) {
        const uint32_t base = sb + SKV0 + (kt & 1) * KVSTG;
        const int s0 = kt * 64;
        const __nv_bfloat16* kh = khi + (size_t)(b * SEQL + s0) * KVD + kv * HEADD;
        const __nv_bfloat16* kl = klo + (size_t)(b * SEQL + s0) * KVD + kv * HEADD;
#pragma unroll
        for (int it = 0; it < 4; it++) {
            const int idx = tid + it * 256;
            const int sub = idx >> 9, rem = idx & 511;
            const int r = rem >> 3, cc = rem & 7;
            const uint32_t o = swz((uint32_t)(r * 128 + cc * 16));
            const size_t src = (size_t)r * KVD + sub * 64 + cc * 8;
            CP_ASYNC16(base + sub * 8192 + o, kh + src);
            CP_ASYNC16(base + 16384 + sub * 8192 + o, kl + src);
        }
        const __nv_bfloat16* vh = vthi + (size_t)(b * NKV + kv) * HEADD * SEQL + s0;
        const __nv_bfloat16* vl = vtlo + (size_t)(b * NKV + kv) * HEADD * SEQL + s0;
#pragma unroll
        for (int it = 0; it < 4; it++) {
            const int idx = tid + it * 256;
            const int r = idx >> 3, cc = idx & 7;
            const uint32_t o = swz((uint32_t)(r * 128 + cc * 16));
            const size_t src = (size_t)r * SEQL + cc * 8;
            CP_ASYNC16(base + 32768 + o, vh + src);
            CP_ASYNC16(base + 49152 + o, vl + src);
        }
        CP_COMMIT();
    };
    load_kv(0);
    if (nkt > 1) load_kv(1);

    float m0 = -1e30f, m1 = -1e30f, l0 = 0.f, l1 = 0.f;
    float O[16][4];
#pragma unroll
    for (int nt = 0; nt < 16; nt++)
#pragma unroll
        for (int e = 0; e < 4; e++) O[nt][e] = 0.f;

    const float SC = 0.08838834764831843f;

    for (int kt = 0; kt < nkt; kt++) {
        if (kt + 1 < nkt) CP_WAIT1(); else CP_WAIT0();
        __syncthreads();
        const uint32_t base = sb + SKV0 + (kt & 1) * KVSTG;

        float S[8][4];
#pragma unroll
        for (int nt = 0; nt < 8; nt++)
#pragma unroll
            for (int e = 0; e < 4; e++) S[nt][e] = 0.f;

#pragma unroll
        for (int ks = 0; ks < 8; ks++) {
            const int sub = ks >> 2, kb = (ks & 3) * 32;
            const uint32_t oA =
                swz((uint32_t)((w * 16 + (lane & 15)) * 128 + kb + ((lane >> 4) << 4)));
            uint32_t aH[4], aL[4];
            LDMX4(aH[0], aH[1], aH[2], aH[3], sb + SQ_HI + sub * 16384 + oA);
            LDMX4(aL[0], aL[1], aL[2], aL[3], sb + SQ_LO + sub * 16384 + oA);
#pragma unroll
            for (int nb = 0; nb < 4; nb++) {
                const uint32_t oB = swz((uint32_t)(
                    (nb * 16 + (lane & 7) + ((lane >> 4) << 3)) * 128 +
                    kb + (((lane >> 3) & 1) << 4)));
                uint32_t bH[4], bL[4];
                LDMX4(bH[0], bH[1], bH[2], bH[3], base + sub * 8192 + oB);
                LDMX4(bL[0], bL[1], bL[2], bL[3], base + 16384 + sub * 8192 + oB);
#pragma unroll
                for (int t2 = 0; t2 < 2; t2++) {
                    const int nt = nb * 2 + t2;
                    MMA16816(S[nt][0], S[nt][1], S[nt][2], S[nt][3],
                             aH[0], aH[1], aH[2], aH[3], bH[t2 * 2], bH[t2 * 2 + 1]);
                    MMA16816(S[nt][0], S[nt][1], S[nt][2], S[nt][3],
                             aH[0], aH[1], aH[2], aH[3], bL[t2 * 2], bL[t2 * 2 + 1]);
                    MMA16816(S[nt][0], S[nt][1], S[nt][2], S[nt][3],
                             aL[0], aL[1], aL[2], aL[3], bH[t2 * 2], bH[t2 * 2 + 1]);
                }
            }
        }

        const int s0 = kt * 64;
        const int row0 = q0 + w * 16 + g;
#pragma unroll
        for (int nt = 0; nt < 8; nt++)
#pragma unroll
            for (int e = 0; e < 2; e++) {
                const int col = s0 + nt * 8 + tg * 2 + e;
                float v0 = S[nt][e] * SC;
                float v1 = S[nt][2 + e] * SC;
                if (col > row0)     v0 = -1e30f;
                if (col > row0 + 8) v1 = -1e30f;
                S[nt][e] = v0;
                S[nt][2 + e] = v1;
            }
        float tm0 = -1e30f, tm1 = -1e30f;
#pragma unroll
        for (int nt = 0; nt < 8; nt++) {
            tm0 = fmaxf(tm0, fmaxf(S[nt][0], S[nt][1]));
            tm1 = fmaxf(tm1, fmaxf(S[nt][2], S[nt][3]));
        }
        tm0 = fmaxf(tm0, __shfl_xor_sync(0xffffffffu, tm0, 1));
        tm0 = fmaxf(tm0, __shfl_xor_sync(0xffffffffu, tm0, 2));
        tm1 = fmaxf(tm1, __shfl_xor_sync(0xffffffffu, tm1, 1));
        tm1 = fmaxf(tm1, __shfl_xor_sync(0xffffffffu, tm1, 2));
        const float mn0 = fmaxf(m0, tm0), mn1 = fmaxf(m1, tm1);
        const float sc0 = __expf(m0 - mn0), sc1 = __expf(m1 - mn1);
        m0 = mn0; m1 = mn1;
        float ts0 = 0.f, ts1 = 0.f;
#pragma unroll
        for (int nt = 0; nt < 8; nt++) {
            S[nt][0] = __expf(S[nt][0] - mn0);
            S[nt][1] = __expf(S[nt][1] - mn0);
            S[nt][2] = __expf(S[nt][2] - mn1);
            S[nt][3] = __expf(S[nt][3] - mn1);
            ts0 += S[nt][0] + S[nt][1];
            ts1 += S[nt][2] + S[nt][3];
        }
        ts0 += __shfl_xor_sync(0xffffffffu, ts0, 1);
        ts0 += __shfl_xor_sync(0xffffffffu, ts0, 2);
        ts1 += __shfl_xor_sync(0xffffffffu, ts1, 1);
        ts1 += __shfl_xor_sync(0xffffffffu, ts1, 2);
        l0 = l0 * sc0 + ts0;
        l1 = l1 * sc1 + ts1;
#pragma unroll
        for (int nt = 0; nt < 16; nt++) {
            O[nt][0] *= sc0; O[nt][1] *= sc0;
            O[nt][2] *= sc1; O[nt][3] *= sc1;
        }

#pragma unroll
        for (int ks = 0; ks < 4; ks++) {
            uint32_t pH[4], pL[4];
#pragma unroll
            for (int half = 0; half < 2; half++) {
                const int st = 2 * ks + half;
                split2(S[st][0], S[st][1], pH[half * 2 + 0], pL[half * 2 + 0]);
                split2(S[st][2], S[st][3], pH[half * 2 + 1], pL[half * 2 + 1]);
            }
#pragma unroll
            for (int nb = 0; nb < 8; nb++) {
                const uint32_t oB = swz((uint32_t)(
                    (nb * 16 + (lane & 7) + ((lane >> 4) << 3)) * 128 +
                    ks * 32 + (((lane >> 3) & 1) << 4)));
                uint32_t vH[4], vL[4];
                LDMX4(vH[0], vH[1], vH[2], vH[3], base + 32768 + oB);
                LDMX4(vL[0], vL[1], vL[2], vL[3], base + 49152 + oB);
#pragma unroll
                for (int t2 = 0; t2 < 2; t2++) {
                    const int nt = nb * 2 + t2;
                    MMA16816(O[nt][0], O[nt][1], O[nt][2], O[nt][3],
                             pH[0], pH[1], pH[2], pH[3], vH[t2 * 2], vH[t2 * 2 + 1]);
                    MMA16816(O[nt][0], O[nt][1], O[nt][2], O[nt][3],
                             pL[0], pL[1], pL[2], pL[3], vH[t2 * 2], vH[t2 * 2 + 1]);
                    MMA16816(O[nt][0], O[nt][1], O[nt][2], O[nt][3],
                             pH[0], pH[1], pH[2], pH[3], vL[t2 * 2], vL[t2 * 2 + 1]);
                }
            }
        }
        __syncthreads();
        if (kt + 2 < nkt) load_kv(kt + 2);
    }

    const float il0 = 1.0f / l0, il1 = 1.0f / l1;
    __nv_bfloat16* OH = ohi + (size_t)(b * SEQL) * QD + h * HEADD;
    __nv_bfloat16* OL = olo + (size_t)(b * SEQL) * QD + h * HEADD;
#pragma unroll
    for (int nt = 0; nt < 16; nt++) {
        const int col = nt * 8 + tg * 2;
        const size_t i0 = (size_t)(q0 + w * 16 + g) * QD + col;
        const size_t i1 = (size_t)(q0 + w * 16 + g + 8) * QD + col;
        uint32_t h0, lo0, h1, lo1;
        split2(O[nt][0] * il0, O[nt][1] * il0, h0, lo0);
        split2(O[nt][2] * il1, O[nt][3] * il1, h1, lo1);
        *(uint32_t*)(OH + i0) = h0;
        *(uint32_t*)(OL + i0) = lo0;
        *(uint32_t*)(OH + i1) = h1;
        *(uint32_t*)(OL + i1) = lo1;
    }
}

// ---------------------------------------------------------------------------
// kernel_launch
// ---------------------------------------------------------------------------
extern "C" void kernel_launch(void* const* d_in, const int* in_sizes, int n_in,
                              void* d_out, int out_size)
{
    const float* x    = (const float*)d_in[0];
    /* d_in[1] = mask (unused; causal handled analytically) */
    const float* fcos = (const float*)d_in[2];
    const float* fsin = (const float*)d_in[3];
    const float* wq   = (const float*)d_in[4];
    const float* wk   = (const float*)d_in[5];
    const float* wv   = (const float*)d_in[6];
    const float* wo   = (const float*)d_in[7];
    const float* w1   = (const float*)d_in[8];
    const float* w2   = (const float*)d_in[9];
    const float* w3   = (const float*)d_in[10];
    float* out = (float*)d_out;

    float *h, *f1, *f3;
    __nv_bfloat16 *ahi, *alo, *whi, *wlo;
    __nv_bfloat16 *qhi, *qlo, *khi, *klo, *vthi, *vtlo;
    cudaGetSymbolAddress((void**)&h,    g_h);
    cudaGetSymbolAddress((void**)&f1,   g_f1);
    cudaGetSymbolAddress((void**)&f3,   g_f3);
    cudaGetSymbolAddress((void**)&ahi,  g_ahi);
    cudaGetSymbolAddress((void**)&alo,  g_alo);
    cudaGetSymbolAddress((void**)&whi,  g_whi);
    cudaGetSymbolAddress((void**)&wlo,  g_wlo);
    cudaGetSymbolAddress((void**)&qhi,  g_qhi);
    cudaGetSymbolAddress((void**)&qlo,  g_qlo);
    cudaGetSymbolAddress((void**)&khi,  g_khi);
    cudaGetSymbolAddress((void**)&klo,  g_klo);
    cudaGetSymbolAddress((void**)&vthi, g_vthi);
    cudaGetSymbolAddress((void**)&vtlo, g_vtlo);

    float* qkv = f1;   // qkv fp32 [TOK, 6144] reuses g_f1 (dead until FFN)

    static int attr_done = 0;
    if (!attr_done) {
        cudaFuncSetAttribute(mma_gemm,
            cudaFuncAttributeMaxDynamicSharedMemorySize, GEMM_SMEM);
        cudaFuncSetAttribute(flash_mma_kernel,
            cudaFuncAttributeMaxDynamicSharedMemorySize, FLASH_SMEM);
        attr_done = 1;
    }

    const dim3 tb(32, 8);

    // x -> bf16 split
    split_kernel<<<2048, 256>>>(x, ahi, alo, (size_t)TOK * DIM);

    // pack wq^T | wk^T | wv^T  (rows 0..4095 | 4096..5119 | 5120..6143)
    split_transpose_kernel<<<dim3(QD / 32, DIM / 32), tb>>>(wq, whi, wlo, DIM, QD);
    split_transpose_kernel<<<dim3(KVD / 32, DIM / 32), tb>>>(
        wk, whi + (size_t)QD * DIM, wlo + (size_t)QD * DIM, DIM, KVD);
    split_transpose_kernel<<<dim3(KVD / 32, DIM / 32), tb>>>(
        wv, whi + (size_t)VOFF * DIM, wlo + (size_t)VOFF * DIM, DIM, KVD);

    // merged QKV projection: [TOK, 6144]
    mma_gemm<<<dim3(QKVN / 128, TOK / 128), 256, GEMM_SMEM>>>(
        ahi, alo, whi, wlo, nullptr, qkv, nullptr, 0, nullptr, nullptr, DIM, QKVN);

    // fused RoPE + split (q, k); V transpose+split
    rope_split_kernel<<<(TOK * NH * 64 + 255) / 256, 256>>>(
        qkv, QKVN, 0, fcos, fsin, NH, qhi, qlo, TOK * NH * 64);
    rope_split_kernel<<<(TOK * NKV * 64 + 255) / 256, 256>>>(
        qkv, QKVN, QD, fcos, fsin, NKV, khi, klo, TOK * NKV * 64);
    vt_split_kernel<<<dim3(SEQL / 32, HEADD / 32, BATCH * NKV), tb>>>(qkv, vthi, vtlo);

    // HMMA flash attention -> attn out as bf16 hi/lo (into ahi/alo)
    flash_mma_kernel<<<dim3(SEQL / 128, BATCH * NH), 256, FLASH_SMEM>>>(
        qhi, qlo, khi, klo, vthi, vtlo, ahi, alo);

    // h = x + attn @ wo ; epilogue also emits h hi/lo into qhi/qlo
    split_transpose_kernel<<<dim3(DIM / 32, QD / 32), tb>>>(wo, whi, wlo, QD, DIM);
    mma_gemm<<<dim3(DIM / 128, TOK / 128), 256, GEMM_SMEM>>>(
        ahi, alo, whi, wlo, x, h, nullptr, 0, qhi, qlo, QD, DIM);

    // merged FFN up-projections: pack w1^T | w3^T (rows 0..11007 | 11008..22015)
    split_transpose_kernel<<<dim3(HIDDEN / 32, DIM / 32), tb>>>(w1, whi, wlo, DIM, HIDDEN);
    split_transpose_kernel<<<dim3(HIDDEN / 32, DIM / 32), tb>>>(
        w3, whi + (size_t)HIDDEN * DIM, wlo + (size_t)HIDDEN * DIM, DIM, HIDDEN);
    mma_gemm<<<dim3((2 * HIDDEN) / 128, TOK / 128), 256, GEMM_SMEM>>>(
        qhi, qlo, whi, wlo, nullptr, f1, f3, HIDDEN, nullptr, nullptr, DIM, HIDDEN);

    // gated = silu(f1) * f3 -> bf16 hi/lo directly
    silu_split_kernel<<<4096, 256>>>(f1, f3, ahi, alo, (size_t)TOK * HIDDEN);

    // out = h + gated @ w2
    split_transpose_kernel<<<dim3(DIM / 32, HIDDEN / 32), tb>>>(w2, whi, wlo, HIDDEN, DIM);
    mma_gemm<<<dim3(DIM / 128, TOK / 128), 256, GEMM_SMEM>>>(
        ahi, alo, whi, wlo, h, out, nullptr, 0, nullptr, nullptr, HIDDEN, DIM);
}

// round 13
// speedup vs baseline: 1.0765x; 1.0141x over previous
#include <cuda_runtime.h>
#include <cuda_bf16.h>
#include <math.h>
#include <stddef.h>
#include <stdint.h>

// ---------------------------------------------------------------------------
// Problem constants
// ---------------------------------------------------------------------------
#define BATCH   2
#define SEQL    2048
#define DIM     4096
#define NH      32
#define NKV     8
#define HEADD   128
#define HIDDEN  11008
#define TOK     (BATCH * SEQL)        /* 4096 */
#define QD      (NH  * HEADD)         /* 4096 */
#define KVD     (NKV * HEADD)         /* 1024 */
#define QKVN    (QD + 2 * KVD)        /* 6144 */
#define VOFF    (QD + KVD)            /* 5120 */
#define MAXEL   ((size_t)TOK * HIDDEN)
#define WMAX    ((size_t)(2 * HIDDEN) * DIM)   /* packed w1|w3 */

// ---------------------------------------------------------------------------
// Scratch (static device globals; allocation-free per harness rules)
// ---------------------------------------------------------------------------
__device__ float g_h [(size_t)TOK * DIM];
__device__ float g_f1[MAXEL];                 // qkv fp32 (reused), then f1
__device__ float g_f3[MAXEL];
__device__ __nv_bfloat16 g_ahi[MAXEL];
__device__ __nv_bfloat16 g_alo[MAXEL];
__device__ __nv_bfloat16 g_whi[WMAX];
__device__ __nv_bfloat16 g_wlo[WMAX];
__device__ __nv_bfloat16 g_qhi[(size_t)TOK * QD];
__device__ __nv_bfloat16 g_qlo[(size_t)TOK * QD];
__device__ __nv_bfloat16 g_khi[(size_t)TOK * KVD];
__device__ __nv_bfloat16 g_klo[(size_t)TOK * KVD];
__device__ __nv_bfloat16 g_vthi[(size_t)TOK * KVD]; // [B][NKV][HEADD][SEQL]
__device__ __nv_bfloat16 g_vtlo[(size_t)TOK * KVD];

// ---------------------------------------------------------------------------
// PTX helpers (sm_100-safe: cp.async / ldmatrix / mma.sync only)
// ---------------------------------------------------------------------------
__device__ __forceinline__ uint32_t smem_u32(const void* p) {
    uint32_t a;
    asm("{ .reg .u64 t; cvta.to.shared.u64 t, %1; cvt.u32.u64 %0, t; }"
        : "=r"(a) : "l"(p));
    return a;
}
#define CP_ASYNC16(dst, src) \
    asm volatile("cp.async.cg.shared.global [%0], [%1], 16;" \
                 :: "r"(dst), "l"(src) : "memory")
#define CP_COMMIT() asm volatile("cp.async.commit_group;" ::: "memory")
#define CP_WAIT0()  asm volatile("cp.async.wait_group 0;" ::: "memory")
#define CP_WAIT1()  asm volatile("cp.async.wait_group 1;" ::: "memory")

#define LDMX4(r0, r1, r2, r3, addr) \
    asm volatile("ldmatrix.sync.aligned.m8n8.x4.shared.b16 {%0,%1,%2,%3}, [%4];" \
                 : "=r"(r0), "=r"(r1), "=r"(r2), "=r"(r3) : "r"(addr))

#define MMA16816(c0, c1, c2, c3, a0, a1, a2, a3, b0, b1) \
    asm volatile("mma.sync.aligned.m16n8k16.row.col.f32.bf16.bf16.f32 " \
                 "{%0,%1,%2,%3}, {%4,%5,%6,%7}, {%8,%9}, {%0,%1,%2,%3};" \
                 : "+f"(c0), "+f"(c1), "+f"(c2), "+f"(c3) \
                 : "r"(a0), "r"(a1), "r"(a2), "r"(a3), "r"(b0), "r"(b1))

__device__ __forceinline__ uint32_t swz(uint32_t o) { return o ^ ((o >> 3) & 0x70); }

__device__ __forceinline__ uint32_t pack_bf16x2(float x, float y) {
    __nv_bfloat162 t = __floats2bfloat162_rn(x, y);
    return *(uint32_t*)&t;
}
__device__ __forceinline__ void split2(float x, float y, uint32_t& hi, uint32_t& lo) {
    __nv_bfloat16 hx = __float2bfloat16(x), hy = __float2bfloat16(y);
    __nv_bfloat162 hh; hh.x = hx; hh.y = hy;
    hi = *(uint32_t*)&hh;
    lo = pack_bf16x2(x - __bfloat162float(hx), y - __bfloat162float(hy));
}

// ---------------------------------------------------------------------------
// bf16 HMMA GEMM (unchanged proven mainloop + routed epilogue)
// ---------------------------------------------------------------------------
#define STG 32768
#define GEMM_SMEM 65536

__global__ void __launch_bounds__(256, 2) mma_gemm(
    const __nv_bfloat16* __restrict__ Ahi, const __nv_bfloat16* __restrict__ Alo,
    const __nv_bfloat16* __restrict__ Bhi, const __nv_bfloat16* __restrict__ Blo,
    const float* __restrict__ resid, float* __restrict__ C,
    float* __restrict__ C2, int nsplit,
    __nv_bfloat16* __restrict__ Chi, __nv_bfloat16* __restrict__ Clo,
    int K, int ldc)
{
    extern __shared__ char smc[];
    const uint32_t sbase = smem_u32(smc);
    const int tid   = threadIdx.x;
    const int lane  = tid & 31;
    const int wid   = tid >> 5;
    const int warpM = wid >> 2;
    const int warpN = wid & 3;
    const int m0 = blockIdx.y * 128;
    const int n0 = blockIdx.x * 128;

    const int NC = K >> 5;

    float acc[4][4][4];
#pragma unroll
    for (int mt = 0; mt < 4; mt++)
#pragma unroll
        for (int nt = 0; nt < 4; nt++)
#pragma unroll
            for (int e = 0; e < 4; e++) acc[mt][nt][e] = 0.f;

    auto load_chunk = [&](int c, int stage) {
        const int k0 = c << 5;
        const uint32_t uA = sbase + stage * STG;
        const uint32_t uB = uA + 16384;
#pragma unroll
        for (int it = 0; it < 4; it++) {
            const int idx = tid + it * 256;
            const int r  = idx >> 3;
            const int cc = idx & 7;
            const uint32_t o = swz((uint32_t)(r * 128 + cc * 16));
            const int kk = k0 + (cc & 3) * 8;
            const __nv_bfloat16* As = (cc < 4) ? Ahi : Alo;
            const __nv_bfloat16* Bs = (cc < 4) ? Bhi : Blo;
            CP_ASYNC16(uA + o, As + (size_t)(m0 + r) * K + kk);
            CP_ASYNC16(uB + o, Bs + (size_t)(n0 + r) * K + kk);
        }
    };

    auto compute_chunk = [&](int stage) {
        const uint32_t uA = sbase + stage * STG;
        const uint32_t uB = uA + 16384;
#pragma unroll
        for (int ks = 0; ks < 2; ks++) {
            const int kb = ks * 32;
            uint32_t a[4][4];
#pragma unroll
            for (int mt = 0; mt < 4; mt++) {
                const int r = warpM * 64 + mt * 16 + (lane & 15);
                const uint32_t o = swz((uint32_t)(r * 128 + kb + ((lane >> 4) << 4)));
                LDMX4(a[mt][0], a[mt][1], a[mt][2], a[mt][3], uA + o);
            }
            uint32_t bH[2][4], bL[2][4];
#pragma unroll
            for (int g = 0; g < 2; g++) {
                const int r = warpN * 32 + g * 16 + (lane & 7) + ((lane >> 4) << 3);
                const uint32_t col = kb + (((lane >> 3) & 1) << 4);
                const uint32_t oH = swz((uint32_t)(r * 128 + col));
                const uint32_t oL = swz((uint32_t)(r * 128 + 64 + col));
                LDMX4(bH[g][0], bH[g][1], bH[g][2], bH[g][3], uB + oH);
                LDMX4(bL[g][0], bL[g][1], bL[g][2], bL[g][3], uB + oL);
            }
#pragma unroll
            for (int mt = 0; mt < 4; mt++)
#pragma unroll
                for (int nt = 0; nt < 4; nt++) {
                    const int gq = nt >> 1, t2 = nt & 1;
                    MMA16816(acc[mt][nt][0], acc[mt][nt][1],
                             acc[mt][nt][2], acc[mt][nt][3],
                             a[mt][0], a[mt][1], a[mt][2], a[mt][3],
                             bH[gq][t2 * 2], bH[gq][t2 * 2 + 1]);
                    MMA16816(acc[mt][nt][0], acc[mt][nt][1],
                             acc[mt][nt][2], acc[mt][nt][3],
                             a[mt][0], a[mt][1], a[mt][2], a[mt][3],
                             bL[gq][t2 * 2], bL[gq][t2 * 2 + 1]);
                }
#pragma unroll
            for (int mt = 0; mt < 4; mt++) {
                const int r = warpM * 64 + mt * 16 + (lane & 15);
                const uint32_t o = swz((uint32_t)(r * 128 + 64 + kb + ((lane >> 4) << 4)));
                LDMX4(a[mt][0], a[mt][1], a[mt][2], a[mt][3], uA + o);
            }
#pragma unroll
            for (int mt = 0; mt < 4; mt++)
#pragma unroll
                for (int nt = 0; nt < 4; nt++) {
                    const int gq = nt >> 1, t2 = nt & 1;
                    MMA16816(acc[mt][nt][0], acc[mt][nt][1],
                             acc[mt][nt][2], acc[mt][nt][3],
                             a[mt][0], a[mt][1], a[mt][2], a[mt][3],
                             bH[gq][t2 * 2], bH[gq][t2 * 2 + 1]);
                }
        }
    };

    load_chunk(0, 0);
    CP_COMMIT();

    for (int i = 0; i < NC; i++) {
        const int b = i & 1;
        if (i + 1 < NC) {
            load_chunk(i + 1, b ^ 1);
            CP_COMMIT();
            CP_WAIT1();
        } else {
            CP_WAIT0();
        }
        __syncthreads();
        compute_chunk(b);
        __syncthreads();
    }

    float* Cout = C;
    int nbase = n0;
    if (C2 && n0 >= nsplit) { Cout = C2; nbase = n0 - nsplit; }

    const int g  = lane >> 2;
    const int tg = lane & 3;
#pragma unroll
    for (int mt = 0; mt < 4; mt++) {
        const int row = m0 + warpM * 64 + mt * 16 + g;
#pragma unroll
        for (int nt = 0; nt < 4; nt++) {
            const int col = nbase + warpN * 32 + nt * 8 + tg * 2;
            const size_t i0 = (size_t)row * ldc + col;
            const size_t i1 = (size_t)(row + 8) * ldc + col;
            float2 v0 = make_float2(acc[mt][nt][0], acc[mt][nt][1]);
            float2 v1 = make_float2(acc[mt][nt][2], acc[mt][nt][3]);
            if (resid) {
                float2 r0 = *(const float2*)(resid + i0);
                float2 r1 = *(const float2*)(resid + i1);
                v0.x += r0.x; v0.y += r0.y;
                v1.x += r1.x; v1.y += r1.y;
            }
            *(float2*)(Cout + i0) = v0;
            *(float2*)(Cout + i1) = v1;
            if (Chi) {
                uint32_t h0, l0, h1, l1;
                split2(v0.x, v0.y, h0, l0);
                split2(v1.x, v1.y, h1, l1);
                *(uint32_t*)(Chi + i0) = h0;
                *(uint32_t*)(Clo + i0) = l0;
                *(uint32_t*)(Chi + i1) = h1;
                *(uint32_t*)(Clo + i1) = l1;
            }
        }
    }
}

// ---------------------------------------------------------------------------
// Vectorized elementwise kernels
// ---------------------------------------------------------------------------
// fp32 -> bf16 hi/lo, 4 elem/thread (float4 load, uint2 stores)
__global__ void split_kernel(const float* __restrict__ src,
                             __nv_bfloat16* __restrict__ hi,
                             __nv_bfloat16* __restrict__ lo, size_t n4)
{
    const size_t stride = (size_t)gridDim.x * blockDim.x;
    for (size_t i = (size_t)blockIdx.x * blockDim.x + threadIdx.x; i < n4; i += stride) {
        float4 v = ((const float4*)src)[i];
        uint2 h, l;
        split2(v.x, v.y, h.x, l.x);
        split2(v.z, v.w, h.y, l.y);
        ((uint2*)hi)[i] = h;
        ((uint2*)lo)[i] = l;
    }
}

// g = silu(f1) * f3 -> bf16 hi/lo, 4 elem/thread
__global__ void silu_split_kernel(const float* __restrict__ f1,
                                  const float* __restrict__ f3,
                                  __nv_bfloat16* __restrict__ hi,
                                  __nv_bfloat16* __restrict__ lo, size_t n4)
{
    const size_t stride = (size_t)gridDim.x * blockDim.x;
    for (size_t i = (size_t)blockIdx.x * blockDim.x + threadIdx.x; i < n4; i += stride) {
        float4 a = ((const float4*)f1)[i];
        float4 b = ((const float4*)f3)[i];
        float g0 = a.x / (1.0f + __expf(-a.x)) * b.x;
        float g1 = a.y / (1.0f + __expf(-a.y)) * b.y;
        float g2 = a.z / (1.0f + __expf(-a.z)) * b.z;
        float g3 = a.w / (1.0f + __expf(-a.w)) * b.w;
        uint2 h, l;
        split2(g0, g1, h.x, l.x);
        split2(g2, g3, h.y, l.y);
        ((uint2*)hi)[i] = h;
        ((uint2*)lo)[i] = l;
    }
}

// W [K,N] fp32 -> W^T [N,K] bf16 hi/lo. 64k x 32n tile, u32 stores.
// grid=(N/32, K/64), block=(32,8).  Smem reads are SCALAR (row stride 65
// floats = 260 B is not 8B-aligned; a float2 read here traps).
__global__ void split_transpose_kernel(const float* __restrict__ W,
                                       __nv_bfloat16* __restrict__ hi,
                                       __nv_bfloat16* __restrict__ lo,
                                       int K, int N)
{
    __shared__ float t[32][65];   // [n][k]
    const int nb = blockIdx.x * 32, kb = blockIdx.y * 64;
    const int tx = threadIdx.x, ty = threadIdx.y;
#pragma unroll
    for (int j = 0; j < 8; j++)
        t[tx][ty + 8 * j] = W[(size_t)(kb + ty + 8 * j) * N + nb + tx];
    __syncthreads();
#pragma unroll
    for (int j = 0; j < 4; j++) {
        const int n = nb + ty + 8 * j;
        const float vx = t[ty + 8 * j][2 * tx];
        const float vy = t[ty + 8 * j][2 * tx + 1];
        uint32_t h, l;
        split2(vx, vy, h, l);
        *(uint32_t*)(hi + (size_t)n * K + kb + 2 * tx) = h;
        *(uint32_t*)(lo + (size_t)n * K + kb + 2 * tx) = l;
    }
}

// fused RoPE + hi/lo split (float2 load, u32 stores)
__global__ void rope_split_kernel(const float* __restrict__ src, int ld, int coloff,
                                  const float* __restrict__ fcos,
                                  const float* __restrict__ fsin,
                                  int nheads,
                                  __nv_bfloat16* __restrict__ hi,
                                  __nv_bfloat16* __restrict__ lo,
                                  int npairs)
{
    int gid = blockIdx.x * blockDim.x + threadIdx.x;
    if (gid >= npairs) return;
    const int i    = gid & 63;
    const int rest = gid >> 6;
    const int hh   = rest % nheads;
    const int tok  = rest / nheads;
    const int s    = tok & (SEQL - 1);
    const float c  = fcos[s * 64 + i];
    const float sn = fsin[s * 64 + i];
    const float2 ab = *(const float2*)(src + (size_t)tok * ld + coloff + hh * HEADD + 2 * i);
    const float r0 = ab.x * c - ab.y * sn;
    const float r1 = ab.x * sn + ab.y * c;
    const size_t ob = ((size_t)tok * nheads + hh) * HEADD + 2 * i;
    uint32_t h2, l2;
    split2(r0, r1, h2, l2);
    *(uint32_t*)(hi + ob) = h2;
    *(uint32_t*)(lo + ob) = l2;
}

// v slice of qkv -> vt [(b*NKV+kv)*HEADD + d][s] hi/lo
__global__ void vt_split_kernel(const float* __restrict__ qkv,
                                __nv_bfloat16* __restrict__ hi,
                                __nv_bfloat16* __restrict__ lo)
{
    __shared__ float t[32][33];
    const int z = blockIdx.z, b = z >> 3, kvh = z & 7;
    const int sb = blockIdx.x * 32, db = blockIdx.y * 32;
    const int tx = threadIdx.x, ty = threadIdx.y;
#pragma unroll
    for (int j = 0; j < 4; j++)
        t[ty + j * 8][tx] =
            qkv[(size_t)(b * SEQL + sb + ty + j * 8) * QKVN + VOFF + kvh * HEADD + db + tx];
    __syncthreads();
#pragma unroll
    for (int j = 0; j < 4; j++) {
        const int d = db + ty + j * 8, s = sb + tx;
        const float val = t[tx][ty + j * 8];
        __nv_bfloat16 h = __float2bfloat16(val);
        const size_t o = ((size_t)(b * NKV + kvh) * HEADD + d) * SEQL + s;
        hi[o] = h;
        lo[o] = __float2bfloat16(val - __bfloat162float(h));
    }
}

// ---------------------------------------------------------------------------
// HMMA flash attention, causal, 3-pass hi/lo (unchanged)
// ---------------------------------------------------------------------------
#define SQ_HI 0
#define SQ_LO 32768
#define SKV0  65536
#define KVSTG 65536
#define FLASH_SMEM (SKV0 + 2 * KVSTG)   /* 196608 */

__global__ void __launch_bounds__(256) flash_mma_kernel(
    const __nv_bfloat16* __restrict__ qhi, const __nv_bfloat16* __restrict__ qlo,
    const __nv_bfloat16* __restrict__ khi, const __nv_bfloat16* __restrict__ klo,
    const __nv_bfloat16* __restrict__ vthi, const __nv_bfloat16* __restrict__ vtlo,
    __nv_bfloat16* __restrict__ ohi, __nv_bfloat16* __restrict__ olo)
{
    extern __shared__ char smc[];
    const uint32_t sb = smem_u32(smc);
    const int z = blockIdx.y, b = z >> 5, h = z & 31, kv = h >> 2;
    const int qt = blockIdx.x, q0 = qt * 128;
    const int tid = threadIdx.x, lane = tid & 31, w = tid >> 5;
    const int g = lane >> 2, tg = lane & 3;

    {
        const __nv_bfloat16* qh = qhi + (size_t)(b * SEQL + q0) * QD + h * HEADD;
        const __nv_bfloat16* ql = qlo + (size_t)(b * SEQL + q0) * QD + h * HEADD;
#pragma unroll
        for (int it = 0; it < 8; it++) {
            const int idx = tid + it * 256;
            const int sub = idx >> 10, rem = idx & 1023;
            const int r = rem >> 3, cc = rem & 7;
            const uint32_t o = swz((uint32_t)(r * 128 + cc * 16));
            const size_t src = (size_t)r * QD + sub * 64 + cc * 8;
            CP_ASYNC16(sb + SQ_HI + sub * 16384 + o, qh + src);
            CP_ASYNC16(sb + SQ_LO + sub * 16384 + o, ql + src);
        }
        CP_COMMIT();
    }

    const int nkt = 2 * qt + 2;
    auto load_kv = [&](int kt) {
        const uint32_t base = sb + SKV0 + (kt & 1) * KVSTG;
        const int s0 = kt * 64;
        const __nv_bfloat16* kh = khi + (size_t)(b * SEQL + s0) * KVD + kv * HEADD;
        const __nv_bfloat16* kl = klo + (size_t)(b * SEQL + s0) * KVD + kv * HEADD;
#pragma unroll
        for (int it = 0; it < 4; it++) {
            const int idx = tid + it * 256;
            const int sub = idx >> 9, rem = idx & 511;
            const int r = rem >> 3, cc = rem & 7;
            const uint32_t o = swz((uint32_t)(r * 128 + cc * 16));
            const size_t src = (size_t)r * KVD + sub * 64 + cc * 8;
            CP_ASYNC16(base + sub * 8192 + o, kh + src);
            CP_ASYNC16(base + 16384 + sub * 8192 + o, kl + src);
        }
        const __nv_bfloat16* vh = vthi + (size_t)(b * NKV + kv) * HEADD * SEQL + s0;
        const __nv_bfloat16* vl = vtlo + (size_t)(b * NKV + kv) * HEADD * SEQL + s0;
#pragma unroll
        for (int it = 0; it < 4; it++) {
            const int idx = tid + it * 256;
            const int r = idx >> 3, cc = idx & 7;
            const uint32_t o = swz((uint32_t)(r * 128 + cc * 16));
            const size_t src = (size_t)r * SEQL + cc * 8;
            CP_ASYNC16(base + 32768 + o, vh + src);
            CP_ASYNC16(base + 49152 + o, vl + src);
        }
        CP_COMMIT();
    };
    load_kv(0);
    if (nkt > 1) load_kv(1);

    float m0 = -1e30f, m1 = -1e30f, l0 = 0.f, l1 = 0.f;
    float O[16][4];
#pragma unroll
    for (int nt = 0; nt < 16; nt++)
#pragma unroll
        for (int e = 0; e < 4; e++) O[nt][e] = 0.f;

    const float SC = 0.08838834764831843f;

    for (int kt = 0; kt < nkt; kt++) {
        if (kt + 1 < nkt) CP_WAIT1(); else CP_WAIT0();
        __syncthreads();
        const uint32_t base = sb + SKV0 + (kt & 1) * KVSTG;

        float S[8][4];
#pragma unroll
        for (int nt = 0; nt < 8; nt++)
#pragma unroll
            for (int e = 0; e < 4; e++) S[nt][e] = 0.f;

#pragma unroll
        for (int ks = 0; ks < 8; ks++) {
            const int sub = ks >> 2, kb = (ks & 3) * 32;
            const uint32_t oA =
                swz((uint32_t)((w * 16 + (lane & 15)) * 128 + kb + ((lane >> 4) << 4)));
            uint32_t aH[4], aL[4];
            LDMX4(aH[0], aH[1], aH[2], aH[3], sb + SQ_HI + sub * 16384 + oA);
            LDMX4(aL[0], aL[1], aL[2], aL[3], sb + SQ_LO + sub * 16384 + oA);
#pragma unroll
            for (int nb = 0; nb < 4; nb++) {
                const uint32_t oB = swz((uint32_t)(
                    (nb * 16 + (lane & 7) + ((lane >> 4) << 3)) * 128 +
                    kb + (((lane >> 3) & 1) << 4)));
                uint32_t bH[4], bL[4];
                LDMX4(bH[0], bH[1], bH[2], bH[3], base + sub * 8192 + oB);
                LDMX4(bL[0], bL[1], bL[2], bL[3], base + 16384 + sub * 8192 + oB);
#pragma unroll
                for (int t2 = 0; t2 < 2; t2++) {
                    const int nt = nb * 2 + t2;
                    MMA16816(S[nt][0], S[nt][1], S[nt][2], S[nt][3],
                             aH[0], aH[1], aH[2], aH[3], bH[t2 * 2], bH[t2 * 2 + 1]);
                    MMA16816(S[nt][0], S[nt][1], S[nt][2], S[nt][3],
                             aH[0], aH[1], aH[2], aH[3], bL[t2 * 2], bL[t2 * 2 + 1]);
                    MMA16816(S[nt][0], S[nt][1], S[nt][2], S[nt][3],
                             aL[0], aL[1], aL[2], aL[3], bH[t2 * 2], bH[t2 * 2 + 1]);
                }
            }
        }

        const int s0 = kt * 64;
        const int row0 = q0 + w * 16 + g;
#pragma unroll
        for (int nt = 0; nt < 8; nt++)
#pragma unroll
            for (int e = 0; e < 2; e++) {
                const int col = s0 + nt * 8 + tg * 2 + e;
                float v0 = S[nt][e] * SC;
                float v1 = S[nt][2 + e] * SC;
                if (col > row0)     v0 = -1e30f;
                if (col > row0 + 8) v1 = -1e30f;
                S[nt][e] = v0;
                S[nt][2 + e] = v1;
            }
        float tm0 = -1e30f, tm1 = -1e30f;
#pragma unroll
        for (int nt = 0; nt < 8; nt++) {
            tm0 = fmaxf(tm0, fmaxf(S[nt][0], S[nt][1]));
            tm1 = fmaxf(tm1, fmaxf(S[nt][2], S[nt][3]));
        }
        tm0 = fmaxf(tm0, __shfl_xor_sync(0xffffffffu, tm0, 1));
        tm0 = fmaxf(tm0, __shfl_xor_sync(0xffffffffu, tm0, 2));
        tm1 = fmaxf(tm1, __shfl_xor_sync(0xffffffffu, tm1, 1));
        tm1 = fmaxf(tm1, __shfl_xor_sync(0xffffffffu, tm1, 2));
        const float mn0 = fmaxf(m0, tm0), mn1 = fmaxf(m1, tm1);
        const float sc0 = __expf(m0 - mn0), sc1 = __expf(m1 - mn1);
        m0 = mn0; m1 = mn1;
        float ts0 = 0.f, ts1 = 0.f;
#pragma unroll
        for (int nt = 0; nt < 8; nt++) {
            S[nt][0] = __expf(S[nt][0] - mn0);
            S[nt][1] = __expf(S[nt][1] - mn0);
            S[nt][2] = __expf(S[nt][2] - mn1);
            S[nt][3] = __expf(S[nt][3] - mn1);
            ts0 += S[nt][0] + S[nt][1];
            ts1 += S[nt][2] + S[nt][3];
        }
        ts0 += __shfl_xor_sync(0xffffffffu, ts0, 1);
        ts0 += __shfl_xor_sync(0xffffffffu, ts0, 2);
        ts1 += __shfl_xor_sync(0xffffffffu, ts1, 1);
        ts1 += __shfl_xor_sync(0xffffffffu, ts1, 2);
        l0 = l0 * sc0 + ts0;
        l1 = l1 * sc1 + ts1;
#pragma unroll
        for (int nt = 0; nt < 16; nt++) {
            O[nt][0] *= sc0; O[nt][1] *= sc0;
            O[nt][2] *= sc1; O[nt][3] *= sc1;
        }

#pragma unroll
        for (int ks = 0; ks < 4; ks++) {
            uint32_t pH[4], pL[4];
#pragma unroll
            for (int half = 0; half < 2; half++) {
                const int st = 2 * ks + half;
                split2(S[st][0], S[st][1], pH[half * 2 + 0], pL[half * 2 + 0]);
                split2(S[st][2], S[st][3], pH[half * 2 + 1], pL[half * 2 + 1]);
            }
#pragma unroll
            for (int nb = 0; nb < 8; nb++) {
                const uint32_t oB = swz((uint32_t)(
                    (nb * 16 + (lane & 7) + ((lane >> 4) << 3)) * 128 +
                    ks * 32 + (((lane >> 3) & 1) << 4)));
                uint32_t vH[4], vL[4];
                LDMX4(vH[0], vH[1], vH[2], vH[3], base + 32768 + oB);
                LDMX4(vL[0], vL[1], vL[2], vL[3], base + 49152 + oB);
#pragma unroll
                for (int t2 = 0; t2 < 2; t2++) {
                    const int nt = nb * 2 + t2;
                    MMA16816(O[nt][0], O[nt][1], O[nt][2], O[nt][3],
                             pH[0], pH[1], pH[2], pH[3], vH[t2 * 2], vH[t2 * 2 + 1]);
                    MMA16816(O[nt][0], O[nt][1], O[nt][2], O[nt][3],
                             pL[0], pL[1], pL[2], pL[3], vH[t2 * 2], vH[t2 * 2 + 1]);
                    MMA16816(O[nt][0], O[nt][1], O[nt][2], O[nt][3],
                             pH[0], pH[1], pH[2], pH[3], vL[t2 * 2], vL[t2 * 2 + 1]);
                }
            }
        }
        __syncthreads();
        if (kt + 2 < nkt) load_kv(kt + 2);
    }

    const float il0 = 1.0f / l0, il1 = 1.0f / l1;
    __nv_bfloat16* OH = ohi + (size_t)(b * SEQL) * QD + h * HEADD;
    __nv_bfloat16* OL = olo + (size_t)(b * SEQL) * QD + h * HEADD;
#pragma unroll
    for (int nt = 0; nt < 16; nt++) {
        const int col = nt * 8 + tg * 2;
        const size_t i0 = (size_t)(q0 + w * 16 + g) * QD + col;
        const size_t i1 = (size_t)(q0 + w * 16 + g + 8) * QD + col;
        uint32_t h0, lo0, h1, lo1;
        split2(O[nt][0] * il0, O[nt][1] * il0, h0, lo0);
        split2(O[nt][2] * il1, O[nt][3] * il1, h1, lo1);
        *(uint32_t*)(OH + i0) = h0;
        *(uint32_t*)(OL + i0) = lo0;
        *(uint32_t*)(OH + i1) = h1;
        *(uint32_t*)(OL + i1) = lo1;
    }
}

// ---------------------------------------------------------------------------
// kernel_launch
// ---------------------------------------------------------------------------
extern "C" void kernel_launch(void* const* d_in, const int* in_sizes, int n_in,
                              void* d_out, int out_size)
{
    const float* x    = (const float*)d_in[0];
    /* d_in[1] = mask (unused; causal handled analytically) */
    const float* fcos = (const float*)d_in[2];
    const float* fsin = (const float*)d_in[3];
    const float* wq   = (const float*)d_in[4];
    const float* wk   = (const float*)d_in[5];
    const float* wv   = (const float*)d_in[6];
    const float* wo   = (const float*)d_in[7];
    const float* w1   = (const float*)d_in[8];
    const float* w2   = (const float*)d_in[9];
    const float* w3   = (const float*)d_in[10];
    float* out = (float*)d_out;

    float *h, *f1, *f3;
    __nv_bfloat16 *ahi, *alo, *whi, *wlo;
    __nv_bfloat16 *qhi, *qlo, *khi, *klo, *vthi, *vtlo;
    cudaGetSymbolAddress((void**)&h,    g_h);
    cudaGetSymbolAddress((void**)&f1,   g_f1);
    cudaGetSymbolAddress((void**)&f3,   g_f3);
    cudaGetSymbolAddress((void**)&ahi,  g_ahi);
    cudaGetSymbolAddress((void**)&alo,  g_alo);
    cudaGetSymbolAddress((void**)&whi,  g_whi);
    cudaGetSymbolAddress((void**)&wlo,  g_wlo);
    cudaGetSymbolAddress((void**)&qhi,  g_qhi);
    cudaGetSymbolAddress((void**)&qlo,  g_qlo);
    cudaGetSymbolAddress((void**)&khi,  g_khi);
    cudaGetSymbolAddress((void**)&klo,  g_klo);
    cudaGetSymbolAddress((void**)&vthi, g_vthi);
    cudaGetSymbolAddress((void**)&vtlo, g_vtlo);

    float* qkv = f1;   // qkv fp32 [TOK, 6144] reuses g_f1

    static int attr_done = 0;
    if (!attr_done) {
        cudaFuncSetAttribute(mma_gemm,
            cudaFuncAttributeMaxDynamicSharedMemorySize, GEMM_SMEM);
        cudaFuncSetAttribute(flash_mma_kernel,
            cudaFuncAttributeMaxDynamicSharedMemorySize, FLASH_SMEM);
        attr_done = 1;
    }

    const dim3 tb(32, 8);

    // x -> bf16 split (vectorized, 4 elem/thread)
    split_kernel<<<2048, 256>>>(x, ahi, alo, (size_t)TOK * DIM / 4);

    // pack wq^T | wk^T | wv^T
    split_transpose_kernel<<<dim3(QD / 32, DIM / 64), tb>>>(wq, whi, wlo, DIM, QD);
    split_transpose_kernel<<<dim3(KVD / 32, DIM / 64), tb>>>(
        wk, whi + (size_t)QD * DIM, wlo + (size_t)QD * DIM, DIM, KVD);
    split_transpose_kernel<<<dim3(KVD / 32, DIM / 64), tb>>>(
        wv, whi + (size_t)VOFF * DIM, wlo + (size_t)VOFF * DIM, DIM, KVD);

    // merged QKV projection: [TOK, 6144]
    mma_gemm<<<dim3(QKVN / 128, TOK / 128), 256, GEMM_SMEM>>>(
        ahi, alo, whi, wlo, nullptr, qkv, nullptr, 0, nullptr, nullptr, DIM, QKVN);

    // fused RoPE + split (q, k); V transpose+split
    rope_split_kernel<<<(TOK * NH * 64 + 255) / 256, 256>>>(
        qkv, QKVN, 0, fcos, fsin, NH, qhi, qlo, TOK * NH * 64);
    rope_split_kernel<<<(TOK * NKV * 64 + 255) / 256, 256>>>(
        qkv, QKVN, QD, fcos, fsin, NKV, khi, klo, TOK * NKV * 64);
    vt_split_kernel<<<dim3(SEQL / 32, HEADD / 32, BATCH * NKV), tb>>>(qkv, vthi, vtlo);

    // HMMA flash attention -> attn out as bf16 hi/lo (into ahi/alo)
    flash_mma_kernel<<<dim3(SEQL / 128, BATCH * NH), 256, FLASH_SMEM>>>(
        qhi, qlo, khi, klo, vthi, vtlo, ahi, alo);

    // h = x + attn @ wo ; epilogue also emits h hi/lo into qhi/qlo
    split_transpose_kernel<<<dim3(DIM / 32, QD / 64), tb>>>(wo, whi, wlo, QD, DIM);
    mma_gemm<<<dim3(DIM / 128, TOK / 128), 256, GEMM_SMEM>>>(
        ahi, alo, whi, wlo, x, h, nullptr, 0, qhi, qlo, QD, DIM);

    // merged FFN up-projections: pack w1^T | w3^T
    split_transpose_kernel<<<dim3(HIDDEN / 32, DIM / 64), tb>>>(w1, whi, wlo, DIM, HIDDEN);
    split_transpose_kernel<<<dim3(HIDDEN / 32, DIM / 64), tb>>>(
        w3, whi + (size_t)HIDDEN * DIM, wlo + (size_t)HIDDEN * DIM, DIM, HIDDEN);
    mma_gemm<<<dim3((2 * HIDDEN) / 128, TOK / 128), 256, GEMM_SMEM>>>(
        qhi, qlo, whi, wlo, nullptr, f1, f3, HIDDEN, nullptr, nullptr, DIM, HIDDEN);

    // gated = silu(f1) * f3 -> bf16 hi/lo directly (vectorized)
    silu_split_kernel<<<4096, 256>>>(f1, f3, ahi, alo, (size_t)TOK * HIDDEN / 4);

    // out = h + gated @ w2
    split_transpose_kernel<<<dim3(DIM / 32, HIDDEN / 64), tb>>>(w2, whi, wlo, HIDDEN, DIM);
    mma_gemm<<<dim3(DIM / 128, TOK / 128), 256, GEMM_SMEM>>>(
        ahi, alo, whi, wlo, h, out, nullptr, 0, nullptr, nullptr, HIDDEN, DIM);
}

// round 14
// speedup vs baseline: 1.0795x; 1.0028x over previous
#include <cuda_runtime.h>
#include <cuda_bf16.h>
#include <math.h>
#include <stddef.h>
#include <stdint.h>

// ---------------------------------------------------------------------------
// Problem constants
// ---------------------------------------------------------------------------
#define BATCH   2
#define SEQL    2048
#define DIM     4096
#define NH      32
#define NKV     8
#define HEADD   128
#define HIDDEN  11008
#define TOK     (BATCH * SEQL)        /* 4096 */
#define QD      (NH  * HEADD)         /* 4096 */
#define KVD     (NKV * HEADD)         /* 1024 */
#define QKVN    (QD + 2 * KVD)        /* 6144 */
#define VOFF    (QD + KVD)            /* 5120 */
#define MAXEL   ((size_t)TOK * HIDDEN)
#define WMAX    ((size_t)(2 * HIDDEN) * DIM)   /* packed w1|w3 */

// ---------------------------------------------------------------------------
// Scratch (static device globals; allocation-free per harness rules)
// ---------------------------------------------------------------------------
__device__ float g_h [(size_t)TOK * DIM];
__device__ float g_f1[MAXEL];                 // qkv fp32 (reused), then f1
__device__ float g_f3[MAXEL];
__device__ __nv_bfloat16 g_ahi[MAXEL];
__device__ __nv_bfloat16 g_alo[MAXEL];
__device__ __nv_bfloat16 g_whi[WMAX];
__device__ __nv_bfloat16 g_wlo[WMAX];
__device__ __nv_bfloat16 g_qhi[(size_t)TOK * QD];
__device__ __nv_bfloat16 g_qlo[(size_t)TOK * QD];
__device__ __nv_bfloat16 g_khi[(size_t)TOK * KVD];
__device__ __nv_bfloat16 g_klo[(size_t)TOK * KVD];
__device__ __nv_bfloat16 g_vthi[(size_t)TOK * KVD]; // [B][NKV][HEADD][SEQL]
__device__ __nv_bfloat16 g_vtlo[(size_t)TOK * KVD];

// ---------------------------------------------------------------------------
// PTX helpers (sm_100-safe: cp.async / ldmatrix / mma.sync only)
// ---------------------------------------------------------------------------
__device__ __forceinline__ uint32_t smem_u32(const void* p) {
    uint32_t a;
    asm("{ .reg .u64 t; cvta.to.shared.u64 t, %1; cvt.u32.u64 %0, t; }"
        : "=r"(a) : "l"(p));
    return a;
}
#define CP_ASYNC16(dst, src) \
    asm volatile("cp.async.cg.shared.global [%0], [%1], 16;" \
                 :: "r"(dst), "l"(src) : "memory")
#define CP_COMMIT() asm volatile("cp.async.commit_group;" ::: "memory")
#define CP_WAIT0()  asm volatile("cp.async.wait_group 0;" ::: "memory")
#define CP_WAIT1()  asm volatile("cp.async.wait_group 1;" ::: "memory")

#define LDMX4(r0, r1, r2, r3, addr) \
    asm volatile("ldmatrix.sync.aligned.m8n8.x4.shared.b16 {%0,%1,%2,%3}, [%4];" \
                 : "=r"(r0), "=r"(r1), "=r"(r2), "=r"(r3) : "r"(addr))

#define MMA16816(c0, c1, c2, c3, a0, a1, a2, a3, b0, b1) \
    asm volatile("mma.sync.aligned.m16n8k16.row.col.f32.bf16.bf16.f32 " \
                 "{%0,%1,%2,%3}, {%4,%5,%6,%7}, {%8,%9}, {%0,%1,%2,%3};" \
                 : "+f"(c0), "+f"(c1), "+f"(c2), "+f"(c3) \
                 : "r"(a0), "r"(a1), "r"(a2), "r"(a3), "r"(b0), "r"(b1))

__device__ __forceinline__ uint32_t swz(uint32_t o) { return o ^ ((o >> 3) & 0x70); }

__device__ __forceinline__ uint32_t pack_bf16x2(float x, float y) {
    __nv_bfloat162 t = __floats2bfloat162_rn(x, y);
    return *(uint32_t*)&t;
}
__device__ __forceinline__ void split2(float x, float y, uint32_t& hi, uint32_t& lo) {
    __nv_bfloat16 hx = __float2bfloat16(x), hy = __float2bfloat16(y);
    __nv_bfloat162 hh; hh.x = hx; hh.y = hy;
    hi = *(uint32_t*)&hh;
    lo = pack_bf16x2(x - __bfloat162float(hx), y - __bfloat162float(hy));
}

// ---------------------------------------------------------------------------
// bf16 HMMA GEMM (unchanged proven mainloop + routed epilogue)
// ---------------------------------------------------------------------------
#define STG 32768
#define GEMM_SMEM 65536

__global__ void __launch_bounds__(256, 2) mma_gemm(
    const __nv_bfloat16* __restrict__ Ahi, const __nv_bfloat16* __restrict__ Alo,
    const __nv_bfloat16* __restrict__ Bhi, const __nv_bfloat16* __restrict__ Blo,
    const float* __restrict__ resid, float* __restrict__ C,
    float* __restrict__ C2, int nsplit,
    __nv_bfloat16* __restrict__ Chi, __nv_bfloat16* __restrict__ Clo,
    int K, int ldc)
{
    extern __shared__ char smc[];
    const uint32_t sbase = smem_u32(smc);
    const int tid   = threadIdx.x;
    const int lane  = tid & 31;
    const int wid   = tid >> 5;
    const int warpM = wid >> 2;
    const int warpN = wid & 3;
    const int m0 = blockIdx.y * 128;
    const int n0 = blockIdx.x * 128;

    const int NC = K >> 5;

    float acc[4][4][4];
#pragma unroll
    for (int mt = 0; mt < 4; mt++)
#pragma unroll
        for (int nt = 0; nt < 4; nt++)
#pragma unroll
            for (int e = 0; e < 4; e++) acc[mt][nt][e] = 0.f;

    auto load_chunk = [&](int c, int stage) {
        const int k0 = c << 5;
        const uint32_t uA = sbase + stage * STG;
        const uint32_t uB = uA + 16384;
#pragma unroll
        for (int it = 0; it < 4; it++) {
            const int idx = tid + it * 256;
            const int r  = idx >> 3;
            const int cc = idx & 7;
            const uint32_t o = swz((uint32_t)(r * 128 + cc * 16));
            const int kk = k0 + (cc & 3) * 8;
            const __nv_bfloat16* As = (cc < 4) ? Ahi : Alo;
            const __nv_bfloat16* Bs = (cc < 4) ? Bhi : Blo;
            CP_ASYNC16(uA + o, As + (size_t)(m0 + r) * K + kk);
            CP_ASYNC16(uB + o, Bs + (size_t)(n0 + r) * K + kk);
        }
    };

    auto compute_chunk = [&](int stage) {
        const uint32_t uA = sbase + stage * STG;
        const uint32_t uB = uA + 16384;
#pragma unroll
        for (int ks = 0; ks < 2; ks++) {
            const int kb = ks * 32;
            uint32_t a[4][4];
#pragma unroll
            for (int mt = 0; mt < 4; mt++) {
                const int r = warpM * 64 + mt * 16 + (lane & 15);
                const uint32_t o = swz((uint32_t)(r * 128 + kb + ((lane >> 4) << 4)));
                LDMX4(a[mt][0], a[mt][1], a[mt][2], a[mt][3], uA + o);
            }
            uint32_t bH[2][4], bL[2][4];
#pragma unroll
            for (int g = 0; g < 2; g++) {
                const int r = warpN * 32 + g * 16 + (lane & 7) + ((lane >> 4) << 3);
                const uint32_t col = kb + (((lane >> 3) & 1) << 4);
                const uint32_t oH = swz((uint32_t)(r * 128 + col));
                const uint32_t oL = swz((uint32_t)(r * 128 + 64 + col));
                LDMX4(bH[g][0], bH[g][1], bH[g][2], bH[g][3], uB + oH);
                LDMX4(bL[g][0], bL[g][1], bL[g][2], bL[g][3], uB + oL);
            }
#pragma unroll
            for (int mt = 0; mt < 4; mt++)
#pragma unroll
                for (int nt = 0; nt < 4; nt++) {
                    const int gq = nt >> 1, t2 = nt & 1;
                    MMA16816(acc[mt][nt][0], acc[mt][nt][1],
                             acc[mt][nt][2], acc[mt][nt][3],
                             a[mt][0], a[mt][1], a[mt][2], a[mt][3],
                             bH[gq][t2 * 2], bH[gq][t2 * 2 + 1]);
                    MMA16816(acc[mt][nt][0], acc[mt][nt][1],
                             acc[mt][nt][2], acc[mt][nt][3],
                             a[mt][0], a[mt][1], a[mt][2], a[mt][3],
                             bL[gq][t2 * 2], bL[gq][t2 * 2 + 1]);
                }
#pragma unroll
            for (int mt = 0; mt < 4; mt++) {
                const int r = warpM * 64 + mt * 16 + (lane & 15);
                const uint32_t o = swz((uint32_t)(r * 128 + 64 + kb + ((lane >> 4) << 4)));
                LDMX4(a[mt][0], a[mt][1], a[mt][2], a[mt][3], uA + o);
            }
#pragma unroll
            for (int mt = 0; mt < 4; mt++)
#pragma unroll
                for (int nt = 0; nt < 4; nt++) {
                    const int gq = nt >> 1, t2 = nt & 1;
                    MMA16816(acc[mt][nt][0], acc[mt][nt][1],
                             acc[mt][nt][2], acc[mt][nt][3],
                             a[mt][0], a[mt][1], a[mt][2], a[mt][3],
                             bH[gq][t2 * 2], bH[gq][t2 * 2 + 1]);
                }
        }
    };

    load_chunk(0, 0);
    CP_COMMIT();

    for (int i = 0; i < NC; i++) {
        const int b = i & 1;
        if (i + 1 < NC) {
            load_chunk(i + 1, b ^ 1);
            CP_COMMIT();
            CP_WAIT1();
        } else {
            CP_WAIT0();
        }
        __syncthreads();
        compute_chunk(b);
        __syncthreads();
    }

    float* Cout = C;
    int nbase = n0;
    if (C2 && n0 >= nsplit) { Cout = C2; nbase = n0 - nsplit; }

    const int g  = lane >> 2;
    const int tg = lane & 3;
#pragma unroll
    for (int mt = 0; mt < 4; mt++) {
        const int row = m0 + warpM * 64 + mt * 16 + g;
#pragma unroll
        for (int nt = 0; nt < 4; nt++) {
            const int col = nbase + warpN * 32 + nt * 8 + tg * 2;
            const size_t i0 = (size_t)row * ldc + col;
            const size_t i1 = (size_t)(row + 8) * ldc + col;
            float2 v0 = make_float2(acc[mt][nt][0], acc[mt][nt][1]);
            float2 v1 = make_float2(acc[mt][nt][2], acc[mt][nt][3]);
            if (resid) {
                float2 r0 = *(const float2*)(resid + i0);
                float2 r1 = *(const float2*)(resid + i1);
                v0.x += r0.x; v0.y += r0.y;
                v1.x += r1.x; v1.y += r1.y;
            }
            *(float2*)(Cout + i0) = v0;
            *(float2*)(Cout + i1) = v1;
            if (Chi) {
                uint32_t h0, l0, h1, l1;
                split2(v0.x, v0.y, h0, l0);
                split2(v1.x, v1.y, h1, l1);
                *(uint32_t*)(Chi + i0) = h0;
                *(uint32_t*)(Clo + i0) = l0;
                *(uint32_t*)(Chi + i1) = h1;
                *(uint32_t*)(Clo + i1) = l1;
            }
        }
    }
}

// ---------------------------------------------------------------------------
// Vectorized elementwise kernels
// ---------------------------------------------------------------------------
// fp32 -> bf16 hi/lo, 4 elem/thread (float4 load, uint2 stores)
__global__ void split_kernel(const float* __restrict__ src,
                             __nv_bfloat16* __restrict__ hi,
                             __nv_bfloat16* __restrict__ lo, size_t n4)
{
    const size_t stride = (size_t)gridDim.x * blockDim.x;
    for (size_t i = (size_t)blockIdx.x * blockDim.x + threadIdx.x; i < n4; i += stride) {
        float4 v = ((const float4*)src)[i];
        uint2 h, l;
        split2(v.x, v.y, h.x, l.x);
        split2(v.z, v.w, h.y, l.y);
        ((uint2*)hi)[i] = h;
        ((uint2*)lo)[i] = l;
    }
}

// g = silu(f1) * f3 -> bf16 hi/lo, 4 elem/thread
__global__ void silu_split_kernel(const float* __restrict__ f1,
                                  const float* __restrict__ f3,
                                  __nv_bfloat16* __restrict__ hi,
                                  __nv_bfloat16* __restrict__ lo, size_t n4)
{
    const size_t stride = (size_t)gridDim.x * blockDim.x;
    for (size_t i = (size_t)blockIdx.x * blockDim.x + threadIdx.x; i < n4; i += stride) {
        float4 a = ((const float4*)f1)[i];
        float4 b = ((const float4*)f3)[i];
        float g0 = a.x / (1.0f + __expf(-a.x)) * b.x;
        float g1 = a.y / (1.0f + __expf(-a.y)) * b.y;
        float g2 = a.z / (1.0f + __expf(-a.z)) * b.z;
        float g3 = a.w / (1.0f + __expf(-a.w)) * b.w;
        uint2 h, l;
        split2(g0, g1, h.x, l.x);
        split2(g2, g3, h.y, l.y);
        ((uint2*)hi)[i] = h;
        ((uint2*)lo)[i] = l;
    }
}

// W [K,N] fp32 -> W^T [N,K] bf16 hi/lo. 64k x 32n tile, u32 stores.
// grid=(N/32, K/64), block=(32,8).  Smem reads are SCALAR (row stride 65
// floats = 260 B is not 8B-aligned; a float2 read here traps).
__global__ void split_transpose_kernel(const float* __restrict__ W,
                                       __nv_bfloat16* __restrict__ hi,
                                       __nv_bfloat16* __restrict__ lo,
                                       int K, int N)
{
    __shared__ float t[32][65];   // [n][k]
    const int nb = blockIdx.x * 32, kb = blockIdx.y * 64;
    const int tx = threadIdx.x, ty = threadIdx.y;
#pragma unroll
    for (int j = 0; j < 8; j++)
        t[tx][ty + 8 * j] = W[(size_t)(kb + ty + 8 * j) * N + nb + tx];
    __syncthreads();
#pragma unroll
    for (int j = 0; j < 4; j++) {
        const int n = nb + ty + 8 * j;
        const float vx = t[ty + 8 * j][2 * tx];
        const float vy = t[ty + 8 * j][2 * tx + 1];
        uint32_t h, l;
        split2(vx, vy, h, l);
        *(uint32_t*)(hi + (size_t)n * K + kb + 2 * tx) = h;
        *(uint32_t*)(lo + (size_t)n * K + kb + 2 * tx) = l;
    }
}

// fused RoPE + hi/lo split (float2 load, u32 stores)
__global__ void rope_split_kernel(const float* __restrict__ src, int ld, int coloff,
                                  const float* __restrict__ fcos,
                                  const float* __restrict__ fsin,
                                  int nheads,
                                  __nv_bfloat16* __restrict__ hi,
                                  __nv_bfloat16* __restrict__ lo,
                                  int npairs)
{
    int gid = blockIdx.x * blockDim.x + threadIdx.x;
    if (gid >= npairs) return;
    const int i    = gid & 63;
    const int rest = gid >> 6;
    const int hh   = rest % nheads;
    const int tok  = rest / nheads;
    const int s    = tok & (SEQL - 1);
    const float c  = fcos[s * 64 + i];
    const float sn = fsin[s * 64 + i];
    const float2 ab = *(const float2*)(src + (size_t)tok * ld + coloff + hh * HEADD + 2 * i);
    const float r0 = ab.x * c - ab.y * sn;
    const float r1 = ab.x * sn + ab.y * c;
    const size_t ob = ((size_t)tok * nheads + hh) * HEADD + 2 * i;
    uint32_t h2, l2;
    split2(r0, r1, h2, l2);
    *(uint32_t*)(hi + ob) = h2;
    *(uint32_t*)(lo + ob) = l2;
}

// v slice of qkv -> vt [(b*NKV+kv)*HEADD + d][s] hi/lo
__global__ void vt_split_kernel(const float* __restrict__ qkv,
                                __nv_bfloat16* __restrict__ hi,
                                __nv_bfloat16* __restrict__ lo)
{
    __shared__ float t[32][33];
    const int z = blockIdx.z, b = z >> 3, kvh = z & 7;
    const int sb = blockIdx.x * 32, db = blockIdx.y * 32;
    const int tx = threadIdx.x, ty = threadIdx.y;
#pragma unroll
    for (int j = 0; j < 4; j++)
        t[ty + j * 8][tx] =
            qkv[(size_t)(b * SEQL + sb + ty + j * 8) * QKVN + VOFF + kvh * HEADD + db + tx];
    __syncthreads();
#pragma unroll
    for (int j = 0; j < 4; j++) {
        const int d = db + ty + j * 8, s = sb + tx;
        const float val = t[tx][ty + j * 8];
        __nv_bfloat16 h = __float2bfloat16(val);
        const size_t o = ((size_t)(b * NKV + kvh) * HEADD + d) * SEQL + s;
        hi[o] = h;
        lo[o] = __float2bfloat16(val - __bfloat162float(h));
    }
}

// ---------------------------------------------------------------------------
// HMMA flash attention, causal, 3-pass hi/lo (unchanged)
// ---------------------------------------------------------------------------
#define SQ_HI 0
#define SQ_LO 32768
#define SKV0  65536
#define KVSTG 65536
#define FLASH_SMEM (SKV0 + 2 * KVSTG)   /* 196608 */

__global__ void __launch_bounds__(256) flash_mma_kernel(
    const __nv_bfloat16* __restrict__ qhi, const __nv_bfloat16* __restrict__ qlo,
    const __nv_bfloat16* __restrict__ khi, const __nv_bfloat16* __restrict__ klo,
    const __nv_bfloat16* __restrict__ vthi, const __nv_bfloat16* __restrict__ vtlo,
    __nv_bfloat16* __restrict__ ohi, __nv_bfloat16* __restrict__ olo)
{
    extern __shared__ char smc[];
    const uint32_t sb = smem_u32(smc);
    const int z = blockIdx.y, b = z >> 5, h = z & 31, kv = h >> 2;
    const int qt = blockIdx.x, q0 = qt * 128;
    const int tid = threadIdx.x, lane = tid & 31, w = tid >> 5;
    const int g = lane >> 2, tg = lane & 3;

    {
        const __nv_bfloat16* qh = qhi + (size_t)(b * SEQL + q0) * QD + h * HEADD;
        const __nv_bfloat16* ql = qlo + (size_t)(b * SEQL + q0) * QD + h * HEADD;
#pragma unroll
        for (int it = 0; it < 8; it++) {
            const int idx = tid + it * 256;
            const int sub = idx >> 10, rem = idx & 1023;
            const int r = rem >> 3, cc = rem & 7;
            const uint32_t o = swz((uint32_t)(r * 128 + cc * 16));
            const size_t src = (size_t)r * QD + sub * 64 + cc * 8;
            CP_ASYNC16(sb + SQ_HI + sub * 16384 + o, qh + src);
            CP_ASYNC16(sb + SQ_LO + sub * 16384 + o, ql + src);
        }
        CP_COMMIT();
    }

    const int nkt = 2 * qt + 2;
    auto load_kv = [&](int kt) {
        const uint32_t base = sb + SKV0 + (kt & 1) * KVSTG;
        const int s0 = kt * 64;
        const __nv_bfloat16* kh = khi + (size_t)(b * SEQL + s0) * KVD + kv * HEADD;
        const __nv_bfloat16* kl = klo + (size_t)(b * SEQL + s0) * KVD + kv * HEADD;
#pragma unroll
        for (int it = 0; it < 4; it++) {
            const int idx = tid + it * 256;
            const int sub = idx >> 9, rem = idx & 511;
            const int r = rem >> 3, cc = rem & 7;
            const uint32_t o = swz((uint32_t)(r * 128 + cc * 16));
            const size_t src = (size_t)r * KVD + sub * 64 + cc * 8;
            CP_ASYNC16(base + sub * 8192 + o, kh + src);
            CP_ASYNC16(base + 16384 + sub * 8192 + o, kl + src);
        }
        const __nv_bfloat16* vh = vthi + (size_t)(b * NKV + kv) * HEADD * SEQL + s0;
        const __nv_bfloat16* vl = vtlo + (size_t)(b * NKV + kv) * HEADD * SEQL + s0;
#pragma unroll
        for (int it = 0; it < 4; it++) {
            const int idx = tid + it * 256;
            const int r = idx >> 3, cc = idx & 7;
            const uint32_t o = swz((uint32_t)(r * 128 + cc * 16));
            const size_t src = (size_t)r * SEQL + cc * 8;
            CP_ASYNC16(base + 32768 + o, vh + src);
            CP_ASYNC16(base + 49152 + o, vl + src);
        }
        CP_COMMIT();
    };
    load_kv(0);
    if (nkt > 1) load_kv(1);

    float m0 = -1e30f, m1 = -1e30f, l0 = 0.f, l1 = 0.f;
    float O[16][4];
#pragma unroll
    for (int nt = 0; nt < 16; nt++)
#pragma unroll
        for (int e = 0; e < 4; e++) O[nt][e] = 0.f;

    const float SC = 0.08838834764831843f;

    for (int kt = 0; kt < nkt; kt++) {
        if (kt + 1 < nkt) CP_WAIT1(); else CP_WAIT0();
        __syncthreads();
        const uint32_t base = sb + SKV0 + (kt & 1) * KVSTG;

        float S[8][4];
#pragma unroll
        for (int nt = 0; nt < 8; nt++)
#pragma unroll
            for (int e = 0; e < 4; e++) S[nt][e] = 0.f;

#pragma unroll
        for (int ks = 0; ks < 8; ks++) {
            const int sub = ks >> 2, kb = (ks & 3) * 32;
            const uint32_t oA =
                swz((uint32_t)((w * 16 + (lane & 15)) * 128 + kb + ((lane >> 4) << 4)));
            uint32_t aH[4], aL[4];
            LDMX4(aH[0], aH[1], aH[2], aH[3], sb + SQ_HI + sub * 16384 + oA);
            LDMX4(aL[0], aL[1], aL[2], aL[3], sb + SQ_LO + sub * 16384 + oA);
#pragma unroll
            for (int nb = 0; nb < 4; nb++) {
                const uint32_t oB = swz((uint32_t)(
                    (nb * 16 + (lane & 7) + ((lane >> 4) << 3)) * 128 +
                    kb + (((lane >> 3) & 1) << 4)));
                uint32_t bH[4], bL[4];
                LDMX4(bH[0], bH[1], bH[2], bH[3], base + sub * 8192 + oB);
                LDMX4(bL[0], bL[1], bL[2], bL[3], base + 16384 + sub * 8192 + oB);
#pragma unroll
                for (int t2 = 0; t2 < 2; t2++) {
                    const int nt = nb * 2 + t2;
                    MMA16816(S[nt][0], S[nt][1], S[nt][2], S[nt][3],
                             aH[0], aH[1], aH[2], aH[3], bH[t2 * 2], bH[t2 * 2 + 1]);
                    MMA16816(S[nt][0], S[nt][1], S[nt][2], S[nt][3],
                             aH[0], aH[1], aH[2], aH[3], bL[t2 * 2], bL[t2 * 2 + 1]);
                    MMA16816(S[nt][0], S[nt][1], S[nt][2], S[nt][3],
                             aL[0], aL[1], aL[2], aL[3], bH[t2 * 2], bH[t2 * 2 + 1]);
                }
            }
        }

        const int s0 = kt * 64;
        const int row0 = q0 + w * 16 + g;
#pragma unroll
        for (int nt = 0; nt < 8; nt++)
#pragma unroll
            for (int e = 0; e < 2; e++) {
                const int col = s0 + nt * 8 + tg * 2 + e;
                float v0 = S[nt][e] * SC;
                float v1 = S[nt][2 + e] * SC;
                if (col > row0)     v0 = -1e30f;
                if (col > row0 + 8) v1 = -1e30f;
                S[nt][e] = v0;
                S[nt][2 + e] = v1;
            }
        float tm0 = -1e30f, tm1 = -1e30f;
#pragma unroll
        for (int nt = 0; nt < 8; nt++) {
            tm0 = fmaxf(tm0, fmaxf(S[nt][0], S[nt][1]));
            tm1 = fmaxf(tm1, fmaxf(S[nt][2], S[nt][3]));
        }
        tm0 = fmaxf(tm0, __shfl_xor_sync(0xffffffffu, tm0, 1));
        tm0 = fmaxf(tm0, __shfl_xor_sync(0xffffffffu, tm0, 2));
        tm1 = fmaxf(tm1, __shfl_xor_sync(0xffffffffu, tm1, 1));
        tm1 = fmaxf(tm1, __shfl_xor_sync(0xffffffffu, tm1, 2));
        const float mn0 = fmaxf(m0, tm0), mn1 = fmaxf(m1, tm1);
        const float sc0 = __expf(m0 - mn0), sc1 = __expf(m1 - mn1);
        m0 = mn0; m1 = mn1;
        float ts0 = 0.f, ts1 = 0.f;
#pragma unroll
        for (int nt = 0; nt < 8; nt++) {
            S[nt][0] = __expf(S[nt][0] - mn0);
            S[nt][1] = __expf(S[nt][1] - mn0);
            S[nt][2] = __expf(S[nt][2] - mn1);
            S[nt][3] = __expf(S[nt][3] - mn1);
            ts0 += S[nt][0] + S[nt][1];
            ts1 += S[nt][2] + S[nt][3];
        }
        ts0 += __shfl_xor_sync(0xffffffffu, ts0, 1);
        ts0 += __shfl_xor_sync(0xffffffffu, ts0, 2);
        ts1 += __shfl_xor_sync(0xffffffffu, ts1, 1);
        ts1 += __shfl_xor_sync(0xffffffffu, ts1, 2);
        l0 = l0 * sc0 + ts0;
        l1 = l1 * sc1 + ts1;
#pragma unroll
        for (int nt = 0; nt < 16; nt++) {
            O[nt][0] *= sc0; O[nt][1] *= sc0;
            O[nt][2] *= sc1; O[nt][3] *= sc1;
        }

#pragma unroll
        for (int ks = 0; ks < 4; ks++) {
            uint32_t pH[4], pL[4];
#pragma unroll
            for (int half = 0; half < 2; half++) {
                const int st = 2 * ks + half;
                split2(S[st][0], S[st][1], pH[half * 2 + 0], pL[half * 2 + 0]);
                split2(S[st][2], S[st][3], pH[half * 2 + 1], pL[half * 2 + 1]);
            }
#pragma unroll
            for (int nb = 0; nb < 8; nb++) {
                const uint32_t oB = swz((uint32_t)(
                    (nb * 16 + (lane & 7) + ((lane >> 4) << 3)) * 128 +
                    ks * 32 + (((lane >> 3) & 1) << 4)));
                uint32_t vH[4], vL[4];
                LDMX4(vH[0], vH[1], vH[2], vH[3], base + 32768 + oB);
                LDMX4(vL[0], vL[1], vL[2], vL[3], base + 49152 + oB);
#pragma unroll
                for (int t2 = 0; t2 < 2; t2++) {
                    const int nt = nb * 2 + t2;
                    MMA16816(O[nt][0], O[nt][1], O[nt][2], O[nt][3],
                             pH[0], pH[1], pH[2], pH[3], vH[t2 * 2], vH[t2 * 2 + 1]);
                    MMA16816(O[nt][0], O[nt][1], O[nt][2], O[nt][3],
                             pL[0], pL[1], pL[2], pL[3], vH[t2 * 2], vH[t2 * 2 + 1]);
                    MMA16816(O[nt][0], O[nt][1], O[nt][2], O[nt][3],
                             pH[0], pH[1], pH[2], pH[3], vL[t2 * 2], vL[t2 * 2 + 1]);
                }
            }
        }
        __syncthreads();
        if (kt + 2 < nkt) load_kv(kt + 2);
    }

    const float il0 = 1.0f / l0, il1 = 1.0f / l1;
    __nv_bfloat16* OH = ohi + (size_t)(b * SEQL) * QD + h * HEADD;
    __nv_bfloat16* OL = olo + (size_t)(b * SEQL) * QD + h * HEADD;
#pragma unroll
    for (int nt = 0; nt < 16; nt++) {
        const int col = nt * 8 + tg * 2;
        const size_t i0 = (size_t)(q0 + w * 16 + g) * QD + col;
        const size_t i1 = (size_t)(q0 + w * 16 + g + 8) * QD + col;
        uint32_t h0, lo0, h1, lo1;
        split2(O[nt][0] * il0, O[nt][1] * il0, h0, lo0);
        split2(O[nt][2] * il1, O[nt][3] * il1, h1, lo1);
        *(uint32_t*)(OH + i0) = h0;
        *(uint32_t*)(OL + i0) = lo0;
        *(uint32_t*)(OH + i1) = h1;
        *(uint32_t*)(OL + i1) = lo1;
    }
}

// ---------------------------------------------------------------------------
// kernel_launch
// ---------------------------------------------------------------------------
extern "C" void kernel_launch(void* const* d_in, const int* in_sizes, int n_in,
                              void* d_out, int out_size)
{
    const float* x    = (const float*)d_in[0];
    /* d_in[1] = mask (unused; causal handled analytically) */
    const float* fcos = (const float*)d_in[2];
    const float* fsin = (const float*)d_in[3];
    const float* wq   = (const float*)d_in[4];
    const float* wk   = (const float*)d_in[5];
    const float* wv   = (const float*)d_in[6];
    const float* wo   = (const float*)d_in[7];
    const float* w1   = (const float*)d_in[8];
    const float* w2   = (const float*)d_in[9];
    const float* w3   = (const float*)d_in[10];
    float* out = (float*)d_out;

    float *h, *f1, *f3;
    __nv_bfloat16 *ahi, *alo, *whi, *wlo;
    __nv_bfloat16 *qhi, *qlo, *khi, *klo, *vthi, *vtlo;
    cudaGetSymbolAddress((void**)&h,    g_h);
    cudaGetSymbolAddress((void**)&f1,   g_f1);
    cudaGetSymbolAddress((void**)&f3,   g_f3);
    cudaGetSymbolAddress((void**)&ahi,  g_ahi);
    cudaGetSymbolAddress((void**)&alo,  g_alo);
    cudaGetSymbolAddress((void**)&whi,  g_whi);
    cudaGetSymbolAddress((void**)&wlo,  g_wlo);
    cudaGetSymbolAddress((void**)&qhi,  g_qhi);
    cudaGetSymbolAddress((void**)&qlo,  g_qlo);
    cudaGetSymbolAddress((void**)&khi,  g_khi);
    cudaGetSymbolAddress((void**)&klo,  g_klo);
    cudaGetSymbolAddress((void**)&vthi, g_vthi);
    cudaGetSymbolAddress((void**)&vtlo, g_vtlo);

    float* qkv = f1;   // qkv fp32 [TOK, 6144] reuses g_f1

    static int attr_done = 0;
    if (!attr_done) {
        cudaFuncSetAttribute(mma_gemm,
            cudaFuncAttributeMaxDynamicSharedMemorySize, GEMM_SMEM);
        cudaFuncSetAttribute(flash_mma_kernel,
            cudaFuncAttributeMaxDynamicSharedMemorySize, FLASH_SMEM);
        attr_done = 1;
    }

    const dim3 tb(32, 8);

    // x -> bf16 split (vectorized, 4 elem/thread)
    split_kernel<<<2048, 256>>>(x, ahi, alo, (size_t)TOK * DIM / 4);

    // pack wq^T | wk^T | wv^T
    split_transpose_kernel<<<dim3(QD / 32, DIM / 64), tb>>>(wq, whi, wlo, DIM, QD);
    split_transpose_kernel<<<dim3(KVD / 32, DIM / 64), tb>>>(
        wk, whi + (size_t)QD * DIM, wlo + (size_t)QD * DIM, DIM, KVD);
    split_transpose_kernel<<<dim3(KVD / 32, DIM / 64), tb>>>(
        wv, whi + (size_t)VOFF * DIM, wlo + (size_t)VOFF * DIM, DIM, KVD);

    // merged QKV projection: [TOK, 6144]
    mma_gemm<<<dim3(QKVN / 128, TOK / 128), 256, GEMM_SMEM>>>(
        ahi, alo, whi, wlo, nullptr, qkv, nullptr, 0, nullptr, nullptr, DIM, QKVN);

    // fused RoPE + split (q, k); V transpose+split
    rope_split_kernel<<<(TOK * NH * 64 + 255) / 256, 256>>>(
        qkv, QKVN, 0, fcos, fsin, NH, qhi, qlo, TOK * NH * 64);
    rope_split_kernel<<<(TOK * NKV * 64 + 255) / 256, 256>>>(
        qkv, QKVN, QD, fcos, fsin, NKV, khi, klo, TOK * NKV * 64);
    vt_split_kernel<<<dim3(SEQL / 32, HEADD / 32, BATCH * NKV), tb>>>(qkv, vthi, vtlo);

    // HMMA flash attention -> attn out as bf16 hi/lo (into ahi/alo)
    flash_mma_kernel<<<dim3(SEQL / 128, BATCH * NH), 256, FLASH_SMEM>>>(
        qhi, qlo, khi, klo, vthi, vtlo, ahi, alo);

    // h = x + attn @ wo ; epilogue also emits h hi/lo into qhi/qlo
    split_transpose_kernel<<<dim3(DIM / 32, QD / 64), tb>>>(wo, whi, wlo, QD, DIM);
    mma_gemm<<<dim3(DIM / 128, TOK / 128), 256, GEMM_SMEM>>>(
        ahi, alo, whi, wlo, x, h, nullptr, 0, qhi, qlo, QD, DIM);

    // merged FFN up-projections: pack w1^T | w3^T
    split_transpose_kernel<<<dim3(HIDDEN / 32, DIM / 64), tb>>>(w1, whi, wlo, DIM, HIDDEN);
    split_transpose_kernel<<<dim3(HIDDEN / 32, DIM / 64), tb>>>(
        w3, whi + (size_t)HIDDEN * DIM, wlo + (size_t)HIDDEN * DIM, DIM, HIDDEN);
    mma_gemm<<<dim3((2 * HIDDEN) / 128, TOK / 128), 256, GEMM_SMEM>>>(
        qhi, qlo, whi, wlo, nullptr, f1, f3, HIDDEN, nullptr, nullptr, DIM, HIDDEN);

    // gated = silu(f1) * f3 -> bf16 hi/lo directly (vectorized)
    silu_split_kernel<<<4096, 256>>>(f1, f3, ahi, alo, (size_t)TOK * HIDDEN / 4);

    // out = h + gated @ w2
    split_transpose_kernel<<<dim3(DIM / 32, HIDDEN / 64), tb>>>(w2, whi, wlo, HIDDEN, DIM);
    mma_gemm<<<dim3(DIM / 128, TOK / 128), 256, GEMM_SMEM>>>(
        ahi, alo, whi, wlo, h, out, nullptr, 0, nullptr, nullptr, HIDDEN, DIM);
}

// round 15
// speedup vs baseline: 1.0964x; 1.0156x over previous
#include <cuda_runtime.h>
#include <cuda_bf16.h>
#include <math.h>
#include <stddef.h>
#include <stdint.h>

// ---------------------------------------------------------------------------
// Problem constants
// ---------------------------------------------------------------------------
#define BATCH   2
#define SEQL    2048
#define DIM     4096
#define NH      32
#define NKV     8
#define HEADD   128
#define HIDDEN  11008
#define TOK     (BATCH * SEQL)        /* 4096 */
#define QD      (NH  * HEADD)         /* 4096 */
#define KVD     (NKV * HEADD)         /* 1024 */
#define QKVN    (QD + 2 * KVD)        /* 6144 */
#define VOFF    (QD + KVD)            /* 5120 */
#define MAXEL   ((size_t)TOK * HIDDEN)
#define WMAX    ((size_t)(2 * HIDDEN) * DIM)   /* packed w1|w3 */

// ---------------------------------------------------------------------------
// Scratch (static device globals; allocation-free per harness rules)
// ---------------------------------------------------------------------------
__device__ float g_h [(size_t)TOK * DIM];
__device__ float g_f1[MAXEL];                 // qkv fp32 (reused)
__device__ __nv_bfloat16 g_ahi[MAXEL];
__device__ __nv_bfloat16 g_alo[MAXEL];
__device__ __nv_bfloat16 g_whi[WMAX];
__device__ __nv_bfloat16 g_wlo[WMAX];
__device__ __nv_bfloat16 g_qhi[(size_t)TOK * QD];
__device__ __nv_bfloat16 g_qlo[(size_t)TOK * QD];
__device__ __nv_bfloat16 g_khi[(size_t)TOK * KVD];
__device__ __nv_bfloat16 g_klo[(size_t)TOK * KVD];
__device__ __nv_bfloat16 g_vthi[(size_t)TOK * KVD]; // [B][NKV][HEADD][SEQL]
__device__ __nv_bfloat16 g_vtlo[(size_t)TOK * KVD];

// ---------------------------------------------------------------------------
// PTX helpers (sm_100-safe: cp.async / ldmatrix / mma.sync only)
// ---------------------------------------------------------------------------
__device__ __forceinline__ uint32_t smem_u32(const void* p) {
    uint32_t a;
    asm("{ .reg .u64 t; cvta.to.shared.u64 t, %1; cvt.u32.u64 %0, t; }"
        : "=r"(a) : "l"(p));
    return a;
}
#define CP_ASYNC16(dst, src) \
    asm volatile("cp.async.cg.shared.global [%0], [%1], 16;" \
                 :: "r"(dst), "l"(src) : "memory")
#define CP_COMMIT() asm volatile("cp.async.commit_group;" ::: "memory")
#define CP_WAIT0()  asm volatile("cp.async.wait_group 0;" ::: "memory")
#define CP_WAIT1()  asm volatile("cp.async.wait_group 1;" ::: "memory")

#define LDMX4(r0, r1, r2, r3, addr) \
    asm volatile("ldmatrix.sync.aligned.m8n8.x4.shared.b16 {%0,%1,%2,%3}, [%4];" \
                 : "=r"(r0), "=r"(r1), "=r"(r2), "=r"(r3) : "r"(addr))

#define MMA16816(c0, c1, c2, c3, a0, a1, a2, a3, b0, b1) \
    asm volatile("mma.sync.aligned.m16n8k16.row.col.f32.bf16.bf16.f32 " \
                 "{%0,%1,%2,%3}, {%4,%5,%6,%7}, {%8,%9}, {%0,%1,%2,%3};" \
                 : "+f"(c0), "+f"(c1), "+f"(c2), "+f"(c3) \
                 : "r"(a0), "r"(a1), "r"(a2), "r"(a3), "r"(b0), "r"(b1))

__device__ __forceinline__ uint32_t swz(uint32_t o) { return o ^ ((o >> 3) & 0x70); }

__device__ __forceinline__ uint32_t pack_bf16x2(float x, float y) {
    __nv_bfloat162 t = __floats2bfloat162_rn(x, y);
    return *(uint32_t*)&t;
}
__device__ __forceinline__ void split2(float x, float y, uint32_t& hi, uint32_t& lo) {
    __nv_bfloat16 hx = __float2bfloat16(x), hy = __float2bfloat16(y);
    __nv_bfloat162 hh; hh.x = hx; hh.y = hy;
    hi = *(uint32_t*)&hh;
    lo = pack_bf16x2(x - __bfloat162float(hx), y - __bfloat162float(hy));
}

// ---------------------------------------------------------------------------
// bf16 HMMA GEMM.  Proven mainloop (2-stage, 64 KB, 2 CTAs/SM, 2 syncs).
// Epilogue modes:
//   gated=0: fp32 C (+resid) [+ routed C2] [+ bf16 hi/lo duplicate Chi/Clo]
//   gated=1: tile cols 0-63 = f1, 64-127 = f3 (interleaved w1|w3 packing);
//            epilogue computes silu(f1)*f3 via smem exchange and writes ONLY
//            bf16 hi/lo gated output (Chi/Clo, ld = ldc, col base = n0/2).
// ---------------------------------------------------------------------------
#define STG 32768
#define GEMM_SMEM 65536
#define GEMM_SMEM_GATED (128 * 132 * 4)   /* 67584; row stride 528B = 8B-aligned */

__global__ void __launch_bounds__(256, 2) mma_gemm(
    const __nv_bfloat16* __restrict__ Ahi, const __nv_bfloat16* __restrict__ Alo,
    const __nv_bfloat16* __restrict__ Bhi, const __nv_bfloat16* __restrict__ Blo,
    const float* __restrict__ resid, float* __restrict__ C,
    float* __restrict__ C2, int nsplit,
    __nv_bfloat16* __restrict__ Chi, __nv_bfloat16* __restrict__ Clo,
    int K, int ldc, int gated)
{
    extern __shared__ char smc[];
    const uint32_t sbase = smem_u32(smc);
    const int tid   = threadIdx.x;
    const int lane  = tid & 31;
    const int wid   = tid >> 5;
    const int warpM = wid >> 2;
    const int warpN = wid & 3;
    const int m0 = blockIdx.y * 128;
    const int n0 = blockIdx.x * 128;

    const int NC = K >> 5;

    float acc[4][4][4];
#pragma unroll
    for (int mt = 0; mt < 4; mt++)
#pragma unroll
        for (int nt = 0; nt < 4; nt++)
#pragma unroll
            for (int e = 0; e < 4; e++) acc[mt][nt][e] = 0.f;

    auto load_chunk = [&](int c, int stage) {
        const int k0 = c << 5;
        const uint32_t uA = sbase + stage * STG;
        const uint32_t uB = uA + 16384;
#pragma unroll
        for (int it = 0; it < 4; it++) {
            const int idx = tid + it * 256;
            const int r  = idx >> 3;
            const int cc = idx & 7;
            const uint32_t o = swz((uint32_t)(r * 128 + cc * 16));
            const int kk = k0 + (cc & 3) * 8;
            const __nv_bfloat16* As = (cc < 4) ? Ahi : Alo;
            const __nv_bfloat16* Bs = (cc < 4) ? Bhi : Blo;
            CP_ASYNC16(uA + o, As + (size_t)(m0 + r) * K + kk);
            CP_ASYNC16(uB + o, Bs + (size_t)(n0 + r) * K + kk);
        }
    };

    auto compute_chunk = [&](int stage) {
        const uint32_t uA = sbase + stage * STG;
        const uint32_t uB = uA + 16384;
#pragma unroll
        for (int ks = 0; ks < 2; ks++) {
            const int kb = ks * 32;
            uint32_t a[4][4];
#pragma unroll
            for (int mt = 0; mt < 4; mt++) {
                const int r = warpM * 64 + mt * 16 + (lane & 15);
                const uint32_t o = swz((uint32_t)(r * 128 + kb + ((lane >> 4) << 4)));
                LDMX4(a[mt][0], a[mt][1], a[mt][2], a[mt][3], uA + o);
            }
            uint32_t bH[2][4], bL[2][4];
#pragma unroll
            for (int g = 0; g < 2; g++) {
                const int r = warpN * 32 + g * 16 + (lane & 7) + ((lane >> 4) << 3);
                const uint32_t col = kb + (((lane >> 3) & 1) << 4);
                const uint32_t oH = swz((uint32_t)(r * 128 + col));
                const uint32_t oL = swz((uint32_t)(r * 128 + 64 + col));
                LDMX4(bH[g][0], bH[g][1], bH[g][2], bH[g][3], uB + oH);
                LDMX4(bL[g][0], bL[g][1], bL[g][2], bL[g][3], uB + oL);
            }
#pragma unroll
            for (int mt = 0; mt < 4; mt++)
#pragma unroll
                for (int nt = 0; nt < 4; nt++) {
                    const int gq = nt >> 1, t2 = nt & 1;
                    MMA16816(acc[mt][nt][0], acc[mt][nt][1],
                             acc[mt][nt][2], acc[mt][nt][3],
                             a[mt][0], a[mt][1], a[mt][2], a[mt][3],
                             bH[gq][t2 * 2], bH[gq][t2 * 2 + 1]);
                    MMA16816(acc[mt][nt][0], acc[mt][nt][1],
                             acc[mt][nt][2], acc[mt][nt][3],
                             a[mt][0], a[mt][1], a[mt][2], a[mt][3],
                             bL[gq][t2 * 2], bL[gq][t2 * 2 + 1]);
                }
#pragma unroll
            for (int mt = 0; mt < 4; mt++) {
                const int r = warpM * 64 + mt * 16 + (lane & 15);
                const uint32_t o = swz((uint32_t)(r * 128 + 64 + kb + ((lane >> 4) << 4)));
                LDMX4(a[mt][0], a[mt][1], a[mt][2], a[mt][3], uA + o);
            }
#pragma unroll
            for (int mt = 0; mt < 4; mt++)
#pragma unroll
                for (int nt = 0; nt < 4; nt++) {
                    const int gq = nt >> 1, t2 = nt & 1;
                    MMA16816(acc[mt][nt][0], acc[mt][nt][1],
                             acc[mt][nt][2], acc[mt][nt][3],
                             a[mt][0], a[mt][1], a[mt][2], a[mt][3],
                             bH[gq][t2 * 2], bH[gq][t2 * 2 + 1]);
                }
        }
    };

    load_chunk(0, 0);
    CP_COMMIT();

    for (int i = 0; i < NC; i++) {
        const int b = i & 1;
        if (i + 1 < NC) {
            load_chunk(i + 1, b ^ 1);
            CP_COMMIT();
            CP_WAIT1();
        } else {
            CP_WAIT0();
        }
        __syncthreads();
        compute_chunk(b);
        __syncthreads();
    }

    const int g  = lane >> 2;
    const int tg = lane & 3;

    if (gated) {
        // stage fp32 tile to smem (mainloop stages are dead; barrier above
        // guarantees all warps finished reading them)
        float* sg = (float*)smc;
#pragma unroll
        for (int mt = 0; mt < 4; mt++) {
            const int rl = warpM * 64 + mt * 16 + g;
#pragma unroll
            for (int nt = 0; nt < 4; nt++) {
                const int cl = warpN * 32 + nt * 8 + tg * 2;
                *(float2*)&sg[rl * 132 + cl] =
                    make_float2(acc[mt][nt][0], acc[mt][nt][1]);
                *(float2*)&sg[(rl + 8) * 132 + cl] =
                    make_float2(acc[mt][nt][2], acc[mt][nt][3]);
            }
        }
        __syncthreads();
        const int jb = n0 >> 1;   // gated output column base
#pragma unroll
        for (int it = 0; it < 16; it++) {
            const int idx = tid + it * 256;
            const int row = idx >> 5, cp = idx & 31;   // warp writes 1 row, coalesced
            const float f1a = sg[row * 132 + 2 * cp];
            const float f1b = sg[row * 132 + 2 * cp + 1];
            const float f3a = sg[row * 132 + 64 + 2 * cp];
            const float f3b = sg[row * 132 + 65 + 2 * cp];
            const float g0 = f1a / (1.0f + __expf(-f1a)) * f3a;
            const float g1 = f1b / (1.0f + __expf(-f1b)) * f3b;
            uint32_t hh, ll;
            split2(g0, g1, hh, ll);
            const size_t o = (size_t)(m0 + row) * ldc + jb + 2 * cp;
            *(uint32_t*)(Chi + o) = hh;
            *(uint32_t*)(Clo + o) = ll;
        }
        return;
    }

    float* Cout = C;
    int nbase = n0;
    if (C2 && n0 >= nsplit) { Cout = C2; nbase = n0 - nsplit; }

#pragma unroll
    for (int mt = 0; mt < 4; mt++) {
        const int row = m0 + warpM * 64 + mt * 16 + g;
#pragma unroll
        for (int nt = 0; nt < 4; nt++) {
            const int col = nbase + warpN * 32 + nt * 8 + tg * 2;
            const size_t i0 = (size_t)row * ldc + col;
            const size_t i1 = (size_t)(row + 8) * ldc + col;
            float2 v0 = make_float2(acc[mt][nt][0], acc[mt][nt][1]);
            float2 v1 = make_float2(acc[mt][nt][2], acc[mt][nt][3]);
            if (resid) {
                float2 r0 = *(const float2*)(resid + i0);
                float2 r1 = *(const float2*)(resid + i1);
                v0.x += r0.x; v0.y += r0.y;
                v1.x += r1.x; v1.y += r1.y;
            }
            *(float2*)(Cout + i0) = v0;
            *(float2*)(Cout + i1) = v1;
            if (Chi) {
                uint32_t h0, l0, h1, l1;
                split2(v0.x, v0.y, h0, l0);
                split2(v1.x, v1.y, h1, l1);
                *(uint32_t*)(Chi + i0) = h0;
                *(uint32_t*)(Clo + i0) = l0;
                *(uint32_t*)(Chi + i1) = h1;
                *(uint32_t*)(Clo + i1) = l1;
            }
        }
    }
}

// ---------------------------------------------------------------------------
// Vectorized elementwise kernels
// ---------------------------------------------------------------------------
__global__ void split_kernel(const float* __restrict__ src,
                             __nv_bfloat16* __restrict__ hi,
                             __nv_bfloat16* __restrict__ lo, size_t n4)
{
    const size_t stride = (size_t)gridDim.x * blockDim.x;
    for (size_t i = (size_t)blockIdx.x * blockDim.x + threadIdx.x; i < n4; i += stride) {
        float4 v = ((const float4*)src)[i];
        uint2 h, l;
        split2(v.x, v.y, h.x, l.x);
        split2(v.z, v.w, h.y, l.y);
        ((uint2*)hi)[i] = h;
        ((uint2*)lo)[i] = l;
    }
}

// W [K,N] fp32 -> W^T bf16 hi/lo. half=-1: row n -> n.
// half=0/1 (interleaved w1|w3): row n -> (n/64)*128 + (n%64) + half*64.
// grid=(N/32, K/64), block=(32,8); scalar smem reads (row stride 260B).
__global__ void split_transpose_kernel(const float* __restrict__ W,
                                       __nv_bfloat16* __restrict__ hi,
                                       __nv_bfloat16* __restrict__ lo,
                                       int K, int N, int half)
{
    __shared__ float t[32][65];   // [n][k]
    const int nb = blockIdx.x * 32, kb = blockIdx.y * 64;
    const int tx = threadIdx.x, ty = threadIdx.y;
#pragma unroll
    for (int j = 0; j < 8; j++)
        t[tx][ty + 8 * j] = W[(size_t)(kb + ty + 8 * j) * N + nb + tx];
    __syncthreads();
#pragma unroll
    for (int j = 0; j < 4; j++) {
        const int n = nb + ty + 8 * j;
        const int dn = (half < 0) ? n : ((n >> 6) * 128 + (n & 63) + (half << 6));
        const float vx = t[ty + 8 * j][2 * tx];
        const float vy = t[ty + 8 * j][2 * tx + 1];
        uint32_t h, l;
        split2(vx, vy, h, l);
        *(uint32_t*)(hi + (size_t)dn * K + kb + 2 * tx) = h;
        *(uint32_t*)(lo + (size_t)dn * K + kb + 2 * tx) = l;
    }
}

// fused RoPE + hi/lo split (float2 load, u32 stores)
__global__ void rope_split_kernel(const float* __restrict__ src, int ld, int coloff,
                                  const float* __restrict__ fcos,
                                  const float* __restrict__ fsin,
                                  int nheads,
                                  __nv_bfloat16* __restrict__ hi,
                                  __nv_bfloat16* __restrict__ lo,
                                  int npairs)
{
    int gid = blockIdx.x * blockDim.x + threadIdx.x;
    if (gid >= npairs) return;
    const int i    = gid & 63;
    const int rest = gid >> 6;
    const int hh   = rest % nheads;
    const int tok  = rest / nheads;
    const int s    = tok & (SEQL - 1);
    const float c  = fcos[s * 64 + i];
    const float sn = fsin[s * 64 + i];
    const float2 ab = *(const float2*)(src + (size_t)tok * ld + coloff + hh * HEADD + 2 * i);
    const float r0 = ab.x * c - ab.y * sn;
    const float r1 = ab.x * sn + ab.y * c;
    const size_t ob = ((size_t)tok * nheads + hh) * HEADD + 2 * i;
    uint32_t h2, l2;
    split2(r0, r1, h2, l2);
    *(uint32_t*)(hi + ob) = h2;
    *(uint32_t*)(lo + ob) = l2;
}

// v slice of qkv -> vt [(b*NKV+kv)*HEADD + d][s] hi/lo
__global__ void vt_split_kernel(const float* __restrict__ qkv,
                                __nv_bfloat16* __restrict__ hi,
                                __nv_bfloat16* __restrict__ lo)
{
    __shared__ float t[32][33];
    const int z = blockIdx.z, b = z >> 3, kvh = z & 7;
    const int sb = blockIdx.x * 32, db = blockIdx.y * 32;
    const int tx = threadIdx.x, ty = threadIdx.y;
#pragma unroll
    for (int j = 0; j < 4; j++)
        t[ty + j * 8][tx] =
            qkv[(size_t)(b * SEQL + sb + ty + j * 8) * QKVN + VOFF + kvh * HEADD + db + tx];
    __syncthreads();
#pragma unroll
    for (int j = 0; j < 4; j++) {
        const int d = db + ty + j * 8, s = sb + tx;
        const float val = t[tx][ty + j * 8];
        __nv_bfloat16 h = __float2bfloat16(val);
        const size_t o = ((size_t)(b * NKV + kvh) * HEADD + d) * SEQL + s;
        hi[o] = h;
        lo[o] = __float2bfloat16(val - __bfloat162float(h));
    }
}

// ---------------------------------------------------------------------------
// HMMA flash attention, causal, 3-pass hi/lo (unchanged)
// ---------------------------------------------------------------------------
#define SQ_HI 0
#define SQ_LO 32768
#define SKV0  65536
#define KVSTG 65536
#define FLASH_SMEM (SKV0 + 2 * KVSTG)   /* 196608 */

__global__ void __launch_bounds__(256) flash_mma_kernel(
    const __nv_bfloat16* __restrict__ qhi, const __nv_bfloat16* __restrict__ qlo,
    const __nv_bfloat16* __restrict__ khi, const __nv_bfloat16* __restrict__ klo,
    const __nv_bfloat16* __restrict__ vthi, const __nv_bfloat16* __restrict__ vtlo,
    __nv_bfloat16* __restrict__ ohi, __nv_bfloat16* __restrict__ olo)
{
    extern __shared__ char smc[];
    const uint32_t sb = smem_u32(smc);
    const int z = blockIdx.y, b = z >> 5, h = z & 31, kv = h >> 2;
    const int qt = blockIdx.x, q0 = qt * 128;
    const int tid = threadIdx.x, lane = tid & 31, w = tid >> 5;
    const int g = lane >> 2, tg = lane & 3;

    {
        const __nv_bfloat16* qh = qhi + (size_t)(b * SEQL + q0) * QD + h * HEADD;
        const __nv_bfloat16* ql = qlo + (size_t)(b * SEQL + q0) * QD + h * HEADD;
#pragma unroll
        for (int it = 0; it < 8; it++) {
            const int idx = tid + it * 256;
            const int sub = idx >> 10, rem = idx & 1023;
            const int r = rem >> 3, cc = rem & 7;
            const uint32_t o = swz((uint32_t)(r * 128 + cc * 16));
            const size_t src = (size_t)r * QD + sub * 64 + cc * 8;
            CP_ASYNC16(sb + SQ_HI + sub * 16384 + o, qh + src);
            CP_ASYNC16(sb + SQ_LO + sub * 16384 + o, ql + src);
        }
        CP_COMMIT();
    }

    const int nkt = 2 * qt + 2;
    auto load_kv = [&](int kt) {
        const uint32_t base = sb + SKV0 + (kt & 1) * KVSTG;
        const int s0 = kt * 64;
        const __nv_bfloat16* kh = khi + (size_t)(b * SEQL + s0) * KVD + kv * HEADD;
        const __nv_bfloat16* kl = klo + (size_t)(b * SEQL + s0) * KVD + kv * HEADD;
#pragma unroll
        for (int it = 0; it < 4; it++) {
            const int idx = tid + it * 256;
            const int sub = idx >> 9, rem = idx & 511;
            const int r = rem >> 3, cc = rem & 7;
            const uint32_t o = swz((uint32_t)(r * 128 + cc * 16));
            const size_t src = (size_t)r * KVD + sub * 64 + cc * 8;
            CP_ASYNC16(base + sub * 8192 + o, kh + src);
            CP_ASYNC16(base + 16384 + sub * 8192 + o, kl + src);
        }
        const __nv_bfloat16* vh = vthi + (size_t)(b * NKV + kv) * HEADD * SEQL + s0;
        const __nv_bfloat16* vl = vtlo + (size_t)(b * NKV + kv) * HEADD * SEQL + s0;
#pragma unroll
        for (int it = 0; it < 4; it++) {
            const int idx = tid + it * 256;
            const int r = idx >> 3, cc = idx & 7;
            const uint32_t o = swz((uint32_t)(r * 128 + cc * 16));
            const size_t src = (size_t)r * SEQL + cc * 8;
            CP_ASYNC16(base + 32768 + o, vh + src);
            CP_ASYNC16(base + 49152 + o, vl + src);
        }
        CP_COMMIT();
    };
    load_kv(0);
    if (nkt > 1) load_kv(1);

    float m0 = -1e30f, m1 = -1e30f, l0 = 0.f, l1 = 0.f;
    float O[16][4];
#pragma unroll
    for (int nt = 0; nt < 16; nt++)
#pragma unroll
        for (int e = 0; e < 4; e++) O[nt][e] = 0.f;

    const float SC = 0.08838834764831843f;

    for (int kt = 0; kt < nkt; kt++) {
        if (kt + 1 < nkt) CP_WAIT1(); else CP_WAIT0();
        __syncthreads();
        const uint32_t base = sb + SKV0 + (kt & 1) * KVSTG;

        float S[8][4];
#pragma unroll
        for (int nt = 0; nt < 8; nt++)
#pragma unroll
            for (int e = 0; e < 4; e++) S[nt][e] = 0.f;

#pragma unroll
        for (int ks = 0; ks < 8; ks++) {
            const int sub = ks >> 2, kb = (ks & 3) * 32;
            const uint32_t oA =
                swz((uint32_t)((w * 16 + (lane & 15)) * 128 + kb + ((lane >> 4) << 4)));
            uint32_t aH[4], aL[4];
            LDMX4(aH[0], aH[1], aH[2], aH[3], sb + SQ_HI + sub * 16384 + oA);
            LDMX4(aL[0], aL[1], aL[2], aL[3], sb + SQ_LO + sub * 16384 + oA);
#pragma unroll
            for (int nb = 0; nb < 4; nb++) {
                const uint32_t oB = swz((uint32_t)(
                    (nb * 16 + (lane & 7) + ((lane >> 4) << 3)) * 128 +
                    kb + (((lane >> 3) & 1) << 4)));
                uint32_t bH[4], bL[4];
                LDMX4(bH[0], bH[1], bH[2], bH[3], base + sub * 8192 + oB);
                LDMX4(bL[0], bL[1], bL[2], bL[3], base + 16384 + sub * 8192 + oB);
#pragma unroll
                for (int t2 = 0; t2 < 2; t2++) {
                    const int nt = nb * 2 + t2;
                    MMA16816(S[nt][0], S[nt][1], S[nt][2], S[nt][3],
                             aH[0], aH[1], aH[2], aH[3], bH[t2 * 2], bH[t2 * 2 + 1]);
                    MMA16816(S[nt][0], S[nt][1], S[nt][2], S[nt][3],
                             aH[0], aH[1], aH[2], aH[3], bL[t2 * 2], bL[t2 * 2 + 1]);
                    MMA16816(S[nt][0], S[nt][1], S[nt][2], S[nt][3],
                             aL[0], aL[1], aL[2], aL[3], bH[t2 * 2], bH[t2 * 2 + 1]);
                }
            }
        }

        const int s0 = kt * 64;
        const int row0 = q0 + w * 16 + g;
#pragma unroll
        for (int nt = 0; nt < 8; nt++)
#pragma unroll
            for (int e = 0; e < 2; e++) {
                const int col = s0 + nt * 8 + tg * 2 + e;
                float v0 = S[nt][e] * SC;
                float v1 = S[nt][2 + e] * SC;
                if (col > row0)     v0 = -1e30f;
                if (col > row0 + 8) v1 = -1e30f;
                S[nt][e] = v0;
                S[nt][2 + e] = v1;
            }
        float tm0 = -1e30f, tm1 = -1e30f;
#pragma unroll
        for (int nt = 0; nt < 8; nt++) {
            tm0 = fmaxf(tm0, fmaxf(S[nt][0], S[nt][1]));
            tm1 = fmaxf(tm1, fmaxf(S[nt][2], S[nt][3]));
        }
        tm0 = fmaxf(tm0, __shfl_xor_sync(0xffffffffu, tm0, 1));
        tm0 = fmaxf(tm0, __shfl_xor_sync(0xffffffffu, tm0, 2));
        tm1 = fmaxf(tm1, __shfl_xor_sync(0xffffffffu, tm1, 1));
        tm1 = fmaxf(tm1, __shfl_xor_sync(0xffffffffu, tm1, 2));
        const float mn0 = fmaxf(m0, tm0), mn1 = fmaxf(m1, tm1);
        const float sc0 = __expf(m0 - mn0), sc1 = __expf(m1 - mn1);
        m0 = mn0; m1 = mn1;
        float ts0 = 0.f, ts1 = 0.f;
#pragma unroll
        for (int nt = 0; nt < 8; nt++) {
            S[nt][0] = __expf(S[nt][0] - mn0);
            S[nt][1] = __expf(S[nt][1] - mn0);
            S[nt][2] = __expf(S[nt][2] - mn1);
            S[nt][3] = __expf(S[nt][3] - mn1);
            ts0 += S[nt][0] + S[nt][1];
            ts1 += S[nt][2] + S[nt][3];
        }
        ts0 += __shfl_xor_sync(0xffffffffu, ts0, 1);
        ts0 += __shfl_xor_sync(0xffffffffu, ts0, 2);
        ts1 += __shfl_xor_sync(0xffffffffu, ts1, 1);
        ts1 += __shfl_xor_sync(0xffffffffu, ts1, 2);
        l0 = l0 * sc0 + ts0;
        l1 = l1 * sc1 + ts1;
#pragma unroll
        for (int nt = 0; nt < 16; nt++) {
            O[nt][0] *= sc0; O[nt][1] *= sc0;
            O[nt][2] *= sc1; O[nt][3] *= sc1;
        }

#pragma unroll
        for (int ks = 0; ks < 4; ks++) {
            uint32_t pH[4], pL[4];
#pragma unroll
            for (int half = 0; half < 2; half++) {
                const int st = 2 * ks + half;
                split2(S[st][0], S[st][1], pH[half * 2 + 0], pL[half * 2 + 0]);
                split2(S[st][2], S[st][3], pH[half * 2 + 1], pL[half * 2 + 1]);
            }
#pragma unroll
            for (int nb = 0; nb < 8; nb++) {
                const uint32_t oB = swz((uint32_t)(
                    (nb * 16 + (lane & 7) + ((lane >> 4) << 3)) * 128 +
                    ks * 32 + (((lane >> 3) & 1) << 4)));
                uint32_t vH[4], vL[4];
                LDMX4(vH[0], vH[1], vH[2], vH[3], base + 32768 + oB);
                LDMX4(vL[0], vL[1], vL[2], vL[3], base + 49152 + oB);
#pragma unroll
                for (int t2 = 0; t2 < 2; t2++) {
                    const int nt = nb * 2 + t2;
                    MMA16816(O[nt][0], O[nt][1], O[nt][2], O[nt][3],
                             pH[0], pH[1], pH[2], pH[3], vH[t2 * 2], vH[t2 * 2 + 1]);
                    MMA16816(O[nt][0], O[nt][1], O[nt][2], O[nt][3],
                             pL[0], pL[1], pL[2], pL[3], vH[t2 * 2], vH[t2 * 2 + 1]);
                    MMA16816(O[nt][0], O[nt][1], O[nt][2], O[nt][3],
                             pH[0], pH[1], pH[2], pH[3], vL[t2 * 2], vL[t2 * 2 + 1]);
                }
            }
        }
        __syncthreads();
        if (kt + 2 < nkt) load_kv(kt + 2);
    }

    const float il0 = 1.0f / l0, il1 = 1.0f / l1;
    __nv_bfloat16* OH = ohi + (size_t)(b * SEQL) * QD + h * HEADD;
    __nv_bfloat16* OL = olo + (size_t)(b * SEQL) * QD + h * HEADD;
#pragma unroll
    for (int nt = 0; nt < 16; nt++) {
        const int col = nt * 8 + tg * 2;
        const size_t i0 = (size_t)(q0 + w * 16 + g) * QD + col;
        const size_t i1 = (size_t)(q0 + w * 16 + g + 8) * QD + col;
        uint32_t h0, lo0, h1, lo1;
        split2(O[nt][0] * il0, O[nt][1] * il0, h0, lo0);
        split2(O[nt][2] * il1, O[nt][3] * il1, h1, lo1);
        *(uint32_t*)(OH + i0) = h0;
        *(uint32_t*)(OL + i0) = lo0;
        *(uint32_t*)(OH + i1) = h1;
        *(uint32_t*)(OL + i1) = lo1;
    }
}

// ---------------------------------------------------------------------------
// kernel_launch
// ---------------------------------------------------------------------------
extern "C" void kernel_launch(void* const* d_in, const int* in_sizes, int n_in,
                              void* d_out, int out_size)
{
    const float* x    = (const float*)d_in[0];
    /* d_in[1] = mask (unused; causal handled analytically) */
    const float* fcos = (const float*)d_in[2];
    const float* fsin = (const float*)d_in[3];
    const float* wq   = (const float*)d_in[4];
    const float* wk   = (const float*)d_in[5];
    const float* wv   = (const float*)d_in[6];
    const float* wo   = (const float*)d_in[7];
    const float* w1   = (const float*)d_in[8];
    const float* w2   = (const float*)d_in[9];
    const float* w3   = (const float*)d_in[10];
    float* out = (float*)d_out;

    float *h, *f1;
    __nv_bfloat16 *ahi, *alo, *whi, *wlo;
    __nv_bfloat16 *qhi, *qlo, *khi, *klo, *vthi, *vtlo;
    cudaGetSymbolAddress((void**)&h,    g_h);
    cudaGetSymbolAddress((void**)&f1,   g_f1);
    cudaGetSymbolAddress((void**)&ahi,  g_ahi);
    cudaGetSymbolAddress((void**)&alo,  g_alo);
    cudaGetSymbolAddress((void**)&whi,  g_whi);
    cudaGetSymbolAddress((void**)&wlo,  g_wlo);
    cudaGetSymbolAddress((void**)&qhi,  g_qhi);
    cudaGetSymbolAddress((void**)&qlo,  g_qlo);
    cudaGetSymbolAddress((void**)&khi,  g_khi);
    cudaGetSymbolAddress((void**)&klo,  g_klo);
    cudaGetSymbolAddress((void**)&vthi, g_vthi);
    cudaGetSymbolAddress((void**)&vtlo, g_vtlo);

    float* qkv = f1;   // qkv fp32 [TOK, 6144] reuses g_f1

    static int attr_done = 0;
    if (!attr_done) {
        cudaFuncSetAttribute(mma_gemm,
            cudaFuncAttributeMaxDynamicSharedMemorySize, GEMM_SMEM_GATED);
        cudaFuncSetAttribute(flash_mma_kernel,
            cudaFuncAttributeMaxDynamicSharedMemorySize, FLASH_SMEM);
        attr_done = 1;
    }

    const dim3 tb(32, 8);

    // x -> bf16 split (vectorized)
    split_kernel<<<2048, 256>>>(x, ahi, alo, (size_t)TOK * DIM / 4);

    // pack wq^T | wk^T | wv^T
    split_transpose_kernel<<<dim3(QD / 32, DIM / 64), tb>>>(wq, whi, wlo, DIM, QD, -1);
    split_transpose_kernel<<<dim3(KVD / 32, DIM / 64), tb>>>(
        wk, whi + (size_t)QD * DIM, wlo + (size_t)QD * DIM, DIM, KVD, -1);
    split_transpose_kernel<<<dim3(KVD / 32, DIM / 64), tb>>>(
        wv, whi + (size_t)VOFF * DIM, wlo + (size_t)VOFF * DIM, DIM, KVD, -1);

    // merged QKV projection: [TOK, 6144]
    mma_gemm<<<dim3(QKVN / 128, TOK / 128), 256, GEMM_SMEM>>>(
        ahi, alo, whi, wlo, nullptr, qkv, nullptr, 0, nullptr, nullptr, DIM, QKVN, 0);

    // fused RoPE + split (q, k); V transpose+split
    rope_split_kernel<<<(TOK * NH * 64 + 255) / 256, 256>>>(
        qkv, QKVN, 0, fcos, fsin, NH, qhi, qlo, TOK * NH * 64);
    rope_split_kernel<<<(TOK * NKV * 64 + 255) / 256, 256>>>(
        qkv, QKVN, QD, fcos, fsin, NKV, khi, klo, TOK * NKV * 64);
    vt_split_kernel<<<dim3(SEQL / 32, HEADD / 32, BATCH * NKV), tb>>>(qkv, vthi, vtlo);

    // HMMA flash attention -> attn out as bf16 hi/lo (into ahi/alo)
    flash_mma_kernel<<<dim3(SEQL / 128, BATCH * NH), 256, FLASH_SMEM>>>(
        qhi, qlo, khi, klo, vthi, vtlo, ahi, alo);

    // h = x + attn @ wo ; epilogue also emits h hi/lo into qhi/qlo
    split_transpose_kernel<<<dim3(DIM / 32, QD / 64), tb>>>(wo, whi, wlo, QD, DIM, -1);
    mma_gemm<<<dim3(DIM / 128, TOK / 128), 256, GEMM_SMEM>>>(
        ahi, alo, whi, wlo, x, h, nullptr, 0, qhi, qlo, QD, DIM, 0);

    // merged FFN up-projection with fused silu: w1|w3 interleaved per 64 rows
    split_transpose_kernel<<<dim3(HIDDEN / 32, DIM / 64), tb>>>(w1, whi, wlo, DIM, HIDDEN, 0);
    split_transpose_kernel<<<dim3(HIDDEN / 32, DIM / 64), tb>>>(w3, whi, wlo, DIM, HIDDEN, 1);
    mma_gemm<<<dim3((2 * HIDDEN) / 128, TOK / 128), 256, GEMM_SMEM_GATED>>>(
        qhi, qlo, whi, wlo, nullptr, nullptr, nullptr, 0, ahi, alo, DIM, HIDDEN, 1);

    // out = h + gated @ w2
    split_transpose_kernel<<<dim3(DIM / 32, HIDDEN / 64), tb>>>(w2, whi, wlo, HIDDEN, DIM, -1);
    mma_gemm<<<dim3(DIM / 128, TOK / 128), 256, GEMM_SMEM>>>(
        ahi, alo, whi, wlo, h, out, nullptr, 0, nullptr, nullptr, HIDDEN, DIM, 0);
}